// round 12
// baseline (speedup 1.0000x reference)
#include <cuda_runtime.h>
#include <cuda_bf16.h>
#include <cstdint>
#include <math.h>

// Problem constants
#define BATCH 8
#define CH    192
#define HH    128
#define WW    128
#define HEADS 6
#define HD    32
#define WIN   8
#define NTOK  64
#define NWIN  2048
#define TOK   131072
#define HID   768
#define SHIFT 4

// ---------------- device scratch ----------------
__device__ __align__(256) float g_xb [TOK * CH];   // GN output NHWC fp32 (residual & shortcut)
__device__ __align__(256) float g_xb2[TOK * CH];   // xb + attn branch NHWC fp32
__device__ __align__(256) __nv_bfloat16 g_hw_bf [TOK * CH];
// qkv in head-major layout: [win][head][mat(q,k,v)][64 tok][32 dim]
__device__ __align__(256) __nv_bfloat16 g_qkv_bf[(size_t)TOK * 3 * CH];
__device__ __align__(256) __nv_bfloat16 g_attn_bf[TOK * CH];
__device__ __align__(256) __nv_bfloat16 g_h2_bf [TOK * CH];
__device__ __align__(256) __nv_bfloat16 g_wqkv[3 * CH * CH];   // [576,192] (N,K)
__device__ __align__(256) __nv_bfloat16 g_wproj[CH * CH];      // [192,192]
__device__ __align__(256) __nv_bfloat16 g_wfc1[HID * CH];      // [768,192]
__device__ __align__(256) __nv_bfloat16 g_wfc2[CH * HID];      // [192,768]
__device__ float g_part[BATCH * 128 * 2];
__device__ float g_stats[BATCH * 2];

// ---------------- helpers ----------------
__device__ __forceinline__ uint32_t s2u(const void* p) {
    uint32_t a;
    asm("{ .reg .u64 t; cvta.to.shared.u64 t, %1; cvt.u32.u64 %0, t; }" : "=r"(a) : "l"(p));
    return a;
}
__device__ __forceinline__ uint32_t sw128(uint32_t o) { return o ^ ((o >> 3) & 0x70); }

__device__ __forceinline__ void cp16(uint32_t saddr, const void* gptr) {
    asm volatile("cp.async.cg.shared.global [%0], [%1], 16;" :: "r"(saddr), "l"(gptr) : "memory");
}
__device__ __forceinline__ void cp_commit() {
    asm volatile("cp.async.commit_group;" ::: "memory");
}
__device__ __forceinline__ void cp_wait0() {
    asm volatile("cp.async.wait_group 0;" ::: "memory");
}
__device__ __forceinline__ void cp_wait2() {
    asm volatile("cp.async.wait_group 2;" ::: "memory");
}
__device__ __forceinline__ void ldsm4(uint32_t& r0, uint32_t& r1, uint32_t& r2, uint32_t& r3,
                                      uint32_t a) {
    asm volatile("ldmatrix.sync.aligned.m8n8.x4.shared.b16 {%0,%1,%2,%3}, [%4];"
                 : "=r"(r0), "=r"(r1), "=r"(r2), "=r"(r3) : "r"(a));
}
__device__ __forceinline__ void ldsm4t(uint32_t& r0, uint32_t& r1, uint32_t& r2, uint32_t& r3,
                                       uint32_t a) {
    asm volatile("ldmatrix.sync.aligned.m8n8.x4.trans.shared.b16 {%0,%1,%2,%3}, [%4];"
                 : "=r"(r0), "=r"(r1), "=r"(r2), "=r"(r3) : "r"(a));
}
__device__ __forceinline__ void mma16816(float* c, const uint32_t* a, const uint32_t* b) {
    asm volatile(
        "mma.sync.aligned.m16n8k16.row.col.f32.bf16.bf16.f32 "
        "{%0,%1,%2,%3}, {%4,%5,%6,%7}, {%8,%9}, {%0,%1,%2,%3};"
        : "+f"(c[0]), "+f"(c[1]), "+f"(c[2]), "+f"(c[3])
        : "r"(a[0]), "r"(a[1]), "r"(a[2]), "r"(a[3]), "r"(b[0]), "r"(b[1]));
}
__device__ __forceinline__ uint32_t packbf(float a, float b) {
    __nv_bfloat162 h = __floats2bfloat162_rn(a, b);
    return *(uint32_t*)&h;
}
__device__ __forceinline__ float gelu(float v) {
    return 0.5f * v * (1.f + erff(v * 0.7071067811865475f));
}

// ---------------- GroupNorm two-stage reduction ----------------
__global__ void gn_partial_kernel(const float* __restrict__ x) {
    const int b = blockIdx.x >> 7;
    const int chunk = blockIdx.x & 127;
    const int tid = threadIdx.x;
    const size_t per_sample = (size_t)CH * HH * WW;
    const float* p = x + (size_t)b * per_sample + (size_t)chunk * 24576;
    float s = 0.f, sq = 0.f;
    for (int i = tid; i < 24576; i += 256) { float v = p[i]; s += v; sq += v * v; }
    __shared__ float rs[256], rq[256];
    rs[tid] = s; rq[tid] = sq;
    __syncthreads();
    for (int o = 128; o; o >>= 1) {
        if (tid < o) { rs[tid] += rs[tid + o]; rq[tid] += rq[tid + o]; }
        __syncthreads();
    }
    if (tid == 0) {
        g_part[blockIdx.x * 2 + 0] = rs[0];
        g_part[blockIdx.x * 2 + 1] = rq[0];
    }
}

__global__ void gn_final_kernel() {
    const int b = blockIdx.x;
    const int tid = threadIdx.x;
    __shared__ double ds[128], dq[128];
    ds[tid] = (double)g_part[(b * 128 + tid) * 2 + 0];
    dq[tid] = (double)g_part[(b * 128 + tid) * 2 + 1];
    __syncthreads();
    for (int o = 64; o; o >>= 1) {
        if (tid < o) { ds[tid] += ds[tid + o]; dq[tid] += dq[tid + o]; }
        __syncthreads();
    }
    if (tid == 0) {
        const double n = 3145728.0;
        double mean = ds[0] / n;
        double var = dq[0] / n - mean * mean;
        g_stats[b * 2 + 0] = (float)mean;
        g_stats[b * 2 + 1] = (float)(1.0 / sqrt(var + 1e-5));
    }
}

// ---------------- all weight transposes in one launch ----------------
__global__ void wtrans_all(const float* __restrict__ qkv_w, const float* __restrict__ proj_w,
                           const float* __restrict__ fc1_w, const float* __restrict__ fc2_w) {
    const int b = blockIdx.x;
    const float* W;
    __nv_bfloat16* Wt;
    int K, N, bx, by;
    if (b < 108)      { W = qkv_w;  Wt = g_wqkv;  K = CH;  N = 3 * CH; bx = b % 18;  by = b / 18; }
    else if (b < 144) { int t = b - 108; W = proj_w; Wt = g_wproj; K = CH;  N = CH;  bx = t % 6;  by = t / 6; }
    else if (b < 288) { int t = b - 144; W = fc1_w;  Wt = g_wfc1;  K = CH;  N = HID; bx = t % 24; by = t / 24; }
    else              { int t = b - 288; W = fc2_w;  Wt = g_wfc2;  K = HID; N = CH;  bx = t % 6;  by = t / 6; }
    __shared__ float t[32][33];
    const int k0 = by * 32, n0 = bx * 32;
    const int lx = threadIdx.x & 31, ly = threadIdx.x >> 5;
    for (int r = ly; r < 32; r += 8) t[r][lx] = W[(size_t)(k0 + r) * N + n0 + lx];
    __syncthreads();
    for (int r = ly; r < 32; r += 8)
        Wt[(size_t)(n0 + r) * K + k0 + lx] = __float2bfloat16(t[lx][r]);
}

// ---------------- GN apply + xb store + LN1 + shift + window partition ----------------
__global__ void build_kernel(const float* __restrict__ x,
                             const float* __restrict__ gnw, const float* __restrict__ gnb,
                             const float* __restrict__ ln1w, const float* __restrict__ ln1b) {
    __shared__ float t[CH][33];
    const int bid = blockIdx.x;
    const int xt = bid & 3;
    const int y  = (bid >> 2) & 127;
    const int b  = bid >> 9;
    const int tid = threadIdx.x;
    const float mu = g_stats[b * 2 + 0];
    const float rstd = g_stats[b * 2 + 1];
    const int lx = tid & 31;
    const int c0 = tid >> 5;

    for (int c = c0; c < CH; c += 8) {
        float v = x[((((size_t)b * CH + c) * HH + y) * WW) + xt * 32 + lx];
        t[c][lx] = (v - mu) * rstd * gnw[c] + gnb[c];
    }
    __syncthreads();

    const size_t tokbase = ((size_t)(b * HH + y) * WW) + xt * 32;
    for (int j = 0; j < 32; j++) {
        if (tid < CH) g_xb[(tokbase + j) * CH + tid] = t[tid][j];
    }

    const int warp = tid >> 5, lane = tid & 31;
    for (int j = warp; j < 32; j += 8) {
        float s = 0.f, sq = 0.f;
#pragma unroll
        for (int k = 0; k < 6; k++) {
            float v = t[lane + k * 32][j];
            s += v; sq += v * v;
        }
#pragma unroll
        for (int o = 16; o; o >>= 1) {
            s  += __shfl_xor_sync(0xffffffffu, s, o);
            sq += __shfl_xor_sync(0xffffffffu, sq, o);
        }
        float mean = s * (1.f / CH);
        float var = sq * (1.f / CH) - mean * mean;
        float r = rsqrtf(var + 1e-5f);
        const int xx = xt * 32 + j;
        const int ys = (y - SHIFT) & 127;
        const int xs = (xx - SHIFT) & 127;
        const size_t dst = ((size_t)(((b * 16 + (ys >> 3)) * 16 + (xs >> 3)) * NTOK)
                            + (ys & 7) * 8 + (xs & 7)) * CH;
#pragma unroll
        for (int k = 0; k < 6; k++) {
            int c = lane + k * 32;
            g_hw_bf[dst + c] = __float2bfloat16((t[c][j] - mean) * r * ln1w[c] + ln1b[c]);
        }
    }
}

// ---------------- mma.sync bf16 GEMM, CTA tile 128x96, 3-stage (K=192) ----------------
// 256 threads = 8 warps (4m x 2n); warp tile 32x48 (2x6 m16n8k16 frags).
// MODE 0: qkv  -> g_qkv_bf HEAD-MAJOR layout
// MODE 1: proj -> g_xb2 = . + g_xb window-reverse
#define GSTAGE 28672
#define GSMEM  (3 * GSTAGE)   // 86016

template <int MODE>
__global__ void __launch_bounds__(256)
mma_gemm(const float* __restrict__ bias) {
    constexpr int K   = CH;
    constexpr int NST = K / 64;   // 3
    const __nv_bfloat16* const A  = (MODE == 0) ? g_hw_bf : g_attn_bf;
    const __nv_bfloat16* const Bt = (MODE == 0) ? g_wqkv : g_wproj;

    extern __shared__ __align__(1024) uint8_t smx[];
    const uint32_t smb = s2u(smx);
    const int tid = threadIdx.x;
    const int wid = tid >> 5, lane = tid & 31;
    const int wm = wid & 3, wn = wid >> 2;    // 4m x 2n
    const int m0 = blockIdx.y * 128;
    const int n0c = blockIdx.x * 96;

    const __nv_bfloat16* const Abase = A  + (size_t)m0 * K;
    const __nv_bfloat16* const Bbase = Bt + (size_t)n0c * K;

    auto load_stage = [&](int st) {
        const uint32_t sA = smb + (st % 3) * GSTAGE;
        const uint32_t sB = sA + 16384;
        const int kel = st * 64;
#pragma unroll
        for (int i = 0; i < 4; i++) {            // A: 128 rows x 128B
            int e = tid + i * 256;
            int row = e >> 3, c16 = e & 7;
            cp16(sA + sw128(row * 128 + c16 * 16), Abase + (size_t)row * K + kel + c16 * 8);
        }
#pragma unroll
        for (int i = 0; i < 3; i++) {            // B: 96 rows x 128B
            int e = tid + i * 256;
            int row = e >> 3, c16 = e & 7;
            cp16(sB + sw128(row * 128 + c16 * 16), Bbase + (size_t)row * K + kel + c16 * 8);
        }
    };

    float acc[2][6][4] = {};

    const int arow0 = wm * 32 + (lane & 15);
    const int akoff = (lane >> 4) * 16;
    const int brow0 = wn * 48 + (lane & 7) + ((lane >> 4) << 3);
    const int bkoff = (lane & 8) ? 16 : 0;

    load_stage(0); cp_commit();
    load_stage(1); cp_commit();
    load_stage(2); cp_commit();

    for (int st = 0; st < NST; st++) {
        cp_wait2();
        __syncthreads();
        const uint32_t sA = smb + (st % 3) * GSTAGE;
        const uint32_t sB = sA + 16384;
#pragma unroll
        for (int kk = 0; kk < 4; kk++) {
            uint32_t af[2][4], bf[3][4];
#pragma unroll
            for (int mi = 0; mi < 2; mi++)
                ldsm4(af[mi][0], af[mi][1], af[mi][2], af[mi][3],
                      sA + sw128((arow0 + mi * 16) * 128 + kk * 32 + akoff));
#pragma unroll
            for (int bi = 0; bi < 3; bi++)
                ldsm4(bf[bi][0], bf[bi][1], bf[bi][2], bf[bi][3],
                      sB + sw128((brow0 + bi * 16) * 128 + kk * 32 + bkoff));
#pragma unroll
            for (int mi = 0; mi < 2; mi++)
#pragma unroll
                for (int ni = 0; ni < 6; ni++)
                    mma16816(acc[mi][ni], af[mi], &bf[ni >> 1][(ni & 1) * 2]);
        }
        __syncthreads();
        cp_commit();
    }

    // ---- epilogue ----
    const int g = lane >> 2, tg = lane & 3;
    const int nbase = n0c + wn * 48;
    float2 bv[6];
#pragma unroll
    for (int ni = 0; ni < 6; ni++) bv[ni] = *(const float2*)&bias[nbase + ni * 8 + tg * 2];

#pragma unroll
    for (int mi = 0; mi < 2; mi++) {
#pragma unroll
        for (int half = 0; half < 2; half++) {
            const int r = m0 + wm * 32 + mi * 16 + g + half * 8;
            if (MODE == 0) {
                const int win = r >> 6, tok = r & 63;
#pragma unroll
                for (int ni = 0; ni < 6; ni++) {
                    const int c = nbase + ni * 8 + tg * 2;
                    const int mat = c / 192, hc = c - mat * 192;
                    const int head = hc >> 5, dim = hc & 31;
                    float v0 = acc[mi][ni][half * 2 + 0] + bv[ni].x;
                    float v1 = acc[mi][ni][half * 2 + 1] + bv[ni].y;
                    __nv_bfloat162 h2 = __floats2bfloat162_rn(v0, v1);
                    *(__nv_bfloat162*)&g_qkv_bf[(((size_t)win * HEADS + head) * 3 + mat) * 2048
                                                + tok * 32 + dim] = h2;
                }
            } else {
                const int win = r >> 6, tok = r & 63;
                const int bb2 = win >> 8, wy = (win >> 4) & 15, wx = win & 15;
                const int yy = ((wy << 3) + (tok >> 3) + SHIFT) & 127;
                const int xx = ((wx << 3) + (tok & 7) + SHIFT) & 127;
                const size_t dr = ((size_t)((bb2 * HH + yy) * WW + xx)) * CH;
#pragma unroll
                for (int ni = 0; ni < 6; ni++) {
                    const size_t o = dr + nbase + ni * 8 + tg * 2;
                    float2 sc = *(const float2*)&g_xb[o];
                    float2 ov;
                    ov.x = acc[mi][ni][half * 2 + 0] + bv[ni].x + sc.x;
                    ov.y = acc[mi][ni][half * 2 + 1] + bv[ni].y + sc.y;
                    *(float2*)&g_xb2[o] = ov;
                }
            }
        }
    }
}

// ---------------- fused MLP: fc1 + GELU + fc2 + residuals + clamp + NCHW out ----------------
// 512 threads. CTA = 128 rows x full 192 output cols. hid processed in 8 chunks of 96.
// smem: sA 48KB (3x[128x128B] sw128) | sT 26.6KB (128x208B) | sW1 36KB (3x[96x128B] sw128)
//       | sW2 39KB (192x208B)
#define M_SA 0
#define M_ST 49152
#define M_SW1 75776
#define M_SW2 112640
#define MSMEM 152576

__global__ void __launch_bounds__(512)
fused_mlp(const float* __restrict__ b1, const float* __restrict__ b2, float* __restrict__ outp) {
    extern __shared__ __align__(1024) uint8_t smx[];
    const uint32_t smb = s2u(smx);
    const int tid = threadIdx.x;
    const int wid = tid >> 5, lane = tid & 31;
    const int g = lane >> 2, tg = lane & 3;
    // fc1 partition: 8m x 2n (warp tile 16x48)
    const int wm1 = wid & 7, wn1 = wid >> 3;
    // fc2 partition: 4m x 4n (warp tile 32x48)
    const int wm2 = wid & 3, wn2 = wid >> 2;
    const int m0 = blockIdx.x * 128;

    const __nv_bfloat16* const A = g_h2_bf + (size_t)m0 * CH;

    // ---- prologue loads ----
    {
        // sA: 128 rows x 192 cols bf16 -> 3072 cp16
#pragma unroll
        for (int i = 0; i < 6; i++) {
            int idx = tid + i * 512;
            int row = idx / 24, q = idx % 24;
            int kc = q >> 3, c16 = q & 7;
            cp16(smb + M_SA + kc * 16384 + sw128(row * 128 + c16 * 16),
                 A + (size_t)row * CH + kc * 64 + c16 * 8);
        }
        // W1[0]: 96 rows x 192 -> 2304 cp16
#pragma unroll
        for (int i = 0; i < 5; i++) {
            int idx = tid + i * 512;
            if (idx < 2304) {
                int row = idx / 24, q = idx % 24;
                int kc = q >> 3, c16 = q & 7;
                cp16(smb + M_SW1 + kc * 12288 + sw128(row * 128 + c16 * 16),
                     g_wfc1 + (size_t)row * CH + kc * 64 + c16 * 8);
            }
        }
        // W2[0]: 192 rows x 96 k-cols -> 2304 cp16
#pragma unroll
        for (int i = 0; i < 5; i++) {
            int idx = tid + i * 512;
            if (idx < 2304) {
                int row = idx / 12, c16 = idx % 12;
                cp16(smb + M_SW2 + row * 208 + c16 * 16,
                     g_wfc2 + (size_t)row * HID + c16 * 8);
            }
        }
        cp_commit();
        cp_wait0();
    }
    __syncthreads();

    float acc2[2][6][4] = {};

    for (int h = 0; h < 8; h++) {
        // ---- fc1: T = A @ W1[h]^T, warp tile 16x48 ----
        float acc1[6][4] = {};
        const int a1row = wm1 * 16 + (lane & 15);
        const int b1row = wn1 * 48 + (lane & 7) + ((lane >> 4) << 3);
        const int akoff = (lane >> 4) * 16;
        const int bkoff = (lane & 8) ? 16 : 0;
#pragma unroll
        for (int kk1 = 0; kk1 < 12; kk1++) {
            const int kc = kk1 >> 2, kkin = kk1 & 3;
            uint32_t af[4], bf[3][4];
            ldsm4(af[0], af[1], af[2], af[3],
                  smb + M_SA + kc * 16384 + sw128(a1row * 128 + kkin * 32 + akoff));
#pragma unroll
            for (int bi = 0; bi < 3; bi++)
                ldsm4(bf[bi][0], bf[bi][1], bf[bi][2], bf[bi][3],
                      smb + M_SW1 + kc * 12288
                      + sw128((b1row + bi * 16) * 128 + kkin * 32 + bkoff));
#pragma unroll
            for (int ni = 0; ni < 6; ni++)
                mma16816(acc1[ni], af, &bf[ni >> 1][(ni & 1) * 2]);
        }
        __syncthreads();   // sW1 free; prior fc2 reads of sT done

        if (h < 7) {       // prefetch W1[h+1]
#pragma unroll
            for (int i = 0; i < 5; i++) {
                int idx = tid + i * 512;
                if (idx < 2304) {
                    int row = idx / 24, q = idx % 24;
                    int kc = q >> 3, c16 = q & 7;
                    cp16(smb + M_SW1 + kc * 12288 + sw128(row * 128 + c16 * 16),
                         g_wfc1 + (size_t)((h + 1) * 96 + row) * CH + kc * 64 + c16 * 8);
                }
            }
            cp_commit();
        }

        // ---- bias + GELU -> sT (bf16, pitch 208) ----
        {
            const int r1 = wm1 * 16 + g;
#pragma unroll
            for (int ni = 0; ni < 6; ni++) {
                const int c = wn1 * 48 + ni * 8 + tg * 2;
                float2 bb = *(const float2*)&b1[h * 96 + c];
                float v0 = gelu(acc1[ni][0] + bb.x);
                float v1 = gelu(acc1[ni][1] + bb.y);
                float v2 = gelu(acc1[ni][2] + bb.x);
                float v3 = gelu(acc1[ni][3] + bb.y);
                uint32_t p01 = packbf(v0, v1), p23 = packbf(v2, v3);
                asm volatile("st.shared.b32 [%0], %1;"
                             :: "r"(smb + M_ST + r1 * 208 + c * 2), "r"(p01) : "memory");
                asm volatile("st.shared.b32 [%0], %1;"
                             :: "r"(smb + M_ST + (r1 + 8) * 208 + c * 2), "r"(p23) : "memory");
            }
        }
        __syncthreads();   // sT ready

        // ---- fc2 accumulate: acc2 += T @ W2[h]^T, warp tile 32x48 ----
        {
            const int a2row = wm2 * 32 + (lane & 15);
            const int b2row = wn2 * 48 + (lane & 7) + ((lane >> 4) << 3);
            const int akoff2 = (lane >> 4) * 16;
            const int bkoff2 = (lane & 8) ? 16 : 0;
#pragma unroll
            for (int kk = 0; kk < 6; kk++) {
                uint32_t af[2][4], bf[3][4];
#pragma unroll
                for (int mi = 0; mi < 2; mi++)
                    ldsm4(af[mi][0], af[mi][1], af[mi][2], af[mi][3],
                          smb + M_ST + (a2row + mi * 16) * 208 + kk * 32 + akoff2);
#pragma unroll
                for (int bi = 0; bi < 3; bi++)
                    ldsm4(bf[bi][0], bf[bi][1], bf[bi][2], bf[bi][3],
                          smb + M_SW2 + (b2row + bi * 16) * 208 + kk * 32 + bkoff2);
#pragma unroll
                for (int mi = 0; mi < 2; mi++)
#pragma unroll
                    for (int ni = 0; ni < 6; ni++)
                        mma16816(acc2[mi][ni], af[mi], &bf[ni >> 1][(ni & 1) * 2]);
            }
        }
        __syncthreads();   // sW2 free

        if (h < 7) {       // prefetch W2[h+1]
#pragma unroll
            for (int i = 0; i < 5; i++) {
                int idx = tid + i * 512;
                if (idx < 2304) {
                    int row = idx / 12, c16 = idx % 12;
                    cp16(smb + M_SW2 + row * 208 + c16 * 16,
                         g_wfc2 + (size_t)row * HID + (h + 1) * 96 + c16 * 8);
                }
            }
            cp_commit();
            cp_wait0();
            __syncthreads();
        }
    }

    // ---- epilogue: + fc2 bias + g_xb2 + g_xb, clamp, NCHW store ----
    const int nbase = wn2 * 48;
    float2 bv[6];
#pragma unroll
    for (int ni = 0; ni < 6; ni++) bv[ni] = *(const float2*)&b2[nbase + ni * 8 + tg * 2];

#pragma unroll
    for (int mi = 0; mi < 2; mi++) {
#pragma unroll
        for (int half = 0; half < 2; half++) {
            const int r = m0 + wm2 * 32 + mi * 16 + g + half * 8;
            const int bb2i = r >> 14, yy = (r >> 7) & 127, xx = r & 127;
            const size_t off = (size_t)r * CH;
            const size_t obase = (((size_t)bb2i * CH) * HH + yy) * WW + xx;
#pragma unroll
            for (int ni = 0; ni < 6; ni++) {
                const size_t o = off + nbase + ni * 8 + tg * 2;
                float2 a2 = *(const float2*)&g_xb2[o];
                float2 a1 = *(const float2*)&g_xb[o];
                float v0 = acc2[mi][ni][half * 2 + 0] + bv[ni].x + a2.x + a1.x;
                float v1 = acc2[mi][ni][half * 2 + 1] + bv[ni].y + a2.y + a1.y;
                v0 = fminf(10.f, fmaxf(-10.f, v0));
                v1 = fminf(10.f, fmaxf(-10.f, v1));
                const int c = nbase + ni * 8 + tg * 2;
                outp[obase + (size_t)c * (HH * WW)] = v0;
                outp[obase + (size_t)(c + 1) * (HH * WW)] = v1;
            }
        }
    }
}

// ---------------- tensor-core windowed attention ----------------
#define ATT_SLICE 5120
#define ATT_QKV   (18 * ATT_SLICE)
#define ATT_SMEM  (ATT_QKV + 5408)
__global__ void __launch_bounds__(384)
attn_kernel(const float* __restrict__ rpb) {
    extern __shared__ __align__(128) uint8_t smem_a[];
    float* srpb = (float*)(smem_a + ATT_QKV);
    const int win = blockIdx.x;
    const int tid = threadIdx.x;
    const int wid = tid >> 5, lane = tid & 31;
    const int head = wid >> 1, wrow = wid & 1;
    const int g = lane >> 2, tg = lane & 3;

    for (int f = tid; f < 225 * HEADS; f += 384) srpb[f] = rpb[f];

    {
        const __nv_bfloat16* gb = g_qkv_bf + (size_t)win * 18 * 2048;
#pragma unroll
        for (int i = 0; i < 12; i++) {
            int idx = tid + i * 384;
            int slice = idx >> 8;
            int cidx = idx & 255;
            int row = cidx >> 2, ch = cidx & 3;
            uint4 v = *(const uint4*)(gb + slice * 2048 + cidx * 8);
            *(uint4*)(smem_a + slice * ATT_SLICE + row * 80 + ch * 16) = v;
        }
    }
    __syncthreads();

    const uint32_t sq = s2u(smem_a) + (head * 3 + 0) * ATT_SLICE;
    const uint32_t sk = sq + ATT_SLICE;
    const uint32_t sv = sq + 2 * ATT_SLICE;

    float s[2][8][4] = {};
#pragma unroll
    for (int kt = 0; kt < 2; kt++) {
        uint32_t af[2][4];
#pragma unroll
        for (int mi = 0; mi < 2; mi++)
            ldsm4(af[mi][0], af[mi][1], af[mi][2], af[mi][3],
                  sq + (wrow * 32 + mi * 16 + (lane & 15)) * 80 + kt * 32 + (lane >> 4) * 16);
#pragma unroll
        for (int nj2 = 0; nj2 < 4; nj2++) {
            uint32_t bf[4];
            ldsm4(bf[0], bf[1], bf[2], bf[3],
                  sk + (nj2 * 16 + (lane & 7) + ((lane >> 4) << 3)) * 80
                     + kt * 32 + ((lane & 8) ? 16 : 0));
#pragma unroll
            for (int mi = 0; mi < 2; mi++) {
                mma16816(s[mi][nj2 * 2 + 0], af[mi], &bf[0]);
                mma16816(s[mi][nj2 * 2 + 1], af[mi], &bf[2]);
            }
        }
    }

    const int wy = (win >> 4) & 15, wx = win & 15;
    const bool my = (wy == 15), mx = (wx == 15);
#pragma unroll
    for (int mi = 0; mi < 2; mi++)
#pragma unroll
        for (int nj = 0; nj < 8; nj++)
#pragma unroll
            for (int e = 0; e < 4; e++) {
                const int i = wrow * 32 + mi * 16 + g + ((e >= 2) ? 8 : 0);
                const int j = nj * 8 + tg * 2 + (e & 1);
                const int iy = i >> 3, ix = i & 7, jy = j >> 3, jx = j & 7;
                float v = s[mi][nj][e] * 0.17677669529663687f
                        + srpb[((iy - jy + 7) * 15 + (ix - jx + 7)) * HEADS + head];
                const int ri = (my ? (iy < 4 ? 1 : 2) : 0) * 3 + (mx ? (ix < 4 ? 1 : 2) : 0);
                const int rj = (my ? (jy < 4 ? 1 : 2) : 0) * 3 + (mx ? (jx < 4 ? 1 : 2) : 0);
                if (ri != rj) v -= 100.f;
                s[mi][nj][e] = v;
            }
#pragma unroll
    for (int mi = 0; mi < 2; mi++)
#pragma unroll
        for (int h = 0; h < 2; h++) {
            float m = -1e30f;
#pragma unroll
            for (int nj = 0; nj < 8; nj++) {
                m = fmaxf(m, s[mi][nj][h * 2 + 0]);
                m = fmaxf(m, s[mi][nj][h * 2 + 1]);
            }
            m = fmaxf(m, __shfl_xor_sync(0xffffffffu, m, 1));
            m = fmaxf(m, __shfl_xor_sync(0xffffffffu, m, 2));
            float sum = 0.f;
#pragma unroll
            for (int nj = 0; nj < 8; nj++) {
                float e0 = __expf(s[mi][nj][h * 2 + 0] - m);
                float e1 = __expf(s[mi][nj][h * 2 + 1] - m);
                s[mi][nj][h * 2 + 0] = e0;
                s[mi][nj][h * 2 + 1] = e1;
                sum += e0 + e1;
            }
            sum += __shfl_xor_sync(0xffffffffu, sum, 1);
            sum += __shfl_xor_sync(0xffffffffu, sum, 2);
            const float inv = 1.f / sum;
#pragma unroll
            for (int nj = 0; nj < 8; nj++) {
                s[mi][nj][h * 2 + 0] *= inv;
                s[mi][nj][h * 2 + 1] *= inv;
            }
        }

    float o[2][4][4] = {};
#pragma unroll
    for (int kt = 0; kt < 4; kt++) {
        const int jr = kt * 16 + (lane & 7) + ((lane & 8) ? 8 : 0);
        const uint32_t vb = sv + jr * 80 + (lane >> 4) * 16;
        uint32_t b0[4], b1r[4];
        ldsm4t(b0[0], b0[1], b0[2], b0[3], vb);
        ldsm4t(b1r[0], b1r[1], b1r[2], b1r[3], vb + 32);
#pragma unroll
        for (int mi = 0; mi < 2; mi++) {
            uint32_t a[4];
            a[0] = packbf(s[mi][2 * kt][0], s[mi][2 * kt][1]);
            a[1] = packbf(s[mi][2 * kt][2], s[mi][2 * kt][3]);
            a[2] = packbf(s[mi][2 * kt + 1][0], s[mi][2 * kt + 1][1]);
            a[3] = packbf(s[mi][2 * kt + 1][2], s[mi][2 * kt + 1][3]);
            mma16816(o[mi][0], a, &b0[0]);
            mma16816(o[mi][1], a, &b0[2]);
            mma16816(o[mi][2], a, &b1r[0]);
            mma16816(o[mi][3], a, &b1r[2]);
        }
    }

    __nv_bfloat16* ob = g_attn_bf + (size_t)(win * NTOK) * CH + head * HD;
#pragma unroll
    for (int mi = 0; mi < 2; mi++) {
        const int rlo = wrow * 32 + mi * 16 + g;
#pragma unroll
        for (int nf = 0; nf < 4; nf++) {
            const int d = nf * 8 + tg * 2;
            *(__nv_bfloat162*)&ob[(size_t)rlo * CH + d] =
                __floats2bfloat162_rn(o[mi][nf][0], o[mi][nf][1]);
            *(__nv_bfloat162*)&ob[(size_t)(rlo + 8) * CH + d] =
                __floats2bfloat162_rn(o[mi][nf][2], o[mi][nf][3]);
        }
    }
}

// ---------------- LN2 ----------------
__global__ void ln2_kernel(const float* __restrict__ w, const float* __restrict__ bias) {
    const int gw = (blockIdx.x * blockDim.x + threadIdx.x) >> 5;
    const int lane = threadIdx.x & 31;
    if (gw >= TOK) return;
    const float* row = g_xb2 + (size_t)gw * CH;
    float v[6];
    float s = 0.f, sq = 0.f;
#pragma unroll
    for (int k = 0; k < 6; k++) {
        v[k] = row[lane + k * 32];
        s += v[k]; sq += v[k] * v[k];
    }
#pragma unroll
    for (int o = 16; o; o >>= 1) {
        s  += __shfl_xor_sync(0xffffffffu, s, o);
        sq += __shfl_xor_sync(0xffffffffu, sq, o);
    }
    float mean = s * (1.f / CH);
    float var = sq * (1.f / CH) - mean * mean;
    float r = rsqrtf(var + 1e-5f);
    __nv_bfloat16* orow = g_h2_bf + (size_t)gw * CH;
#pragma unroll
    for (int k = 0; k < 6; k++) {
        int cc = lane + k * 32;
        orow[cc] = __float2bfloat16((v[k] - mean) * r * w[cc] + bias[cc]);
    }
}

// ---------------- launch ----------------
extern "C" void kernel_launch(void* const* d_in, const int* in_sizes, int n_in,
                              void* d_out, int out_size) {
    (void)in_sizes; (void)n_in; (void)out_size;
    const float* x      = (const float*)d_in[0];
    const float* gn_w   = (const float*)d_in[1];
    const float* gn_b   = (const float*)d_in[2];
    const float* ln1_w  = (const float*)d_in[3];
    const float* ln1_b  = (const float*)d_in[4];
    const float* qkv_w  = (const float*)d_in[5];
    const float* qkv_b  = (const float*)d_in[6];
    const float* proj_w = (const float*)d_in[7];
    const float* proj_b = (const float*)d_in[8];
    const float* rpb    = (const float*)d_in[9];
    const float* ln2_w  = (const float*)d_in[10];
    const float* ln2_b  = (const float*)d_in[11];
    const float* fc1_w  = (const float*)d_in[12];
    const float* fc1_b  = (const float*)d_in[13];
    const float* fc2_w  = (const float*)d_in[14];
    const float* fc2_b  = (const float*)d_in[15];
    float* out = (float*)d_out;

    cudaFuncSetAttribute((const void*)attn_kernel,
                         cudaFuncAttributeMaxDynamicSharedMemorySize, ATT_SMEM);
    cudaFuncSetAttribute((const void*)mma_gemm<0>, cudaFuncAttributeMaxDynamicSharedMemorySize, GSMEM);
    cudaFuncSetAttribute((const void*)mma_gemm<1>, cudaFuncAttributeMaxDynamicSharedMemorySize, GSMEM);
    cudaFuncSetAttribute((const void*)fused_mlp, cudaFuncAttributeMaxDynamicSharedMemorySize, MSMEM);

    wtrans_all<<<432, 256>>>(qkv_w, proj_w, fc1_w, fc2_w);

    gn_partial_kernel<<<BATCH * 128, 256>>>(x);
    gn_final_kernel<<<BATCH, 128>>>();
    build_kernel<<<BATCH * HH * (WW / 32), 256>>>(x, gn_w, gn_b, ln1_w, ln1_b);

    // QKV -> head-major g_qkv_bf
    mma_gemm<0><<<dim3(6, TOK / 128), 256, GSMEM>>>(qkv_b);

    attn_kernel<<<NWIN, 384, ATT_SMEM>>>(rpb);

    // proj: window-reverse + shortcut -> g_xb2
    mma_gemm<1><<<dim3(2, TOK / 128), 256, GSMEM>>>(proj_b);

    ln2_kernel<<<TOK / 8, 256>>>(ln2_w, ln2_b);

    // fused fc1 + GELU + fc2 + double residual + clamp -> out (NCHW)
    fused_mlp<<<TOK / 128, 512, MSMEM>>>(fc1_b, fc2_b, out);
}

// round 13
// speedup vs baseline: 1.0558x; 1.0558x over previous
#include <cuda_runtime.h>
#include <cuda_bf16.h>
#include <cstdint>
#include <math.h>

// Problem constants
#define BATCH 8
#define CH    192
#define HH    128
#define WW    128
#define HEADS 6
#define HD    32
#define WIN   8
#define NTOK  64
#define NWIN  2048
#define TOK   131072
#define HID   768
#define SHIFT 4

// ---------------- device scratch ----------------
__device__ __align__(256) float g_xb [TOK * CH];   // GN output NHWC fp32 (residual & shortcut)
__device__ __align__(256) float g_xb2[TOK * CH];   // holds xb2 + xb (pre-summed residual for fc2)
__device__ __align__(256) __nv_bfloat16 g_xb2bf[TOK * CH];   // xb2 in bf16 (ln2 input)
__device__ __align__(256) __nv_bfloat16 g_hw_bf [TOK * CH];
// qkv in head-major layout: [win][head][mat(q,k,v)][64 tok][32 dim]
__device__ __align__(256) __nv_bfloat16 g_qkv_bf[(size_t)TOK * 3 * CH];
__device__ __align__(256) __nv_bfloat16 g_attn_bf[TOK * CH];
__device__ __align__(256) __nv_bfloat16 g_h2_bf [TOK * CH];
__device__ __align__(256) __nv_bfloat16 g_hid_bf[(size_t)TOK * HID];
__device__ __align__(256) __nv_bfloat16 g_wqkv[3 * CH * CH];   // [576,192] (N,K)
__device__ __align__(256) __nv_bfloat16 g_wproj[CH * CH];      // [192,192]
__device__ __align__(256) __nv_bfloat16 g_wfc1[HID * CH];      // [768,192]
__device__ __align__(256) __nv_bfloat16 g_wfc2[CH * HID];      // [192,768]
__device__ float g_part[BATCH * 128 * 2];
__device__ float g_stats[BATCH * 2];

// ---------------- helpers ----------------
__device__ __forceinline__ uint32_t s2u(const void* p) {
    uint32_t a;
    asm("{ .reg .u64 t; cvta.to.shared.u64 t, %1; cvt.u32.u64 %0, t; }" : "=r"(a) : "l"(p));
    return a;
}
__device__ __forceinline__ uint32_t sw128(uint32_t o) { return o ^ ((o >> 3) & 0x70); }

__device__ __forceinline__ void cp16(uint32_t saddr, const void* gptr) {
    asm volatile("cp.async.cg.shared.global [%0], [%1], 16;" :: "r"(saddr), "l"(gptr) : "memory");
}
__device__ __forceinline__ void cp_commit() {
    asm volatile("cp.async.commit_group;" ::: "memory");
}
__device__ __forceinline__ void cp_wait1() {
    asm volatile("cp.async.wait_group 1;" ::: "memory");
}
__device__ __forceinline__ void ldsm4(uint32_t& r0, uint32_t& r1, uint32_t& r2, uint32_t& r3,
                                      uint32_t a) {
    asm volatile("ldmatrix.sync.aligned.m8n8.x4.shared.b16 {%0,%1,%2,%3}, [%4];"
                 : "=r"(r0), "=r"(r1), "=r"(r2), "=r"(r3) : "r"(a));
}
__device__ __forceinline__ void ldsm4t(uint32_t& r0, uint32_t& r1, uint32_t& r2, uint32_t& r3,
                                       uint32_t a) {
    asm volatile("ldmatrix.sync.aligned.m8n8.x4.trans.shared.b16 {%0,%1,%2,%3}, [%4];"
                 : "=r"(r0), "=r"(r1), "=r"(r2), "=r"(r3) : "r"(a));
}
__device__ __forceinline__ void mma16816(float* c, const uint32_t* a, const uint32_t* b) {
    asm volatile(
        "mma.sync.aligned.m16n8k16.row.col.f32.bf16.bf16.f32 "
        "{%0,%1,%2,%3}, {%4,%5,%6,%7}, {%8,%9}, {%0,%1,%2,%3};"
        : "+f"(c[0]), "+f"(c[1]), "+f"(c[2]), "+f"(c[3])
        : "r"(a[0]), "r"(a[1]), "r"(a[2]), "r"(a[3]), "r"(b[0]), "r"(b[1]));
}
__device__ __forceinline__ uint32_t packbf(float a, float b) {
    __nv_bfloat162 h = __floats2bfloat162_rn(a, b);
    return *(uint32_t*)&h;
}

// ---------------- GroupNorm two-stage reduction ----------------
__global__ void gn_partial_kernel(const float* __restrict__ x) {
    const int b = blockIdx.x >> 7;
    const int chunk = blockIdx.x & 127;
    const int tid = threadIdx.x;
    const size_t per_sample = (size_t)CH * HH * WW;
    const float* p = x + (size_t)b * per_sample + (size_t)chunk * 24576;
    float s = 0.f, sq = 0.f;
    for (int i = tid; i < 24576; i += 256) { float v = p[i]; s += v; sq += v * v; }
    __shared__ float rs[256], rq[256];
    rs[tid] = s; rq[tid] = sq;
    __syncthreads();
    for (int o = 128; o; o >>= 1) {
        if (tid < o) { rs[tid] += rs[tid + o]; rq[tid] += rq[tid + o]; }
        __syncthreads();
    }
    if (tid == 0) {
        g_part[blockIdx.x * 2 + 0] = rs[0];
        g_part[blockIdx.x * 2 + 1] = rq[0];
    }
}

__global__ void gn_final_kernel() {
    const int b = blockIdx.x;
    const int tid = threadIdx.x;
    __shared__ double ds[128], dq[128];
    ds[tid] = (double)g_part[(b * 128 + tid) * 2 + 0];
    dq[tid] = (double)g_part[(b * 128 + tid) * 2 + 1];
    __syncthreads();
    for (int o = 64; o; o >>= 1) {
        if (tid < o) { ds[tid] += ds[tid + o]; dq[tid] += dq[tid + o]; }
        __syncthreads();
    }
    if (tid == 0) {
        const double n = 3145728.0;
        double mean = ds[0] / n;
        double var = dq[0] / n - mean * mean;
        g_stats[b * 2 + 0] = (float)mean;
        g_stats[b * 2 + 1] = (float)(1.0 / sqrt(var + 1e-5));
    }
}

// ---------------- all weight transposes in one launch ----------------
__global__ void wtrans_all(const float* __restrict__ qkv_w, const float* __restrict__ proj_w,
                           const float* __restrict__ fc1_w, const float* __restrict__ fc2_w) {
    const int b = blockIdx.x;
    const float* W;
    __nv_bfloat16* Wt;
    int K, N, bx, by;
    if (b < 108)      { W = qkv_w;  Wt = g_wqkv;  K = CH;  N = 3 * CH; bx = b % 18;  by = b / 18; }
    else if (b < 144) { int t = b - 108; W = proj_w; Wt = g_wproj; K = CH;  N = CH;  bx = t % 6;  by = t / 6; }
    else if (b < 288) { int t = b - 144; W = fc1_w;  Wt = g_wfc1;  K = CH;  N = HID; bx = t % 24; by = t / 24; }
    else              { int t = b - 288; W = fc2_w;  Wt = g_wfc2;  K = HID; N = CH;  bx = t % 6;  by = t / 6; }
    __shared__ float t[32][33];
    const int k0 = by * 32, n0 = bx * 32;
    const int lx = threadIdx.x & 31, ly = threadIdx.x >> 5;
    for (int r = ly; r < 32; r += 8) t[r][lx] = W[(size_t)(k0 + r) * N + n0 + lx];
    __syncthreads();
    for (int r = ly; r < 32; r += 8)
        Wt[(size_t)(n0 + r) * K + k0 + lx] = __float2bfloat16(t[lx][r]);
}

// ---------------- GN apply + xb store + LN1 + shift + window partition ----------------
__global__ void build_kernel(const float* __restrict__ x,
                             const float* __restrict__ gnw, const float* __restrict__ gnb,
                             const float* __restrict__ ln1w, const float* __restrict__ ln1b) {
    __shared__ float t[CH][33];
    const int bid = blockIdx.x;
    const int xt = bid & 3;
    const int y  = (bid >> 2) & 127;
    const int b  = bid >> 9;
    const int tid = threadIdx.x;
    const float mu = g_stats[b * 2 + 0];
    const float rstd = g_stats[b * 2 + 1];
    const int lx = tid & 31;
    const int c0 = tid >> 5;

    for (int c = c0; c < CH; c += 8) {
        float v = x[((((size_t)b * CH + c) * HH + y) * WW) + xt * 32 + lx];
        t[c][lx] = (v - mu) * rstd * gnw[c] + gnb[c];
    }
    __syncthreads();

    const size_t tokbase = ((size_t)(b * HH + y) * WW) + xt * 32;
    for (int j = 0; j < 32; j++) {
        if (tid < CH) g_xb[(tokbase + j) * CH + tid] = t[tid][j];
    }

    const int warp = tid >> 5, lane = tid & 31;
    for (int j = warp; j < 32; j += 8) {
        float s = 0.f, sq = 0.f;
#pragma unroll
        for (int k = 0; k < 6; k++) {
            float v = t[lane + k * 32][j];
            s += v; sq += v * v;
        }
#pragma unroll
        for (int o = 16; o; o >>= 1) {
            s  += __shfl_xor_sync(0xffffffffu, s, o);
            sq += __shfl_xor_sync(0xffffffffu, sq, o);
        }
        float mean = s * (1.f / CH);
        float var = sq * (1.f / CH) - mean * mean;
        float r = rsqrtf(var + 1e-5f);
        const int xx = xt * 32 + j;
        const int ys = (y - SHIFT) & 127;
        const int xs = (xx - SHIFT) & 127;
        const size_t dst = ((size_t)(((b * 16 + (ys >> 3)) * 16 + (xs >> 3)) * NTOK)
                            + (ys & 7) * 8 + (xs & 7)) * CH;
#pragma unroll
        for (int k = 0; k < 6; k++) {
            int c = lane + k * 32;
            g_hw_bf[dst + c] = __float2bfloat16((t[c][j] - mean) * r * ln1w[c] + ln1b[c]);
        }
    }
}

// ---------------- mma.sync bf16 GEMM, CTA tile 128x96, 2-stage ----------------
// 256 threads = 8 warps (4m x 2n); warp tile 32x48 (2x6 m16n8k16 frags).
// MODE 0: qkv  -> g_qkv_bf HEAD-MAJOR layout
// MODE 1: proj -> window-reverse; writes g_xb2 = xb2 + xb (fp32) AND g_xb2bf = xb2 (bf16)
// MODE 2: fc1  -> GELU -> g_hid_bf
// MODE 3: fc2  -> out NCHW = clamp(. + g_xb2)   [g_xb2 already holds xb2 + xb]
#define GSTAGE 28672
#define GSMEM  (2 * GSTAGE)   // 57344

template <int MODE>
__global__ void __launch_bounds__(256)
mma_gemm(const float* __restrict__ bias, float* __restrict__ outp) {
    constexpr int K    = (MODE == 3) ? HID : CH;
    constexpr int NST  = K / 64;
    const __nv_bfloat16* const A  = (MODE == 0) ? g_hw_bf : (MODE == 1) ? g_attn_bf
                                  : (MODE == 2) ? g_h2_bf : g_hid_bf;
    const __nv_bfloat16* const Bt = (MODE == 0) ? g_wqkv : (MODE == 1) ? g_wproj
                                  : (MODE == 2) ? g_wfc1 : g_wfc2;
    constexpr int Nout = (MODE == 0) ? 3 * CH : (MODE == 2) ? HID : CH;

    extern __shared__ __align__(1024) uint8_t smx[];
    const uint32_t smb = s2u(smx);
    const int tid = threadIdx.x;
    const int wid = tid >> 5, lane = tid & 31;
    const int wm = wid & 3, wn = wid >> 2;    // 4m x 2n
    const int m0 = blockIdx.y * 128;
    const int n0c = blockIdx.x * 96;

    const __nv_bfloat16* const Abase = A  + (size_t)m0 * K;
    const __nv_bfloat16* const Bbase = Bt + (size_t)n0c * K;

    auto load_stage = [&](int st, int buf) {
        const uint32_t sA = smb + buf * GSTAGE;
        const uint32_t sB = sA + 16384;
        const int kel = st * 64;
#pragma unroll
        for (int i = 0; i < 4; i++) {            // A: 128 rows x 128B
            int e = tid + i * 256;
            int row = e >> 3, c16 = e & 7;
            cp16(sA + sw128(row * 128 + c16 * 16), Abase + (size_t)row * K + kel + c16 * 8);
        }
#pragma unroll
        for (int i = 0; i < 3; i++) {            // B: 96 rows x 128B
            int e = tid + i * 256;
            int row = e >> 3, c16 = e & 7;
            cp16(sB + sw128(row * 128 + c16 * 16), Bbase + (size_t)row * K + kel + c16 * 8);
        }
    };

    float acc[2][6][4] = {};

    const int arow0 = wm * 32 + (lane & 15);
    const int akoff = (lane >> 4) * 16;
    const int brow0 = wn * 48 + (lane & 7) + ((lane >> 4) << 3);
    const int bkoff = (lane & 8) ? 16 : 0;

    load_stage(0, 0); cp_commit();
    load_stage(1, 1); cp_commit();

    for (int st = 0; st < NST; st++) {
        cp_wait1();
        __syncthreads();
        const int buf = st & 1;
        const uint32_t sA = smb + buf * GSTAGE;
        const uint32_t sB = sA + 16384;
#pragma unroll
        for (int kk = 0; kk < 4; kk++) {
            uint32_t af[2][4], bf[3][4];
#pragma unroll
            for (int mi = 0; mi < 2; mi++)
                ldsm4(af[mi][0], af[mi][1], af[mi][2], af[mi][3],
                      sA + sw128((arow0 + mi * 16) * 128 + kk * 32 + akoff));
#pragma unroll
            for (int bi = 0; bi < 3; bi++)
                ldsm4(bf[bi][0], bf[bi][1], bf[bi][2], bf[bi][3],
                      sB + sw128((brow0 + bi * 16) * 128 + kk * 32 + bkoff));
#pragma unroll
            for (int mi = 0; mi < 2; mi++)
#pragma unroll
                for (int ni = 0; ni < 6; ni++)
                    mma16816(acc[mi][ni], af[mi], &bf[ni >> 1][(ni & 1) * 2]);
        }
        __syncthreads();
        if (st + 2 < NST) load_stage(st + 2, buf);
        cp_commit();
    }

    // ---- epilogue ----
    const int g = lane >> 2, tg = lane & 3;
    const int nbase = n0c + wn * 48;
    float2 bv[6];
#pragma unroll
    for (int ni = 0; ni < 6; ni++) bv[ni] = *(const float2*)&bias[nbase + ni * 8 + tg * 2];

#pragma unroll
    for (int mi = 0; mi < 2; mi++) {
#pragma unroll
        for (int half = 0; half < 2; half++) {
            const int r = m0 + wm * 32 + mi * 16 + g + half * 8;
            if (MODE == 0) {
                // head-major: [win][head][mat][tok][32]
                const int win = r >> 6, tok = r & 63;
#pragma unroll
                for (int ni = 0; ni < 6; ni++) {
                    const int c = nbase + ni * 8 + tg * 2;
                    const int mat = c / 192, hc = c - mat * 192;
                    const int head = hc >> 5, dim = hc & 31;
                    float v0 = acc[mi][ni][half * 2 + 0] + bv[ni].x;
                    float v1 = acc[mi][ni][half * 2 + 1] + bv[ni].y;
                    __nv_bfloat162 h2 = __floats2bfloat162_rn(v0, v1);
                    *(__nv_bfloat162*)&g_qkv_bf[(((size_t)win * HEADS + head) * 3 + mat) * 2048
                                                + tok * 32 + dim] = h2;
                }
            } else if (MODE == 2) {
#pragma unroll
                for (int ni = 0; ni < 6; ni++) {
                    float v0 = acc[mi][ni][half * 2 + 0] + bv[ni].x;
                    float v1 = acc[mi][ni][half * 2 + 1] + bv[ni].y;
                    v0 = 0.5f * v0 * (1.f + erff(v0 * 0.7071067811865475f));
                    v1 = 0.5f * v1 * (1.f + erff(v1 * 0.7071067811865475f));
                    __nv_bfloat162 h2 = __floats2bfloat162_rn(v0, v1);
                    *(__nv_bfloat162*)&g_hid_bf[(size_t)r * Nout + nbase + ni * 8 + tg * 2] = h2;
                }
            } else if (MODE == 1) {
                const int win = r >> 6, tok = r & 63;
                const int bb2 = win >> 8, wy = (win >> 4) & 15, wx = win & 15;
                const int yy = ((wy << 3) + (tok >> 3) + SHIFT) & 127;
                const int xx = ((wx << 3) + (tok & 7) + SHIFT) & 127;
                const size_t dr = ((size_t)((bb2 * HH + yy) * WW + xx)) * CH;
#pragma unroll
                for (int ni = 0; ni < 6; ni++) {
                    const size_t o = dr + nbase + ni * 8 + tg * 2;
                    float2 sc = *(const float2*)&g_xb[o];
                    // xb2 = attn_proj + bias + xb
                    float x2a = acc[mi][ni][half * 2 + 0] + bv[ni].x + sc.x;
                    float x2b = acc[mi][ni][half * 2 + 1] + bv[ni].y + sc.y;
                    // fp32 pre-summed residual for fc2: xb2 + xb
                    float2 ov;
                    ov.x = x2a + sc.x;
                    ov.y = x2b + sc.y;
                    *(float2*)&g_xb2[o] = ov;
                    // bf16 xb2 for ln2
                    *(uint32_t*)&g_xb2bf[o] = packbf(x2a, x2b);
                }
            } else {
                // MODE 3: direct NCHW clamped output; g_xb2 already holds xb2 + xb
                const int bb2 = r >> 14, yy = (r >> 7) & 127, xx = r & 127;
                const size_t off = (size_t)r * CH;
                const size_t obase = (((size_t)bb2 * CH) * HH + yy) * WW + xx;
#pragma unroll
                for (int ni = 0; ni < 6; ni++) {
                    const size_t o = off + nbase + ni * 8 + tg * 2;
                    float2 a2 = *(const float2*)&g_xb2[o];
                    float v0 = acc[mi][ni][half * 2 + 0] + bv[ni].x + a2.x;
                    float v1 = acc[mi][ni][half * 2 + 1] + bv[ni].y + a2.y;
                    v0 = fminf(10.f, fmaxf(-10.f, v0));
                    v1 = fminf(10.f, fmaxf(-10.f, v1));
                    const int c = nbase + ni * 8 + tg * 2;
                    outp[obase + (size_t)c * (HH * WW)] = v0;
                    outp[obase + (size_t)(c + 1) * (HH * WW)] = v1;
                }
            }
        }
    }
}

// ---------------- tensor-core windowed attention ----------------
// 1 block = 1 window; 12 warps = 6 heads x 2 row-halves (32 rows each).
#define ATT_SLICE 5120
#define ATT_QKV   (18 * ATT_SLICE)      // 92160
#define ATT_SMEM  (ATT_QKV + 5408)
__global__ void __launch_bounds__(384)
attn_kernel(const float* __restrict__ rpb) {
    extern __shared__ __align__(128) uint8_t smem_a[];
    float* srpb = (float*)(smem_a + ATT_QKV);
    const int win = blockIdx.x;
    const int tid = threadIdx.x;
    const int wid = tid >> 5, lane = tid & 31;
    const int head = wid >> 1, wrow = wid & 1;
    const int g = lane >> 2, tg = lane & 3;

    for (int f = tid; f < 225 * HEADS; f += 384) srpb[f] = rpb[f];

    {
        const __nv_bfloat16* gb = g_qkv_bf + (size_t)win * 18 * 2048;
#pragma unroll
        for (int i = 0; i < 12; i++) {
            int idx = tid + i * 384;
            int slice = idx >> 8;
            int cidx = idx & 255;
            int row = cidx >> 2, ch = cidx & 3;
            uint4 v = *(const uint4*)(gb + slice * 2048 + cidx * 8);
            *(uint4*)(smem_a + slice * ATT_SLICE + row * 80 + ch * 16) = v;
        }
    }
    __syncthreads();

    const uint32_t sq = s2u(smem_a) + (head * 3 + 0) * ATT_SLICE;
    const uint32_t sk = sq + ATT_SLICE;
    const uint32_t sv = sq + 2 * ATT_SLICE;

    float s[2][8][4] = {};
#pragma unroll
    for (int kt = 0; kt < 2; kt++) {
        uint32_t af[2][4];
#pragma unroll
        for (int mi = 0; mi < 2; mi++)
            ldsm4(af[mi][0], af[mi][1], af[mi][2], af[mi][3],
                  sq + (wrow * 32 + mi * 16 + (lane & 15)) * 80 + kt * 32 + (lane >> 4) * 16);
#pragma unroll
        for (int nj2 = 0; nj2 < 4; nj2++) {
            uint32_t bf[4];
            ldsm4(bf[0], bf[1], bf[2], bf[3],
                  sk + (nj2 * 16 + (lane & 7) + ((lane >> 4) << 3)) * 80
                     + kt * 32 + ((lane & 8) ? 16 : 0));
#pragma unroll
            for (int mi = 0; mi < 2; mi++) {
                mma16816(s[mi][nj2 * 2 + 0], af[mi], &bf[0]);
                mma16816(s[mi][nj2 * 2 + 1], af[mi], &bf[2]);
            }
        }
    }

    const int wy = (win >> 4) & 15, wx = win & 15;
    const bool my = (wy == 15), mx = (wx == 15);
#pragma unroll
    for (int mi = 0; mi < 2; mi++)
#pragma unroll
        for (int nj = 0; nj < 8; nj++)
#pragma unroll
            for (int e = 0; e < 4; e++) {
                const int i = wrow * 32 + mi * 16 + g + ((e >= 2) ? 8 : 0);
                const int j = nj * 8 + tg * 2 + (e & 1);
                const int iy = i >> 3, ix = i & 7, jy = j >> 3, jx = j & 7;
                float v = s[mi][nj][e] * 0.17677669529663687f
                        + srpb[((iy - jy + 7) * 15 + (ix - jx + 7)) * HEADS + head];
                const int ri = (my ? (iy < 4 ? 1 : 2) : 0) * 3 + (mx ? (ix < 4 ? 1 : 2) : 0);
                const int rj = (my ? (jy < 4 ? 1 : 2) : 0) * 3 + (mx ? (jx < 4 ? 1 : 2) : 0);
                if (ri != rj) v -= 100.f;
                s[mi][nj][e] = v;
            }
#pragma unroll
    for (int mi = 0; mi < 2; mi++)
#pragma unroll
        for (int h = 0; h < 2; h++) {
            float m = -1e30f;
#pragma unroll
            for (int nj = 0; nj < 8; nj++) {
                m = fmaxf(m, s[mi][nj][h * 2 + 0]);
                m = fmaxf(m, s[mi][nj][h * 2 + 1]);
            }
            m = fmaxf(m, __shfl_xor_sync(0xffffffffu, m, 1));
            m = fmaxf(m, __shfl_xor_sync(0xffffffffu, m, 2));
            float sum = 0.f;
#pragma unroll
            for (int nj = 0; nj < 8; nj++) {
                float e0 = __expf(s[mi][nj][h * 2 + 0] - m);
                float e1 = __expf(s[mi][nj][h * 2 + 1] - m);
                s[mi][nj][h * 2 + 0] = e0;
                s[mi][nj][h * 2 + 1] = e1;
                sum += e0 + e1;
            }
            sum += __shfl_xor_sync(0xffffffffu, sum, 1);
            sum += __shfl_xor_sync(0xffffffffu, sum, 2);
            const float inv = 1.f / sum;
#pragma unroll
            for (int nj = 0; nj < 8; nj++) {
                s[mi][nj][h * 2 + 0] *= inv;
                s[mi][nj][h * 2 + 1] *= inv;
            }
        }

    float o[2][4][4] = {};
#pragma unroll
    for (int kt = 0; kt < 4; kt++) {
        const int jr = kt * 16 + (lane & 7) + ((lane & 8) ? 8 : 0);
        const uint32_t vb = sv + jr * 80 + (lane >> 4) * 16;
        uint32_t b0[4], b1[4];
        ldsm4t(b0[0], b0[1], b0[2], b0[3], vb);
        ldsm4t(b1[0], b1[1], b1[2], b1[3], vb + 32);
#pragma unroll
        for (int mi = 0; mi < 2; mi++) {
            uint32_t a[4];
            a[0] = packbf(s[mi][2 * kt][0], s[mi][2 * kt][1]);
            a[1] = packbf(s[mi][2 * kt][2], s[mi][2 * kt][3]);
            a[2] = packbf(s[mi][2 * kt + 1][0], s[mi][2 * kt + 1][1]);
            a[3] = packbf(s[mi][2 * kt + 1][2], s[mi][2 * kt + 1][3]);
            mma16816(o[mi][0], a, &b0[0]);
            mma16816(o[mi][1], a, &b0[2]);
            mma16816(o[mi][2], a, &b1[0]);
            mma16816(o[mi][3], a, &b1[2]);
        }
    }

    __nv_bfloat16* ob = g_attn_bf + (size_t)(win * NTOK) * CH + head * HD;
#pragma unroll
    for (int mi = 0; mi < 2; mi++) {
        const int rlo = wrow * 32 + mi * 16 + g;
#pragma unroll
        for (int nf = 0; nf < 4; nf++) {
            const int d = nf * 8 + tg * 2;
            *(__nv_bfloat162*)&ob[(size_t)rlo * CH + d] =
                __floats2bfloat162_rn(o[mi][nf][0], o[mi][nf][1]);
            *(__nv_bfloat162*)&ob[(size_t)(rlo + 8) * CH + d] =
                __floats2bfloat162_rn(o[mi][nf][2], o[mi][nf][3]);
        }
    }
}

// ---------------- LN2 (reads bf16 xb2) ----------------
__global__ void ln2_kernel(const float* __restrict__ w, const float* __restrict__ bias) {
    const int gw = (blockIdx.x * blockDim.x + threadIdx.x) >> 5;
    const int lane = threadIdx.x & 31;
    if (gw >= TOK) return;
    const __nv_bfloat16* row = g_xb2bf + (size_t)gw * CH;
    float v[6];
    float s = 0.f, sq = 0.f;
#pragma unroll
    for (int k = 0; k < 6; k++) {
        v[k] = __bfloat162float(row[lane + k * 32]);
        s += v[k]; sq += v[k] * v[k];
    }
#pragma unroll
    for (int o = 16; o; o >>= 1) {
        s  += __shfl_xor_sync(0xffffffffu, s, o);
        sq += __shfl_xor_sync(0xffffffffu, sq, o);
    }
    float mean = s * (1.f / CH);
    float var = sq * (1.f / CH) - mean * mean;
    float r = rsqrtf(var + 1e-5f);
    __nv_bfloat16* orow = g_h2_bf + (size_t)gw * CH;
#pragma unroll
    for (int k = 0; k < 6; k++) {
        int cc = lane + k * 32;
        orow[cc] = __float2bfloat16((v[k] - mean) * r * w[cc] + bias[cc]);
    }
}

// ---------------- launch ----------------
extern "C" void kernel_launch(void* const* d_in, const int* in_sizes, int n_in,
                              void* d_out, int out_size) {
    (void)in_sizes; (void)n_in; (void)out_size;
    const float* x      = (const float*)d_in[0];
    const float* gn_w   = (const float*)d_in[1];
    const float* gn_b   = (const float*)d_in[2];
    const float* ln1_w  = (const float*)d_in[3];
    const float* ln1_b  = (const float*)d_in[4];
    const float* qkv_w  = (const float*)d_in[5];
    const float* qkv_b  = (const float*)d_in[6];
    const float* proj_w = (const float*)d_in[7];
    const float* proj_b = (const float*)d_in[8];
    const float* rpb    = (const float*)d_in[9];
    const float* ln2_w  = (const float*)d_in[10];
    const float* ln2_b  = (const float*)d_in[11];
    const float* fc1_w  = (const float*)d_in[12];
    const float* fc1_b  = (const float*)d_in[13];
    const float* fc2_w  = (const float*)d_in[14];
    const float* fc2_b  = (const float*)d_in[15];
    float* out = (float*)d_out;

    cudaFuncSetAttribute((const void*)attn_kernel,
                         cudaFuncAttributeMaxDynamicSharedMemorySize, ATT_SMEM);
    cudaFuncSetAttribute((const void*)mma_gemm<0>, cudaFuncAttributeMaxDynamicSharedMemorySize, GSMEM);
    cudaFuncSetAttribute((const void*)mma_gemm<1>, cudaFuncAttributeMaxDynamicSharedMemorySize, GSMEM);
    cudaFuncSetAttribute((const void*)mma_gemm<2>, cudaFuncAttributeMaxDynamicSharedMemorySize, GSMEM);
    cudaFuncSetAttribute((const void*)mma_gemm<3>, cudaFuncAttributeMaxDynamicSharedMemorySize, GSMEM);

    wtrans_all<<<432, 256>>>(qkv_w, proj_w, fc1_w, fc2_w);

    gn_partial_kernel<<<BATCH * 128, 256>>>(x);
    gn_final_kernel<<<BATCH, 128>>>();
    build_kernel<<<BATCH * HH * (WW / 32), 256>>>(x, gn_w, gn_b, ln1_w, ln1_b);

    // QKV -> head-major g_qkv_bf
    mma_gemm<0><<<dim3(6, TOK / 128), 256, GSMEM>>>(qkv_b, nullptr);

    attn_kernel<<<NWIN, 384, ATT_SMEM>>>(rpb);

    // proj: window-reverse + residual pre-sum -> g_xb2 (fp32), g_xb2bf (bf16)
    mma_gemm<1><<<dim3(2, TOK / 128), 256, GSMEM>>>(proj_b, nullptr);

    ln2_kernel<<<TOK / 8, 256>>>(ln2_w, ln2_b);

    // fc1 + GELU -> g_hid_bf
    mma_gemm<2><<<dim3(8, TOK / 128), 256, GSMEM>>>(fc1_b, nullptr);

    // fc2 + pre-summed residual + clamp -> out (NCHW)
    mma_gemm<3><<<dim3(2, TOK / 128), 256, GSMEM>>>(fc2_b, out);
}

// round 14
// speedup vs baseline: 1.0726x; 1.0159x over previous
#include <cuda_runtime.h>
#include <cuda_bf16.h>
#include <cstdint>
#include <math.h>

// Problem constants
#define BATCH 8
#define CH    192
#define HH    128
#define WW    128
#define HEADS 6
#define HD    32
#define WIN   8
#define NTOK  64
#define NWIN  2048
#define TOK   131072
#define HID   768
#define SHIFT 4

// ---------------- device scratch ----------------
__device__ __align__(256) float g_xb [TOK * CH];   // GN output NHWC fp32 (residual & shortcut)
__device__ __align__(256) float g_xb2[TOK * CH];   // xb2 + xb (pre-summed residual for fc2)
__device__ __align__(256) __nv_bfloat16 g_hw_bf [TOK * CH];
// qkv in head-major layout: [win][head][mat(q,k,v)][64 tok][32 dim]
__device__ __align__(256) __nv_bfloat16 g_qkv_bf[(size_t)TOK * 3 * CH];
__device__ __align__(256) __nv_bfloat16 g_attn_bf[TOK * CH];
__device__ __align__(256) __nv_bfloat16 g_h2_bf [TOK * CH];   // LN2 output (spatial order)
__device__ __align__(256) __nv_bfloat16 g_hid_bf[(size_t)TOK * HID];
__device__ __align__(256) __nv_bfloat16 g_wqkv[3 * CH * CH];   // [576,192] (N,K)
__device__ __align__(256) __nv_bfloat16 g_wproj[CH * CH];      // [192,192]
__device__ __align__(256) __nv_bfloat16 g_wfc1[HID * CH];      // [768,192]
__device__ __align__(256) __nv_bfloat16 g_wfc2[CH * HID];      // [192,768]
__device__ float g_part[BATCH * 128 * 2];
__device__ float g_stats[BATCH * 2];

// ---------------- helpers ----------------
__device__ __forceinline__ uint32_t s2u(const void* p) {
    uint32_t a;
    asm("{ .reg .u64 t; cvta.to.shared.u64 t, %1; cvt.u32.u64 %0, t; }" : "=r"(a) : "l"(p));
    return a;
}
__device__ __forceinline__ uint32_t sw128(uint32_t o) { return o ^ ((o >> 3) & 0x70); }

__device__ __forceinline__ void cp16(uint32_t saddr, const void* gptr) {
    asm volatile("cp.async.cg.shared.global [%0], [%1], 16;" :: "r"(saddr), "l"(gptr) : "memory");
}
__device__ __forceinline__ void cp_commit() {
    asm volatile("cp.async.commit_group;" ::: "memory");
}
__device__ __forceinline__ void cp_wait1() {
    asm volatile("cp.async.wait_group 1;" ::: "memory");
}
__device__ __forceinline__ void ldsm4(uint32_t& r0, uint32_t& r1, uint32_t& r2, uint32_t& r3,
                                      uint32_t a) {
    asm volatile("ldmatrix.sync.aligned.m8n8.x4.shared.b16 {%0,%1,%2,%3}, [%4];"
                 : "=r"(r0), "=r"(r1), "=r"(r2), "=r"(r3) : "r"(a));
}
__device__ __forceinline__ void ldsm4t(uint32_t& r0, uint32_t& r1, uint32_t& r2, uint32_t& r3,
                                       uint32_t a) {
    asm volatile("ldmatrix.sync.aligned.m8n8.x4.trans.shared.b16 {%0,%1,%2,%3}, [%4];"
                 : "=r"(r0), "=r"(r1), "=r"(r2), "=r"(r3) : "r"(a));
}
__device__ __forceinline__ void mma16816(float* c, const uint32_t* a, const uint32_t* b) {
    asm volatile(
        "mma.sync.aligned.m16n8k16.row.col.f32.bf16.bf16.f32 "
        "{%0,%1,%2,%3}, {%4,%5,%6,%7}, {%8,%9}, {%0,%1,%2,%3};"
        : "+f"(c[0]), "+f"(c[1]), "+f"(c[2]), "+f"(c[3])
        : "r"(a[0]), "r"(a[1]), "r"(a[2]), "r"(a[3]), "r"(b[0]), "r"(b[1]));
}
__device__ __forceinline__ uint32_t packbf(float a, float b) {
    __nv_bfloat162 h = __floats2bfloat162_rn(a, b);
    return *(uint32_t*)&h;
}

// ---------------- prep: GN partial sums (blocks 0..1023) + weight transposes (1024..1455) ----------------
__global__ void prep_kernel(const float* __restrict__ x,
                            const float* __restrict__ qkv_w, const float* __restrict__ proj_w,
                            const float* __restrict__ fc1_w, const float* __restrict__ fc2_w) {
    const int tid = threadIdx.x;
    if (blockIdx.x < 1024) {
        const int b = blockIdx.x >> 7;
        const int chunk = blockIdx.x & 127;
        const size_t per_sample = (size_t)CH * HH * WW;
        const float* p = x + (size_t)b * per_sample + (size_t)chunk * 24576;
        float s = 0.f, sq = 0.f;
        for (int i = tid; i < 24576; i += 256) { float v = p[i]; s += v; sq += v * v; }
        __shared__ float rs[256], rq[256];
        rs[tid] = s; rq[tid] = sq;
        __syncthreads();
        for (int o = 128; o; o >>= 1) {
            if (tid < o) { rs[tid] += rs[tid + o]; rq[tid] += rq[tid + o]; }
            __syncthreads();
        }
        if (tid == 0) {
            g_part[blockIdx.x * 2 + 0] = rs[0];
            g_part[blockIdx.x * 2 + 1] = rq[0];
        }
    } else {
        const int b = blockIdx.x - 1024;
        const float* W;
        __nv_bfloat16* Wt;
        int K, N, bx, by;
        if (b < 108)      { W = qkv_w;  Wt = g_wqkv;  K = CH;  N = 3 * CH; bx = b % 18;  by = b / 18; }
        else if (b < 144) { int t = b - 108; W = proj_w; Wt = g_wproj; K = CH;  N = CH;  bx = t % 6;  by = t / 6; }
        else if (b < 288) { int t = b - 144; W = fc1_w;  Wt = g_wfc1;  K = CH;  N = HID; bx = t % 24; by = t / 24; }
        else              { int t = b - 288; W = fc2_w;  Wt = g_wfc2;  K = HID; N = CH;  bx = t % 6;  by = t / 6; }
        __shared__ float t[32][33];
        const int k0 = by * 32, n0 = bx * 32;
        const int lx = tid & 31, ly = tid >> 5;
        for (int r = ly; r < 32; r += 8) t[r][lx] = W[(size_t)(k0 + r) * N + n0 + lx];
        __syncthreads();
        for (int r = ly; r < 32; r += 8)
            Wt[(size_t)(n0 + r) * K + k0 + lx] = __float2bfloat16(t[lx][r]);
    }
}

__global__ void gn_final_kernel() {
    const int b = blockIdx.x;
    const int tid = threadIdx.x;
    __shared__ double ds[128], dq[128];
    ds[tid] = (double)g_part[(b * 128 + tid) * 2 + 0];
    dq[tid] = (double)g_part[(b * 128 + tid) * 2 + 1];
    __syncthreads();
    for (int o = 64; o; o >>= 1) {
        if (tid < o) { ds[tid] += ds[tid + o]; dq[tid] += dq[tid + o]; }
        __syncthreads();
    }
    if (tid == 0) {
        const double n = 3145728.0;
        double mean = ds[0] / n;
        double var = dq[0] / n - mean * mean;
        g_stats[b * 2 + 0] = (float)mean;
        g_stats[b * 2 + 1] = (float)(1.0 / sqrt(var + 1e-5));
    }
}

// ---------------- GN apply + xb store + LN1 + shift + window partition ----------------
__global__ void build_kernel(const float* __restrict__ x,
                             const float* __restrict__ gnw, const float* __restrict__ gnb,
                             const float* __restrict__ ln1w, const float* __restrict__ ln1b) {
    __shared__ float t[CH][33];
    const int bid = blockIdx.x;
    const int xt = bid & 3;
    const int y  = (bid >> 2) & 127;
    const int b  = bid >> 9;
    const int tid = threadIdx.x;
    const float mu = g_stats[b * 2 + 0];
    const float rstd = g_stats[b * 2 + 1];
    const int lx = tid & 31;
    const int c0 = tid >> 5;

    for (int c = c0; c < CH; c += 8) {
        float v = x[((((size_t)b * CH + c) * HH + y) * WW) + xt * 32 + lx];
        t[c][lx] = (v - mu) * rstd * gnw[c] + gnb[c];
    }
    __syncthreads();

    const size_t tokbase = ((size_t)(b * HH + y) * WW) + xt * 32;
    for (int j = 0; j < 32; j++) {
        if (tid < CH) g_xb[(tokbase + j) * CH + tid] = t[tid][j];
    }

    const int warp = tid >> 5, lane = tid & 31;
    for (int j = warp; j < 32; j += 8) {
        float s = 0.f, sq = 0.f;
#pragma unroll
        for (int k = 0; k < 6; k++) {
            float v = t[lane + k * 32][j];
            s += v; sq += v * v;
        }
#pragma unroll
        for (int o = 16; o; o >>= 1) {
            s  += __shfl_xor_sync(0xffffffffu, s, o);
            sq += __shfl_xor_sync(0xffffffffu, sq, o);
        }
        float mean = s * (1.f / CH);
        float var = sq * (1.f / CH) - mean * mean;
        float r = rsqrtf(var + 1e-5f);
        const int xx = xt * 32 + j;
        const int ys = (y - SHIFT) & 127;
        const int xs = (xx - SHIFT) & 127;
        const size_t dst = ((size_t)(((b * 16 + (ys >> 3)) * 16 + (xs >> 3)) * NTOK)
                            + (ys & 7) * 8 + (xs & 7)) * CH;
#pragma unroll
        for (int k = 0; k < 6; k++) {
            int c = lane + k * 32;
            g_hw_bf[dst + c] = __float2bfloat16((t[c][j] - mean) * r * ln1w[c] + ln1b[c]);
        }
    }
}

// ---------------- mma.sync bf16 GEMM, CTA tile 128x96, 2-stage ----------------
// MODE 0: qkv  -> g_qkv_bf HEAD-MAJOR layout
// MODE 2: fc1  -> GELU -> g_hid_bf
// MODE 3: fc2  -> out NCHW = clamp(. + g_xb2)   [g_xb2 holds xb2 + xb]
#define GSTAGE 28672
#define GSMEM  (2 * GSTAGE)   // 57344

template <int MODE>
__global__ void __launch_bounds__(256)
mma_gemm(const float* __restrict__ bias, float* __restrict__ outp) {
    constexpr int K    = (MODE == 3) ? HID : CH;
    constexpr int NST  = K / 64;
    const __nv_bfloat16* const A  = (MODE == 0) ? g_hw_bf : (MODE == 2) ? g_h2_bf : g_hid_bf;
    const __nv_bfloat16* const Bt = (MODE == 0) ? g_wqkv : (MODE == 2) ? g_wfc1 : g_wfc2;
    constexpr int Nout = (MODE == 0) ? 3 * CH : (MODE == 2) ? HID : CH;

    extern __shared__ __align__(1024) uint8_t smx[];
    const uint32_t smb = s2u(smx);
    const int tid = threadIdx.x;
    const int wid = tid >> 5, lane = tid & 31;
    const int wm = wid & 3, wn = wid >> 2;    // 4m x 2n
    const int m0 = blockIdx.y * 128;
    const int n0c = blockIdx.x * 96;

    const __nv_bfloat16* const Abase = A  + (size_t)m0 * K;
    const __nv_bfloat16* const Bbase = Bt + (size_t)n0c * K;

    auto load_stage = [&](int st, int buf) {
        const uint32_t sA = smb + buf * GSTAGE;
        const uint32_t sB = sA + 16384;
        const int kel = st * 64;
#pragma unroll
        for (int i = 0; i < 4; i++) {            // A: 128 rows x 128B
            int e = tid + i * 256;
            int row = e >> 3, c16 = e & 7;
            cp16(sA + sw128(row * 128 + c16 * 16), Abase + (size_t)row * K + kel + c16 * 8);
        }
#pragma unroll
        for (int i = 0; i < 3; i++) {            // B: 96 rows x 128B
            int e = tid + i * 256;
            int row = e >> 3, c16 = e & 7;
            cp16(sB + sw128(row * 128 + c16 * 16), Bbase + (size_t)row * K + kel + c16 * 8);
        }
    };

    float acc[2][6][4] = {};

    const int arow0 = wm * 32 + (lane & 15);
    const int akoff = (lane >> 4) * 16;
    const int brow0 = wn * 48 + (lane & 7) + ((lane >> 4) << 3);
    const int bkoff = (lane & 8) ? 16 : 0;

    load_stage(0, 0); cp_commit();
    load_stage(1, 1); cp_commit();

    for (int st = 0; st < NST; st++) {
        cp_wait1();
        __syncthreads();
        const int buf = st & 1;
        const uint32_t sA = smb + buf * GSTAGE;
        const uint32_t sB = sA + 16384;
#pragma unroll
        for (int kk = 0; kk < 4; kk++) {
            uint32_t af[2][4], bf[3][4];
#pragma unroll
            for (int mi = 0; mi < 2; mi++)
                ldsm4(af[mi][0], af[mi][1], af[mi][2], af[mi][3],
                      sA + sw128((arow0 + mi * 16) * 128 + kk * 32 + akoff));
#pragma unroll
            for (int bi = 0; bi < 3; bi++)
                ldsm4(bf[bi][0], bf[bi][1], bf[bi][2], bf[bi][3],
                      sB + sw128((brow0 + bi * 16) * 128 + kk * 32 + bkoff));
#pragma unroll
            for (int mi = 0; mi < 2; mi++)
#pragma unroll
                for (int ni = 0; ni < 6; ni++)
                    mma16816(acc[mi][ni], af[mi], &bf[ni >> 1][(ni & 1) * 2]);
        }
        __syncthreads();
        if (st + 2 < NST) load_stage(st + 2, buf);
        cp_commit();
    }

    // ---- epilogue ----
    const int g = lane >> 2, tg = lane & 3;
    const int nbase = n0c + wn * 48;
    float2 bv[6];
#pragma unroll
    for (int ni = 0; ni < 6; ni++) bv[ni] = *(const float2*)&bias[nbase + ni * 8 + tg * 2];

#pragma unroll
    for (int mi = 0; mi < 2; mi++) {
#pragma unroll
        for (int half = 0; half < 2; half++) {
            const int r = m0 + wm * 32 + mi * 16 + g + half * 8;
            if (MODE == 0) {
                const int win = r >> 6, tok = r & 63;
#pragma unroll
                for (int ni = 0; ni < 6; ni++) {
                    const int c = nbase + ni * 8 + tg * 2;
                    const int mat = c / 192, hc = c - mat * 192;
                    const int head = hc >> 5, dim = hc & 31;
                    float v0 = acc[mi][ni][half * 2 + 0] + bv[ni].x;
                    float v1 = acc[mi][ni][half * 2 + 1] + bv[ni].y;
                    __nv_bfloat162 h2 = __floats2bfloat162_rn(v0, v1);
                    *(__nv_bfloat162*)&g_qkv_bf[(((size_t)win * HEADS + head) * 3 + mat) * 2048
                                                + tok * 32 + dim] = h2;
                }
            } else if (MODE == 2) {
#pragma unroll
                for (int ni = 0; ni < 6; ni++) {
                    float v0 = acc[mi][ni][half * 2 + 0] + bv[ni].x;
                    float v1 = acc[mi][ni][half * 2 + 1] + bv[ni].y;
                    v0 = 0.5f * v0 * (1.f + erff(v0 * 0.7071067811865475f));
                    v1 = 0.5f * v1 * (1.f + erff(v1 * 0.7071067811865475f));
                    __nv_bfloat162 h2 = __floats2bfloat162_rn(v0, v1);
                    *(__nv_bfloat162*)&g_hid_bf[(size_t)r * Nout + nbase + ni * 8 + tg * 2] = h2;
                }
            } else {
                const int bb2 = r >> 14, yy = (r >> 7) & 127, xx = r & 127;
                const size_t off = (size_t)r * CH;
                const size_t obase = (((size_t)bb2 * CH) * HH + yy) * WW + xx;
#pragma unroll
                for (int ni = 0; ni < 6; ni++) {
                    const size_t o = off + nbase + ni * 8 + tg * 2;
                    float2 a2 = *(const float2*)&g_xb2[o];
                    float v0 = acc[mi][ni][half * 2 + 0] + bv[ni].x + a2.x;
                    float v1 = acc[mi][ni][half * 2 + 1] + bv[ni].y + a2.y;
                    v0 = fminf(10.f, fmaxf(-10.f, v0));
                    v1 = fminf(10.f, fmaxf(-10.f, v1));
                    const int c = nbase + ni * 8 + tg * 2;
                    outp[obase + (size_t)c * (HH * WW)] = v0;
                    outp[obase + (size_t)(c + 1) * (HH * WW)] = v1;
                }
            }
        }
    }
}

// ---------------- fused proj + LN2: one window per CTA (M=64, N=192) ----------------
// 256 threads = 8 warps (2m x 4n); warp tile 32x48. 2-stage cp.async, K=192.
// Epilogue: xb2 = proj + bias + xb (window-reverse scatter);
//   g_xb2 = xb2 + xb (fp32, for fc2); LN2(xb2) -> g_h2_bf (spatial order).
#define PSTAGE 32768            // A 8KB + B 24KB
#define PSMEM  (2 * PSTAGE + 2048)

__global__ void __launch_bounds__(256, 2)
proj_ln2(const float* __restrict__ bias,
         const float* __restrict__ ln2w, const float* __restrict__ ln2b) {
    constexpr int K = CH;
    extern __shared__ __align__(1024) uint8_t smx[];
    const uint32_t smb = s2u(smx);
    const int tid = threadIdx.x;
    const int wid = tid >> 5, lane = tid & 31;
    const int wm = wid & 1, wn = wid >> 1;     // 2m x 4n
    const int win = blockIdx.x;
    const int m0 = win * 64;

    const __nv_bfloat16* const Abase = g_attn_bf + (size_t)m0 * K;

    auto load_stage = [&](int st, int buf) {
        const uint32_t sA = smb + buf * PSTAGE;
        const uint32_t sB = sA + 8192;
        const int kel = st * 64;
#pragma unroll
        for (int i = 0; i < 2; i++) {            // A: 64 rows x 128B
            int e = tid + i * 256;
            int row = e >> 3, c16 = e & 7;
            cp16(sA + sw128(row * 128 + c16 * 16), Abase + (size_t)row * K + kel + c16 * 8);
        }
#pragma unroll
        for (int i = 0; i < 6; i++) {            // B: 192 rows x 128B
            int e = tid + i * 256;
            int row = e >> 3, c16 = e & 7;
            cp16(sB + sw128(row * 128 + c16 * 16), g_wproj + (size_t)row * K + kel + c16 * 8);
        }
    };

    float acc[2][6][4] = {};
    const int arow0 = wm * 32 + (lane & 15);
    const int akoff = (lane >> 4) * 16;
    const int brow0 = wn * 48 + (lane & 7) + ((lane >> 4) << 3);
    const int bkoff = (lane & 8) ? 16 : 0;

    load_stage(0, 0); cp_commit();
    load_stage(1, 1); cp_commit();

    for (int st = 0; st < 3; st++) {
        cp_wait1();
        __syncthreads();
        const int buf = st & 1;
        const uint32_t sA = smb + buf * PSTAGE;
        const uint32_t sB = sA + 8192;
#pragma unroll
        for (int kk = 0; kk < 4; kk++) {
            uint32_t af[2][4], bf[3][4];
#pragma unroll
            for (int mi = 0; mi < 2; mi++)
                ldsm4(af[mi][0], af[mi][1], af[mi][2], af[mi][3],
                      sA + sw128((arow0 + mi * 16) * 128 + kk * 32 + akoff));
#pragma unroll
            for (int bi = 0; bi < 3; bi++)
                ldsm4(bf[bi][0], bf[bi][1], bf[bi][2], bf[bi][3],
                      sB + sw128((brow0 + bi * 16) * 128 + kk * 32 + bkoff));
#pragma unroll
            for (int mi = 0; mi < 2; mi++)
#pragma unroll
                for (int ni = 0; ni < 6; ni++)
                    mma16816(acc[mi][ni], af[mi], &bf[ni >> 1][(ni & 1) * 2]);
        }
        __syncthreads();
        if (st + 2 < 3) load_stage(st + 2, buf);
        cp_commit();
    }
    __syncthreads();   // stage smem now reusable

    float* sx = (float*)smx;                     // [64][196] xb2 scratch
    float2* spart = (float2*)(smx + 50176);      // [64][4] (sum, sumsq)

    const int g = lane >> 2, tg = lane & 3;
    const int nbase = wn * 48;
    float2 bv[6], lw[6], lb[6];
#pragma unroll
    for (int ni = 0; ni < 6; ni++) {
        bv[ni] = *(const float2*)&bias[nbase + ni * 8 + tg * 2];
        lw[ni] = *(const float2*)&ln2w[nbase + ni * 8 + tg * 2];
        lb[ni] = *(const float2*)&ln2b[nbase + ni * 8 + tg * 2];
    }

    const int bb2 = win >> 8, wy = (win >> 4) & 15, wx = win & 15;

#pragma unroll
    for (int mi = 0; mi < 2; mi++) {
#pragma unroll
        for (int half = 0; half < 2; half++) {
            const int rl = wm * 32 + mi * 16 + g + half * 8;
            const int yy = ((wy << 3) + (rl >> 3) + SHIFT) & 127;
            const int xx = ((wx << 3) + (rl & 7) + SHIFT) & 127;
            const size_t dr = ((size_t)((bb2 * HH + yy) * WW + xx)) * CH;
            float s = 0.f, sq = 0.f;
#pragma unroll
            for (int ni = 0; ni < 6; ni++) {
                const int c = nbase + ni * 8 + tg * 2;
                float2 xbv = *(const float2*)&g_xb[dr + c];
                float x2a = acc[mi][ni][half * 2 + 0] + bv[ni].x + xbv.x;
                float x2b = acc[mi][ni][half * 2 + 1] + bv[ni].y + xbv.y;
                float2 ov;
                ov.x = x2a + xbv.x; ov.y = x2b + xbv.y;
                *(float2*)&g_xb2[dr + c] = ov;
                sx[rl * 196 + c] = x2a;
                sx[rl * 196 + c + 1] = x2b;
                s += x2a + x2b;
                sq += x2a * x2a + x2b * x2b;
            }
            s  += __shfl_xor_sync(0xffffffffu, s, 1);
            s  += __shfl_xor_sync(0xffffffffu, s, 2);
            sq += __shfl_xor_sync(0xffffffffu, sq, 1);
            sq += __shfl_xor_sync(0xffffffffu, sq, 2);
            if (tg == 0) { spart[rl * 4 + wn] = make_float2(s, sq); }
        }
    }
    __syncthreads();

#pragma unroll
    for (int mi = 0; mi < 2; mi++) {
#pragma unroll
        for (int half = 0; half < 2; half++) {
            const int rl = wm * 32 + mi * 16 + g + half * 8;
            float s = 0.f, sq = 0.f;
#pragma unroll
            for (int p = 0; p < 4; p++) {
                float2 pp = spart[rl * 4 + p];
                s += pp.x; sq += pp.y;
            }
            float mean = s * (1.f / CH);
            float var = sq * (1.f / CH) - mean * mean;
            float rstd = rsqrtf(var + 1e-5f);
            const int yy = ((wy << 3) + (rl >> 3) + SHIFT) & 127;
            const int xx = ((wx << 3) + (rl & 7) + SHIFT) & 127;
            const size_t dr = ((size_t)((bb2 * HH + yy) * WW + xx)) * CH;
#pragma unroll
            for (int ni = 0; ni < 6; ni++) {
                const int c = nbase + ni * 8 + tg * 2;
                float x2a = sx[rl * 196 + c];
                float x2b = sx[rl * 196 + c + 1];
                float h0 = (x2a - mean) * rstd * lw[ni].x + lb[ni].x;
                float h1 = (x2b - mean) * rstd * lw[ni].y + lb[ni].y;
                *(uint32_t*)&g_h2_bf[dr + c] = packbf(h0, h1);
            }
        }
    }
}

// ---------------- tensor-core windowed attention ----------------
#define ATT_SLICE 5120
#define ATT_QKV   (18 * ATT_SLICE)
#define ATT_SMEM  (ATT_QKV + 5408)
__global__ void __launch_bounds__(384)
attn_kernel(const float* __restrict__ rpb) {
    extern __shared__ __align__(128) uint8_t smem_a[];
    float* srpb = (float*)(smem_a + ATT_QKV);
    const int win = blockIdx.x;
    const int tid = threadIdx.x;
    const int wid = tid >> 5, lane = tid & 31;
    const int head = wid >> 1, wrow = wid & 1;
    const int g = lane >> 2, tg = lane & 3;

    for (int f = tid; f < 225 * HEADS; f += 384) srpb[f] = rpb[f];

    {
        const __nv_bfloat16* gb = g_qkv_bf + (size_t)win * 18 * 2048;
#pragma unroll
        for (int i = 0; i < 12; i++) {
            int idx = tid + i * 384;
            int slice = idx >> 8;
            int cidx = idx & 255;
            int row = cidx >> 2, ch = cidx & 3;
            uint4 v = *(const uint4*)(gb + slice * 2048 + cidx * 8);
            *(uint4*)(smem_a + slice * ATT_SLICE + row * 80 + ch * 16) = v;
        }
    }
    __syncthreads();

    const uint32_t sq = s2u(smem_a) + (head * 3 + 0) * ATT_SLICE;
    const uint32_t sk = sq + ATT_SLICE;
    const uint32_t sv = sq + 2 * ATT_SLICE;

    float s[2][8][4] = {};
#pragma unroll
    for (int kt = 0; kt < 2; kt++) {
        uint32_t af[2][4];
#pragma unroll
        for (int mi = 0; mi < 2; mi++)
            ldsm4(af[mi][0], af[mi][1], af[mi][2], af[mi][3],
                  sq + (wrow * 32 + mi * 16 + (lane & 15)) * 80 + kt * 32 + (lane >> 4) * 16);
#pragma unroll
        for (int nj2 = 0; nj2 < 4; nj2++) {
            uint32_t bf[4];
            ldsm4(bf[0], bf[1], bf[2], bf[3],
                  sk + (nj2 * 16 + (lane & 7) + ((lane >> 4) << 3)) * 80
                     + kt * 32 + ((lane & 8) ? 16 : 0));
#pragma unroll
            for (int mi = 0; mi < 2; mi++) {
                mma16816(s[mi][nj2 * 2 + 0], af[mi], &bf[0]);
                mma16816(s[mi][nj2 * 2 + 1], af[mi], &bf[2]);
            }
        }
    }

    const int wy = (win >> 4) & 15, wx = win & 15;
    const bool my = (wy == 15), mx = (wx == 15);
#pragma unroll
    for (int mi = 0; mi < 2; mi++)
#pragma unroll
        for (int nj = 0; nj < 8; nj++)
#pragma unroll
            for (int e = 0; e < 4; e++) {
                const int i = wrow * 32 + mi * 16 + g + ((e >= 2) ? 8 : 0);
                const int j = nj * 8 + tg * 2 + (e & 1);
                const int iy = i >> 3, ix = i & 7, jy = j >> 3, jx = j & 7;
                float v = s[mi][nj][e] * 0.17677669529663687f
                        + srpb[((iy - jy + 7) * 15 + (ix - jx + 7)) * HEADS + head];
                const int ri = (my ? (iy < 4 ? 1 : 2) : 0) * 3 + (mx ? (ix < 4 ? 1 : 2) : 0);
                const int rj = (my ? (jy < 4 ? 1 : 2) : 0) * 3 + (mx ? (jx < 4 ? 1 : 2) : 0);
                if (ri != rj) v -= 100.f;
                s[mi][nj][e] = v;
            }
#pragma unroll
    for (int mi = 0; mi < 2; mi++)
#pragma unroll
        for (int h = 0; h < 2; h++) {
            float m = -1e30f;
#pragma unroll
            for (int nj = 0; nj < 8; nj++) {
                m = fmaxf(m, s[mi][nj][h * 2 + 0]);
                m = fmaxf(m, s[mi][nj][h * 2 + 1]);
            }
            m = fmaxf(m, __shfl_xor_sync(0xffffffffu, m, 1));
            m = fmaxf(m, __shfl_xor_sync(0xffffffffu, m, 2));
            float sum = 0.f;
#pragma unroll
            for (int nj = 0; nj < 8; nj++) {
                float e0 = __expf(s[mi][nj][h * 2 + 0] - m);
                float e1 = __expf(s[mi][nj][h * 2 + 1] - m);
                s[mi][nj][h * 2 + 0] = e0;
                s[mi][nj][h * 2 + 1] = e1;
                sum += e0 + e1;
            }
            sum += __shfl_xor_sync(0xffffffffu, sum, 1);
            sum += __shfl_xor_sync(0xffffffffu, sum, 2);
            const float inv = 1.f / sum;
#pragma unroll
            for (int nj = 0; nj < 8; nj++) {
                s[mi][nj][h * 2 + 0] *= inv;
                s[mi][nj][h * 2 + 1] *= inv;
            }
        }

    float o[2][4][4] = {};
#pragma unroll
    for (int kt = 0; kt < 4; kt++) {
        const int jr = kt * 16 + (lane & 7) + ((lane & 8) ? 8 : 0);
        const uint32_t vb = sv + jr * 80 + (lane >> 4) * 16;
        uint32_t b0[4], b1[4];
        ldsm4t(b0[0], b0[1], b0[2], b0[3], vb);
        ldsm4t(b1[0], b1[1], b1[2], b1[3], vb + 32);
#pragma unroll
        for (int mi = 0; mi < 2; mi++) {
            uint32_t a[4];
            a[0] = packbf(s[mi][2 * kt][0], s[mi][2 * kt][1]);
            a[1] = packbf(s[mi][2 * kt][2], s[mi][2 * kt][3]);
            a[2] = packbf(s[mi][2 * kt + 1][0], s[mi][2 * kt + 1][1]);
            a[3] = packbf(s[mi][2 * kt + 1][2], s[mi][2 * kt + 1][3]);
            mma16816(o[mi][0], a, &b0[0]);
            mma16816(o[mi][1], a, &b0[2]);
            mma16816(o[mi][2], a, &b1[0]);
            mma16816(o[mi][3], a, &b1[2]);
        }
    }

    __nv_bfloat16* ob = g_attn_bf + (size_t)(win * NTOK) * CH + head * HD;
#pragma unroll
    for (int mi = 0; mi < 2; mi++) {
        const int rlo = wrow * 32 + mi * 16 + g;
#pragma unroll
        for (int nf = 0; nf < 4; nf++) {
            const int d = nf * 8 + tg * 2;
            *(__nv_bfloat162*)&ob[(size_t)rlo * CH + d] =
                __floats2bfloat162_rn(o[mi][nf][0], o[mi][nf][1]);
            *(__nv_bfloat162*)&ob[(size_t)(rlo + 8) * CH + d] =
                __floats2bfloat162_rn(o[mi][nf][2], o[mi][nf][3]);
        }
    }
}

// ---------------- launch ----------------
extern "C" void kernel_launch(void* const* d_in, const int* in_sizes, int n_in,
                              void* d_out, int out_size) {
    (void)in_sizes; (void)n_in; (void)out_size;
    const float* x      = (const float*)d_in[0];
    const float* gn_w   = (const float*)d_in[1];
    const float* gn_b   = (const float*)d_in[2];
    const float* ln1_w  = (const float*)d_in[3];
    const float* ln1_b  = (const float*)d_in[4];
    const float* qkv_w  = (const float*)d_in[5];
    const float* qkv_b  = (const float*)d_in[6];
    const float* proj_w = (const float*)d_in[7];
    const float* proj_b = (const float*)d_in[8];
    const float* rpb    = (const float*)d_in[9];
    const float* ln2_w  = (const float*)d_in[10];
    const float* ln2_b  = (const float*)d_in[11];
    const float* fc1_w  = (const float*)d_in[12];
    const float* fc1_b  = (const float*)d_in[13];
    const float* fc2_w  = (const float*)d_in[14];
    const float* fc2_b  = (const float*)d_in[15];
    float* out = (float*)d_out;

    cudaFuncSetAttribute((const void*)attn_kernel,
                         cudaFuncAttributeMaxDynamicSharedMemorySize, ATT_SMEM);
    cudaFuncSetAttribute((const void*)mma_gemm<0>, cudaFuncAttributeMaxDynamicSharedMemorySize, GSMEM);
    cudaFuncSetAttribute((const void*)mma_gemm<2>, cudaFuncAttributeMaxDynamicSharedMemorySize, GSMEM);
    cudaFuncSetAttribute((const void*)mma_gemm<3>, cudaFuncAttributeMaxDynamicSharedMemorySize, GSMEM);
    cudaFuncSetAttribute((const void*)proj_ln2, cudaFuncAttributeMaxDynamicSharedMemorySize, PSMEM);

    // GN partial sums + weight transposes in one launch
    prep_kernel<<<1456, 256>>>(x, qkv_w, proj_w, fc1_w, fc2_w);
    gn_final_kernel<<<BATCH, 128>>>();
    build_kernel<<<BATCH * HH * (WW / 32), 256>>>(x, gn_w, gn_b, ln1_w, ln1_b);

    // QKV -> head-major g_qkv_bf
    mma_gemm<0><<<dim3(6, TOK / 128), 256, GSMEM>>>(qkv_b, nullptr);

    attn_kernel<<<NWIN, 384, ATT_SMEM>>>(rpb);

    // fused proj + residual pre-sum + LN2 -> g_xb2 (fp32), g_h2_bf (bf16)
    proj_ln2<<<NWIN, 256, PSMEM>>>(proj_b, ln2_w, ln2_b);

    // fc1 + GELU -> g_hid_bf
    mma_gemm<2><<<dim3(8, TOK / 128), 256, GSMEM>>>(fc1_b, nullptr);

    // fc2 + pre-summed residual + clamp -> out (NCHW)
    mma_gemm<3><<<dim3(2, TOK / 128), 256, GSMEM>>>(fc2_b, out);
}

// round 15
// speedup vs baseline: 1.1279x; 1.0515x over previous
#include <cuda_runtime.h>
#include <cuda_bf16.h>
#include <cstdint>
#include <math.h>

// Problem constants
#define BATCH 8
#define CH    192
#define HH    128
#define WW    128
#define HEADS 6
#define HD    32
#define WIN   8
#define NTOK  64
#define NWIN  2048
#define TOK   131072
#define HID   768
#define SHIFT 4

// ---------------- device scratch ----------------
__device__ __align__(256) float g_xb [TOK * CH];   // GN output NHWC fp32 (residual & shortcut)
__device__ __align__(256) float g_xb2[TOK * CH];   // xb2 + xb (pre-summed residual for fc2)
__device__ __align__(256) __nv_bfloat16 g_hw_bf [TOK * CH];
// qkv in head-major layout: [win][head][mat(q,k,v)][64 tok][32 dim]
__device__ __align__(256) __nv_bfloat16 g_qkv_bf[(size_t)TOK * 3 * CH];
__device__ __align__(256) __nv_bfloat16 g_attn_bf[TOK * CH];
__device__ __align__(256) __nv_bfloat16 g_h2_bf [TOK * CH];   // LN2 output (spatial order)
__device__ __align__(256) __nv_bfloat16 g_hid_bf[(size_t)TOK * HID];
__device__ __align__(256) __nv_bfloat16 g_wqkv[3 * CH * CH];   // [576,192] (N,K)
__device__ __align__(256) __nv_bfloat16 g_wproj[CH * CH];      // [192,192]
__device__ __align__(256) __nv_bfloat16 g_wfc1[HID * CH];      // [768,192]
__device__ __align__(256) __nv_bfloat16 g_wfc2[CH * HID];      // [192,768]
__device__ float g_part[BATCH * 128 * 2];
__device__ float g_stats[BATCH * 2];

// ---------------- helpers ----------------
__device__ __forceinline__ uint32_t s2u(const void* p) {
    uint32_t a;
    asm("{ .reg .u64 t; cvta.to.shared.u64 t, %1; cvt.u32.u64 %0, t; }" : "=r"(a) : "l"(p));
    return a;
}
__device__ __forceinline__ uint32_t sw128(uint32_t o) { return o ^ ((o >> 3) & 0x70); }

__device__ __forceinline__ void cp16(uint32_t saddr, const void* gptr) {
    asm volatile("cp.async.cg.shared.global [%0], [%1], 16;" :: "r"(saddr), "l"(gptr) : "memory");
}
__device__ __forceinline__ void cp_commit() {
    asm volatile("cp.async.commit_group;" ::: "memory");
}
__device__ __forceinline__ void cp_wait2() {
    asm volatile("cp.async.wait_group 2;" ::: "memory");
}
__device__ __forceinline__ void ldsm4(uint32_t& r0, uint32_t& r1, uint32_t& r2, uint32_t& r3,
                                      uint32_t a) {
    asm volatile("ldmatrix.sync.aligned.m8n8.x4.shared.b16 {%0,%1,%2,%3}, [%4];"
                 : "=r"(r0), "=r"(r1), "=r"(r2), "=r"(r3) : "r"(a));
}
__device__ __forceinline__ void ldsm4t(uint32_t& r0, uint32_t& r1, uint32_t& r2, uint32_t& r3,
                                       uint32_t a) {
    asm volatile("ldmatrix.sync.aligned.m8n8.x4.trans.shared.b16 {%0,%1,%2,%3}, [%4];"
                 : "=r"(r0), "=r"(r1), "=r"(r2), "=r"(r3) : "r"(a));
}
__device__ __forceinline__ void mma16816(float* c, const uint32_t* a, const uint32_t* b) {
    asm volatile(
        "mma.sync.aligned.m16n8k16.row.col.f32.bf16.bf16.f32 "
        "{%0,%1,%2,%3}, {%4,%5,%6,%7}, {%8,%9}, {%0,%1,%2,%3};"
        : "+f"(c[0]), "+f"(c[1]), "+f"(c[2]), "+f"(c[3])
        : "r"(a[0]), "r"(a[1]), "r"(a[2]), "r"(a[3]), "r"(b[0]), "r"(b[1]));
}
__device__ __forceinline__ uint32_t packbf(float a, float b) {
    __nv_bfloat162 h = __floats2bfloat162_rn(a, b);
    return *(uint32_t*)&h;
}

// ---------------- prep: GN partial sums (blocks 0..1023) + weight transposes (1024..1455) ----------------
__global__ void prep_kernel(const float* __restrict__ x,
                            const float* __restrict__ qkv_w, const float* __restrict__ proj_w,
                            const float* __restrict__ fc1_w, const float* __restrict__ fc2_w) {
    const int tid = threadIdx.x;
    if (blockIdx.x < 1024) {
        const int b = blockIdx.x >> 7;
        const int chunk = blockIdx.x & 127;
        const size_t per_sample = (size_t)CH * HH * WW;
        const float* p = x + (size_t)b * per_sample + (size_t)chunk * 24576;
        float s = 0.f, sq = 0.f;
        for (int i = tid; i < 24576; i += 256) { float v = p[i]; s += v; sq += v * v; }
        __shared__ float rs[256], rq[256];
        rs[tid] = s; rq[tid] = sq;
        __syncthreads();
        for (int o = 128; o; o >>= 1) {
            if (tid < o) { rs[tid] += rs[tid + o]; rq[tid] += rq[tid + o]; }
            __syncthreads();
        }
        if (tid == 0) {
            g_part[blockIdx.x * 2 + 0] = rs[0];
            g_part[blockIdx.x * 2 + 1] = rq[0];
        }
    } else {
        const int b = blockIdx.x - 1024;
        const float* W;
        __nv_bfloat16* Wt;
        int K, N, bx, by;
        if (b < 108)      { W = qkv_w;  Wt = g_wqkv;  K = CH;  N = 3 * CH; bx = b % 18;  by = b / 18; }
        else if (b < 144) { int t = b - 108; W = proj_w; Wt = g_wproj; K = CH;  N = CH;  bx = t % 6;  by = t / 6; }
        else if (b < 288) { int t = b - 144; W = fc1_w;  Wt = g_wfc1;  K = CH;  N = HID; bx = t % 24; by = t / 24; }
        else              { int t = b - 288; W = fc2_w;  Wt = g_wfc2;  K = HID; N = CH;  bx = t % 6;  by = t / 6; }
        __shared__ float t[32][33];
        const int k0 = by * 32, n0 = bx * 32;
        const int lx = tid & 31, ly = tid >> 5;
        for (int r = ly; r < 32; r += 8) t[r][lx] = W[(size_t)(k0 + r) * N + n0 + lx];
        __syncthreads();
        for (int r = ly; r < 32; r += 8)
            Wt[(size_t)(n0 + r) * K + k0 + lx] = __float2bfloat16(t[lx][r]);
    }
}

__global__ void gn_final_kernel() {
    const int b = blockIdx.x;
    const int tid = threadIdx.x;
    __shared__ double ds[128], dq[128];
    ds[tid] = (double)g_part[(b * 128 + tid) * 2 + 0];
    dq[tid] = (double)g_part[(b * 128 + tid) * 2 + 1];
    __syncthreads();
    for (int o = 64; o; o >>= 1) {
        if (tid < o) { ds[tid] += ds[tid + o]; dq[tid] += dq[tid + o]; }
        __syncthreads();
    }
    if (tid == 0) {
        const double n = 3145728.0;
        double mean = ds[0] / n;
        double var = dq[0] / n - mean * mean;
        g_stats[b * 2 + 0] = (float)mean;
        g_stats[b * 2 + 1] = (float)(1.0 / sqrt(var + 1e-5));
    }
}

// ---------------- GN apply + xb store + LN1 + shift + window partition ----------------
__global__ void build_kernel(const float* __restrict__ x,
                             const float* __restrict__ gnw, const float* __restrict__ gnb,
                             const float* __restrict__ ln1w, const float* __restrict__ ln1b) {
    __shared__ float t[CH][33];
    const int bid = blockIdx.x;
    const int xt = bid & 3;
    const int y  = (bid >> 2) & 127;
    const int b  = bid >> 9;
    const int tid = threadIdx.x;
    const float mu = g_stats[b * 2 + 0];
    const float rstd = g_stats[b * 2 + 1];
    const int lx = tid & 31;
    const int c0 = tid >> 5;

    for (int c = c0; c < CH; c += 8) {
        float v = x[((((size_t)b * CH + c) * HH + y) * WW) + xt * 32 + lx];
        t[c][lx] = (v - mu) * rstd * gnw[c] + gnb[c];
    }
    __syncthreads();

    const size_t tokbase = ((size_t)(b * HH + y) * WW) + xt * 32;
    for (int j = 0; j < 32; j++) {
        if (tid < CH) g_xb[(tokbase + j) * CH + tid] = t[tid][j];
    }

    const int warp = tid >> 5, lane = tid & 31;
    for (int j = warp; j < 32; j += 8) {
        float s = 0.f, sq = 0.f;
#pragma unroll
        for (int k = 0; k < 6; k++) {
            float v = t[lane + k * 32][j];
            s += v; sq += v * v;
        }
#pragma unroll
        for (int o = 16; o; o >>= 1) {
            s  += __shfl_xor_sync(0xffffffffu, s, o);
            sq += __shfl_xor_sync(0xffffffffu, sq, o);
        }
        float mean = s * (1.f / CH);
        float var = sq * (1.f / CH) - mean * mean;
        float r = rsqrtf(var + 1e-5f);
        const int xx = xt * 32 + j;
        const int ys = (y - SHIFT) & 127;
        const int xs = (xx - SHIFT) & 127;
        const size_t dst = ((size_t)(((b * 16 + (ys >> 3)) * 16 + (xs >> 3)) * NTOK)
                            + (ys & 7) * 8 + (xs & 7)) * CH;
#pragma unroll
        for (int k = 0; k < 6; k++) {
            int c = lane + k * 32;
            g_hw_bf[dst + c] = __float2bfloat16((t[c][j] - mean) * r * ln1w[c] + ln1b[c]);
        }
    }
}

// ---------------- mma.sync bf16 GEMM, CTA tile 128x96, 3-stage ----------------
// MODE 0: qkv  -> g_qkv_bf HEAD-MAJOR layout
// MODE 2: fc1  -> GELU -> g_hid_bf
// MODE 3: fc2  -> out NCHW = clamp(. + g_xb2)   [g_xb2 holds xb2 + xb]
#define GSTAGE 28672
#define GSMEM  (3 * GSTAGE)   // 86016

template <int MODE>
__global__ void __launch_bounds__(256)
mma_gemm(const float* __restrict__ bias, float* __restrict__ outp) {
    constexpr int K    = (MODE == 3) ? HID : CH;
    constexpr int NST  = K / 64;
    const __nv_bfloat16* const A  = (MODE == 0) ? g_hw_bf : (MODE == 2) ? g_h2_bf : g_hid_bf;
    const __nv_bfloat16* const Bt = (MODE == 0) ? g_wqkv : (MODE == 2) ? g_wfc1 : g_wfc2;
    constexpr int Nout = (MODE == 0) ? 3 * CH : (MODE == 2) ? HID : CH;

    extern __shared__ __align__(1024) uint8_t smx[];
    const uint32_t smb = s2u(smx);
    const int tid = threadIdx.x;
    const int wid = tid >> 5, lane = tid & 31;
    const int wm = wid & 3, wn = wid >> 2;    // 4m x 2n
    const int m0 = blockIdx.y * 128;
    const int n0c = blockIdx.x * 96;

    const __nv_bfloat16* const Abase = A  + (size_t)m0 * K;
    const __nv_bfloat16* const Bbase = Bt + (size_t)n0c * K;

    auto load_stage = [&](int st) {
        const uint32_t sA = smb + (st % 3) * GSTAGE;
        const uint32_t sB = sA + 16384;
        const int kel = st * 64;
#pragma unroll
        for (int i = 0; i < 4; i++) {            // A: 128 rows x 128B
            int e = tid + i * 256;
            int row = e >> 3, c16 = e & 7;
            cp16(sA + sw128(row * 128 + c16 * 16), Abase + (size_t)row * K + kel + c16 * 8);
        }
#pragma unroll
        for (int i = 0; i < 3; i++) {            // B: 96 rows x 128B
            int e = tid + i * 256;
            int row = e >> 3, c16 = e & 7;
            cp16(sB + sw128(row * 128 + c16 * 16), Bbase + (size_t)row * K + kel + c16 * 8);
        }
    };

    float acc[2][6][4] = {};

    const int arow0 = wm * 32 + (lane & 15);
    const int akoff = (lane >> 4) * 16;
    const int brow0 = wn * 48 + (lane & 7) + ((lane >> 4) << 3);
    const int bkoff = (lane & 8) ? 16 : 0;

    load_stage(0); cp_commit();
    load_stage(1); cp_commit();
    load_stage(2); cp_commit();

    for (int st = 0; st < NST; st++) {
        cp_wait2();
        __syncthreads();
        const uint32_t sA = smb + (st % 3) * GSTAGE;
        const uint32_t sB = sA + 16384;
#pragma unroll
        for (int kk = 0; kk < 4; kk++) {
            uint32_t af[2][4], bf[3][4];
#pragma unroll
            for (int mi = 0; mi < 2; mi++)
                ldsm4(af[mi][0], af[mi][1], af[mi][2], af[mi][3],
                      sA + sw128((arow0 + mi * 16) * 128 + kk * 32 + akoff));
#pragma unroll
            for (int bi = 0; bi < 3; bi++)
                ldsm4(bf[bi][0], bf[bi][1], bf[bi][2], bf[bi][3],
                      sB + sw128((brow0 + bi * 16) * 128 + kk * 32 + bkoff));
#pragma unroll
            for (int mi = 0; mi < 2; mi++)
#pragma unroll
                for (int ni = 0; ni < 6; ni++)
                    mma16816(acc[mi][ni], af[mi], &bf[ni >> 1][(ni & 1) * 2]);
        }
        __syncthreads();
        if (st + 3 < NST) load_stage(st + 3);
        cp_commit();
    }

    // ---- epilogue ----
    const int g = lane >> 2, tg = lane & 3;
    const int nbase = n0c + wn * 48;
    float2 bv[6];
#pragma unroll
    for (int ni = 0; ni < 6; ni++) bv[ni] = *(const float2*)&bias[nbase + ni * 8 + tg * 2];

#pragma unroll
    for (int mi = 0; mi < 2; mi++) {
#pragma unroll
        for (int half = 0; half < 2; half++) {
            const int r = m0 + wm * 32 + mi * 16 + g + half * 8;
            if (MODE == 0) {
                const int win = r >> 6, tok = r & 63;
#pragma unroll
                for (int ni = 0; ni < 6; ni++) {
                    const int c = nbase + ni * 8 + tg * 2;
                    const int mat = c / 192, hc = c - mat * 192;
                    const int head = hc >> 5, dim = hc & 31;
                    float v0 = acc[mi][ni][half * 2 + 0] + bv[ni].x;
                    float v1 = acc[mi][ni][half * 2 + 1] + bv[ni].y;
                    __nv_bfloat162 h2 = __floats2bfloat162_rn(v0, v1);
                    *(__nv_bfloat162*)&g_qkv_bf[(((size_t)win * HEADS + head) * 3 + mat) * 2048
                                                + tok * 32 + dim] = h2;
                }
            } else if (MODE == 2) {
#pragma unroll
                for (int ni = 0; ni < 6; ni++) {
                    float v0 = acc[mi][ni][half * 2 + 0] + bv[ni].x;
                    float v1 = acc[mi][ni][half * 2 + 1] + bv[ni].y;
                    v0 = 0.5f * v0 * (1.f + erff(v0 * 0.7071067811865475f));
                    v1 = 0.5f * v1 * (1.f + erff(v1 * 0.7071067811865475f));
                    __nv_bfloat162 h2 = __floats2bfloat162_rn(v0, v1);
                    *(__nv_bfloat162*)&g_hid_bf[(size_t)r * Nout + nbase + ni * 8 + tg * 2] = h2;
                }
            } else {
                const int bb2 = r >> 14, yy = (r >> 7) & 127, xx = r & 127;
                const size_t off = (size_t)r * CH;
                const size_t obase = (((size_t)bb2 * CH) * HH + yy) * WW + xx;
#pragma unroll
                for (int ni = 0; ni < 6; ni++) {
                    const size_t o = off + nbase + ni * 8 + tg * 2;
                    float2 a2 = *(const float2*)&g_xb2[o];
                    float v0 = acc[mi][ni][half * 2 + 0] + bv[ni].x + a2.x;
                    float v1 = acc[mi][ni][half * 2 + 1] + bv[ni].y + a2.y;
                    v0 = fminf(10.f, fmaxf(-10.f, v0));
                    v1 = fminf(10.f, fmaxf(-10.f, v1));
                    const int c = nbase + ni * 8 + tg * 2;
                    outp[obase + (size_t)c * (HH * WW)] = v0;
                    outp[obase + (size_t)(c + 1) * (HH * WW)] = v1;
                }
            }
        }
    }
}

// ---------------- fused proj + LN2: one window per CTA (M=64, N=192), 3-stage ----------------
#define PSTAGE 32768            // A 8KB + B 24KB
#define PSMEM  (3 * PSTAGE)     // 98304

__global__ void __launch_bounds__(256, 2)
proj_ln2(const float* __restrict__ bias,
         const float* __restrict__ ln2w, const float* __restrict__ ln2b) {
    constexpr int K = CH;
    extern __shared__ __align__(1024) uint8_t smx[];
    const uint32_t smb = s2u(smx);
    const int tid = threadIdx.x;
    const int wid = tid >> 5, lane = tid & 31;
    const int wm = wid & 1, wn = wid >> 1;     // 2m x 4n
    const int win = blockIdx.x;
    const int m0 = win * 64;

    const __nv_bfloat16* const Abase = g_attn_bf + (size_t)m0 * K;

    auto load_stage = [&](int st) {
        const uint32_t sA = smb + st * PSTAGE;
        const uint32_t sB = sA + 8192;
        const int kel = st * 64;
#pragma unroll
        for (int i = 0; i < 2; i++) {            // A: 64 rows x 128B
            int e = tid + i * 256;
            int row = e >> 3, c16 = e & 7;
            cp16(sA + sw128(row * 128 + c16 * 16), Abase + (size_t)row * K + kel + c16 * 8);
        }
#pragma unroll
        for (int i = 0; i < 6; i++) {            // B: 192 rows x 128B
            int e = tid + i * 256;
            int row = e >> 3, c16 = e & 7;
            cp16(sB + sw128(row * 128 + c16 * 16), g_wproj + (size_t)row * K + kel + c16 * 8);
        }
    };

    float acc[2][6][4] = {};
    const int arow0 = wm * 32 + (lane & 15);
    const int akoff = (lane >> 4) * 16;
    const int brow0 = wn * 48 + (lane & 7) + ((lane >> 4) << 3);
    const int bkoff = (lane & 8) ? 16 : 0;

    load_stage(0); cp_commit();
    load_stage(1); cp_commit();
    load_stage(2); cp_commit();

    for (int st = 0; st < 3; st++) {
        cp_wait2();
        __syncthreads();
        const uint32_t sA = smb + st * PSTAGE;
        const uint32_t sB = sA + 8192;
#pragma unroll
        for (int kk = 0; kk < 4; kk++) {
            uint32_t af[2][4], bf[3][4];
#pragma unroll
            for (int mi = 0; mi < 2; mi++)
                ldsm4(af[mi][0], af[mi][1], af[mi][2], af[mi][3],
                      sA + sw128((arow0 + mi * 16) * 128 + kk * 32 + akoff));
#pragma unroll
            for (int bi = 0; bi < 3; bi++)
                ldsm4(bf[bi][0], bf[bi][1], bf[bi][2], bf[bi][3],
                      sB + sw128((brow0 + bi * 16) * 128 + kk * 32 + bkoff));
#pragma unroll
            for (int mi = 0; mi < 2; mi++)
#pragma unroll
                for (int ni = 0; ni < 6; ni++)
                    mma16816(acc[mi][ni], af[mi], &bf[ni >> 1][(ni & 1) * 2]);
        }
        __syncthreads();
        cp_commit();
    }
    __syncthreads();   // stage smem now reusable

    float* sx = (float*)smx;                     // [64][196] xb2 scratch
    float2* spart = (float2*)(smx + 50176);      // [64][4] (sum, sumsq)

    const int g = lane >> 2, tg = lane & 3;
    const int nbase = wn * 48;
    float2 bv[6], lw[6], lb[6];
#pragma unroll
    for (int ni = 0; ni < 6; ni++) {
        bv[ni] = *(const float2*)&bias[nbase + ni * 8 + tg * 2];
        lw[ni] = *(const float2*)&ln2w[nbase + ni * 8 + tg * 2];
        lb[ni] = *(const float2*)&ln2b[nbase + ni * 8 + tg * 2];
    }

    const int bb2 = win >> 8, wy = (win >> 4) & 15, wx = win & 15;

#pragma unroll
    for (int mi = 0; mi < 2; mi++) {
#pragma unroll
        for (int half = 0; half < 2; half++) {
            const int rl = wm * 32 + mi * 16 + g + half * 8;
            const int yy = ((wy << 3) + (rl >> 3) + SHIFT) & 127;
            const int xx = ((wx << 3) + (rl & 7) + SHIFT) & 127;
            const size_t dr = ((size_t)((bb2 * HH + yy) * WW + xx)) * CH;
            float s = 0.f, sq = 0.f;
#pragma unroll
            for (int ni = 0; ni < 6; ni++) {
                const int c = nbase + ni * 8 + tg * 2;
                float2 xbv = *(const float2*)&g_xb[dr + c];
                float x2a = acc[mi][ni][half * 2 + 0] + bv[ni].x + xbv.x;
                float x2b = acc[mi][ni][half * 2 + 1] + bv[ni].y + xbv.y;
                float2 ov;
                ov.x = x2a + xbv.x; ov.y = x2b + xbv.y;
                *(float2*)&g_xb2[dr + c] = ov;
                sx[rl * 196 + c] = x2a;
                sx[rl * 196 + c + 1] = x2b;
                s += x2a + x2b;
                sq += x2a * x2a + x2b * x2b;
            }
            s  += __shfl_xor_sync(0xffffffffu, s, 1);
            s  += __shfl_xor_sync(0xffffffffu, s, 2);
            sq += __shfl_xor_sync(0xffffffffu, sq, 1);
            sq += __shfl_xor_sync(0xffffffffu, sq, 2);
            if (tg == 0) { spart[rl * 4 + wn] = make_float2(s, sq); }
        }
    }
    __syncthreads();

#pragma unroll
    for (int mi = 0; mi < 2; mi++) {
#pragma unroll
        for (int half = 0; half < 2; half++) {
            const int rl = wm * 32 + mi * 16 + g + half * 8;
            float s = 0.f, sq = 0.f;
#pragma unroll
            for (int p = 0; p < 4; p++) {
                float2 pp = spart[rl * 4 + p];
                s += pp.x; sq += pp.y;
            }
            float mean = s * (1.f / CH);
            float var = sq * (1.f / CH) - mean * mean;
            float rstd = rsqrtf(var + 1e-5f);
            const int yy = ((wy << 3) + (rl >> 3) + SHIFT) & 127;
            const int xx = ((wx << 3) + (rl & 7) + SHIFT) & 127;
            const size_t dr = ((size_t)((bb2 * HH + yy) * WW + xx)) * CH;
#pragma unroll
            for (int ni = 0; ni < 6; ni++) {
                const int c = nbase + ni * 8 + tg * 2;
                float x2a = sx[rl * 196 + c];
                float x2b = sx[rl * 196 + c + 1];
                float h0 = (x2a - mean) * rstd * lw[ni].x + lb[ni].x;
                float h1 = (x2b - mean) * rstd * lw[ni].y + lb[ni].y;
                *(uint32_t*)&g_h2_bf[dr + c] = packbf(h0, h1);
            }
        }
    }
}

// ---------------- tensor-core windowed attention ----------------
#define ATT_SLICE 5120
#define ATT_QKV   (18 * ATT_SLICE)
#define ATT_SMEM  (ATT_QKV + 5408)
__global__ void __launch_bounds__(384)
attn_kernel(const float* __restrict__ rpb) {
    extern __shared__ __align__(128) uint8_t smem_a[];
    float* srpb = (float*)(smem_a + ATT_QKV);
    const int win = blockIdx.x;
    const int tid = threadIdx.x;
    const int wid = tid >> 5, lane = tid & 31;
    const int head = wid >> 1, wrow = wid & 1;
    const int g = lane >> 2, tg = lane & 3;

    for (int f = tid; f < 225 * HEADS; f += 384) srpb[f] = rpb[f];

    {
        const __nv_bfloat16* gb = g_qkv_bf + (size_t)win * 18 * 2048;
#pragma unroll
        for (int i = 0; i < 12; i++) {
            int idx = tid + i * 384;
            int slice = idx >> 8;
            int cidx = idx & 255;
            int row = cidx >> 2, ch = cidx & 3;
            uint4 v = *(const uint4*)(gb + slice * 2048 + cidx * 8);
            *(uint4*)(smem_a + slice * ATT_SLICE + row * 80 + ch * 16) = v;
        }
    }
    __syncthreads();

    const uint32_t sq = s2u(smem_a) + (head * 3 + 0) * ATT_SLICE;
    const uint32_t sk = sq + ATT_SLICE;
    const uint32_t sv = sq + 2 * ATT_SLICE;

    float s[2][8][4] = {};
#pragma unroll
    for (int kt = 0; kt < 2; kt++) {
        uint32_t af[2][4];
#pragma unroll
        for (int mi = 0; mi < 2; mi++)
            ldsm4(af[mi][0], af[mi][1], af[mi][2], af[mi][3],
                  sq + (wrow * 32 + mi * 16 + (lane & 15)) * 80 + kt * 32 + (lane >> 4) * 16);
#pragma unroll
        for (int nj2 = 0; nj2 < 4; nj2++) {
            uint32_t bf[4];
            ldsm4(bf[0], bf[1], bf[2], bf[3],
                  sk + (nj2 * 16 + (lane & 7) + ((lane >> 4) << 3)) * 80
                     + kt * 32 + ((lane & 8) ? 16 : 0));
#pragma unroll
            for (int mi = 0; mi < 2; mi++) {
                mma16816(s[mi][nj2 * 2 + 0], af[mi], &bf[0]);
                mma16816(s[mi][nj2 * 2 + 1], af[mi], &bf[2]);
            }
        }
    }

    const int wy = (win >> 4) & 15, wx = win & 15;
    const bool my = (wy == 15), mx = (wx == 15);
#pragma unroll
    for (int mi = 0; mi < 2; mi++)
#pragma unroll
        for (int nj = 0; nj < 8; nj++)
#pragma unroll
            for (int e = 0; e < 4; e++) {
                const int i = wrow * 32 + mi * 16 + g + ((e >= 2) ? 8 : 0);
                const int j = nj * 8 + tg * 2 + (e & 1);
                const int iy = i >> 3, ix = i & 7, jy = j >> 3, jx = j & 7;
                float v = s[mi][nj][e] * 0.17677669529663687f
                        + srpb[((iy - jy + 7) * 15 + (ix - jx + 7)) * HEADS + head];
                const int ri = (my ? (iy < 4 ? 1 : 2) : 0) * 3 + (mx ? (ix < 4 ? 1 : 2) : 0);
                const int rj = (my ? (jy < 4 ? 1 : 2) : 0) * 3 + (mx ? (jx < 4 ? 1 : 2) : 0);
                if (ri != rj) v -= 100.f;
                s[mi][nj][e] = v;
            }
#pragma unroll
    for (int mi = 0; mi < 2; mi++)
#pragma unroll
        for (int h = 0; h < 2; h++) {
            float m = -1e30f;
#pragma unroll
            for (int nj = 0; nj < 8; nj++) {
                m = fmaxf(m, s[mi][nj][h * 2 + 0]);
                m = fmaxf(m, s[mi][nj][h * 2 + 1]);
            }
            m = fmaxf(m, __shfl_xor_sync(0xffffffffu, m, 1));
            m = fmaxf(m, __shfl_xor_sync(0xffffffffu, m, 2));
            float sum = 0.f;
#pragma unroll
            for (int nj = 0; nj < 8; nj++) {
                float e0 = __expf(s[mi][nj][h * 2 + 0] - m);
                float e1 = __expf(s[mi][nj][h * 2 + 1] - m);
                s[mi][nj][h * 2 + 0] = e0;
                s[mi][nj][h * 2 + 1] = e1;
                sum += e0 + e1;
            }
            sum += __shfl_xor_sync(0xffffffffu, sum, 1);
            sum += __shfl_xor_sync(0xffffffffu, sum, 2);
            const float inv = 1.f / sum;
#pragma unroll
            for (int nj = 0; nj < 8; nj++) {
                s[mi][nj][h * 2 + 0] *= inv;
                s[mi][nj][h * 2 + 1] *= inv;
            }
        }

    float o[2][4][4] = {};
#pragma unroll
    for (int kt = 0; kt < 4; kt++) {
        const int jr = kt * 16 + (lane & 7) + ((lane & 8) ? 8 : 0);
        const uint32_t vb = sv + jr * 80 + (lane >> 4) * 16;
        uint32_t b0[4], b1[4];
        ldsm4t(b0[0], b0[1], b0[2], b0[3], vb);
        ldsm4t(b1[0], b1[1], b1[2], b1[3], vb + 32);
#pragma unroll
        for (int mi = 0; mi < 2; mi++) {
            uint32_t a[4];
            a[0] = packbf(s[mi][2 * kt][0], s[mi][2 * kt][1]);
            a[1] = packbf(s[mi][2 * kt][2], s[mi][2 * kt][3]);
            a[2] = packbf(s[mi][2 * kt + 1][0], s[mi][2 * kt + 1][1]);
            a[3] = packbf(s[mi][2 * kt + 1][2], s[mi][2 * kt + 1][3]);
            mma16816(o[mi][0], a, &b0[0]);
            mma16816(o[mi][1], a, &b0[2]);
            mma16816(o[mi][2], a, &b1[0]);
            mma16816(o[mi][3], a, &b1[2]);
        }
    }

    __nv_bfloat16* ob = g_attn_bf + (size_t)(win * NTOK) * CH + head * HD;
#pragma unroll
    for (int mi = 0; mi < 2; mi++) {
        const int rlo = wrow * 32 + mi * 16 + g;
#pragma unroll
        for (int nf = 0; nf < 4; nf++) {
            const int d = nf * 8 + tg * 2;
            *(__nv_bfloat162*)&ob[(size_t)rlo * CH + d] =
                __floats2bfloat162_rn(o[mi][nf][0], o[mi][nf][1]);
            *(__nv_bfloat162*)&ob[(size_t)(rlo + 8) * CH + d] =
                __floats2bfloat162_rn(o[mi][nf][2], o[mi][nf][3]);
        }
    }
}

// ---------------- launch ----------------
extern "C" void kernel_launch(void* const* d_in, const int* in_sizes, int n_in,
                              void* d_out, int out_size) {
    (void)in_sizes; (void)n_in; (void)out_size;
    const float* x      = (const float*)d_in[0];
    const float* gn_w   = (const float*)d_in[1];
    const float* gn_b   = (const float*)d_in[2];
    const float* ln1_w  = (const float*)d_in[3];
    const float* ln1_b  = (const float*)d_in[4];
    const float* qkv_w  = (const float*)d_in[5];
    const float* qkv_b  = (const float*)d_in[6];
    const float* proj_w = (const float*)d_in[7];
    const float* proj_b = (const float*)d_in[8];
    const float* rpb    = (const float*)d_in[9];
    const float* ln2_w  = (const float*)d_in[10];
    const float* ln2_b  = (const float*)d_in[11];
    const float* fc1_w  = (const float*)d_in[12];
    const float* fc1_b  = (const float*)d_in[13];
    const float* fc2_w  = (const float*)d_in[14];
    const float* fc2_b  = (const float*)d_in[15];
    float* out = (float*)d_out;

    cudaFuncSetAttribute((const void*)attn_kernel,
                         cudaFuncAttributeMaxDynamicSharedMemorySize, ATT_SMEM);
    cudaFuncSetAttribute((const void*)mma_gemm<0>, cudaFuncAttributeMaxDynamicSharedMemorySize, GSMEM);
    cudaFuncSetAttribute((const void*)mma_gemm<2>, cudaFuncAttributeMaxDynamicSharedMemorySize, GSMEM);
    cudaFuncSetAttribute((const void*)mma_gemm<3>, cudaFuncAttributeMaxDynamicSharedMemorySize, GSMEM);
    cudaFuncSetAttribute((const void*)proj_ln2, cudaFuncAttributeMaxDynamicSharedMemorySize, PSMEM);

    // GN partial sums + weight transposes in one launch
    prep_kernel<<<1456, 256>>>(x, qkv_w, proj_w, fc1_w, fc2_w);
    gn_final_kernel<<<BATCH, 128>>>();
    build_kernel<<<BATCH * HH * (WW / 32), 256>>>(x, gn_w, gn_b, ln1_w, ln1_b);

    // QKV -> head-major g_qkv_bf
    mma_gemm<0><<<dim3(6, TOK / 128), 256, GSMEM>>>(qkv_b, nullptr);

    attn_kernel<<<NWIN, 384, ATT_SMEM>>>(rpb);

    // fused proj + residual pre-sum + LN2 -> g_xb2 (fp32), g_h2_bf (bf16)
    proj_ln2<<<NWIN, 256, PSMEM>>>(proj_b, ln2_w, ln2_b);

    // fc1 + GELU -> g_hid_bf
    mma_gemm<2><<<dim3(8, TOK / 128), 256, GSMEM>>>(fc1_b, nullptr);

    // fc2 + pre-summed residual + clamp -> out (NCHW)
    mma_gemm<3><<<dim3(2, TOK / 128), 256, GSMEM>>>(fc2_b, out);
}

// round 16
// speedup vs baseline: 1.1448x; 1.0150x over previous
#include <cuda_runtime.h>
#include <cuda_bf16.h>
#include <cstdint>
#include <math.h>

// Problem constants
#define BATCH 8
#define CH    192
#define HH    128
#define WW    128
#define HEADS 6
#define HD    32
#define WIN   8
#define NTOK  64
#define NWIN  2048
#define TOK   131072
#define HID   768
#define SHIFT 4

// ---------------- device scratch ----------------
__device__ __align__(256) float g_xb [TOK * CH];   // GN output NHWC fp32 (residual & shortcut)
__device__ __align__(256) float g_xb2[TOK * CH];   // xb2 + xb (pre-summed residual for fc2)
__device__ __align__(256) __nv_bfloat16 g_hw_bf [TOK * CH];
// qkv in head-major layout: [win][head][mat(q,k,v)][64 tok][32 dim]
__device__ __align__(256) __nv_bfloat16 g_qkv_bf[(size_t)TOK * 3 * CH];
__device__ __align__(256) __nv_bfloat16 g_attn_bf[TOK * CH];
__device__ __align__(256) __nv_bfloat16 g_h2_bf [TOK * CH];   // LN2 output (spatial order)
__device__ __align__(256) __nv_bfloat16 g_hid_bf[(size_t)TOK * HID];
__device__ __align__(256) __nv_bfloat16 g_wqkv[3 * CH * CH];   // [576,192] (N,K)
__device__ __align__(256) __nv_bfloat16 g_wproj[CH * CH];      // [192,192]
__device__ __align__(256) __nv_bfloat16 g_wfc1[HID * CH];      // [768,192]
__device__ __align__(256) __nv_bfloat16 g_wfc2[CH * HID];      // [192,768]
__device__ float g_part[BATCH * 128 * 2];
__device__ float g_stats[BATCH * 2];

// ---------------- helpers ----------------
__device__ __forceinline__ uint32_t s2u(const void* p) {
    uint32_t a;
    asm("{ .reg .u64 t; cvta.to.shared.u64 t, %1; cvt.u32.u64 %0, t; }" : "=r"(a) : "l"(p));
    return a;
}
__device__ __forceinline__ uint32_t sw128(uint32_t o) { return o ^ ((o >> 3) & 0x70); }

__device__ __forceinline__ void cp16(uint32_t saddr, const void* gptr) {
    asm volatile("cp.async.cg.shared.global [%0], [%1], 16;" :: "r"(saddr), "l"(gptr) : "memory");
}
__device__ __forceinline__ void cp_commit() {
    asm volatile("cp.async.commit_group;" ::: "memory");
}
__device__ __forceinline__ void cp_wait0() {
    asm volatile("cp.async.wait_group 0;" ::: "memory");
}
__device__ __forceinline__ void cp_wait2() {
    asm volatile("cp.async.wait_group 2;" ::: "memory");
}
__device__ __forceinline__ void ldsm4(uint32_t& r0, uint32_t& r1, uint32_t& r2, uint32_t& r3,
                                      uint32_t a) {
    asm volatile("ldmatrix.sync.aligned.m8n8.x4.shared.b16 {%0,%1,%2,%3}, [%4];"
                 : "=r"(r0), "=r"(r1), "=r"(r2), "=r"(r3) : "r"(a));
}
__device__ __forceinline__ void ldsm4t(uint32_t& r0, uint32_t& r1, uint32_t& r2, uint32_t& r3,
                                       uint32_t a) {
    asm volatile("ldmatrix.sync.aligned.m8n8.x4.trans.shared.b16 {%0,%1,%2,%3}, [%4];"
                 : "=r"(r0), "=r"(r1), "=r"(r2), "=r"(r3) : "r"(a));
}
__device__ __forceinline__ void mma16816(float* c, const uint32_t* a, const uint32_t* b) {
    asm volatile(
        "mma.sync.aligned.m16n8k16.row.col.f32.bf16.bf16.f32 "
        "{%0,%1,%2,%3}, {%4,%5,%6,%7}, {%8,%9}, {%0,%1,%2,%3};"
        : "+f"(c[0]), "+f"(c[1]), "+f"(c[2]), "+f"(c[3])
        : "r"(a[0]), "r"(a[1]), "r"(a[2]), "r"(a[3]), "r"(b[0]), "r"(b[1]));
}
__device__ __forceinline__ uint32_t packbf(float a, float b) {
    __nv_bfloat162 h = __floats2bfloat162_rn(a, b);
    return *(uint32_t*)&h;
}

// ---------------- prep: GN partial sums (blocks 0..1023) + weight transposes (1024..1455) ----------------
__global__ void prep_kernel(const float* __restrict__ x,
                            const float* __restrict__ qkv_w, const float* __restrict__ proj_w,
                            const float* __restrict__ fc1_w, const float* __restrict__ fc2_w) {
    const int tid = threadIdx.x;
    if (blockIdx.x < 1024) {
        const int b = blockIdx.x >> 7;
        const int chunk = blockIdx.x & 127;
        const size_t per_sample = (size_t)CH * HH * WW;
        const float* p = x + (size_t)b * per_sample + (size_t)chunk * 24576;
        float s = 0.f, sq = 0.f;
        for (int i = tid; i < 24576; i += 256) { float v = p[i]; s += v; sq += v * v; }
        __shared__ float rs[256], rq[256];
        rs[tid] = s; rq[tid] = sq;
        __syncthreads();
        for (int o = 128; o; o >>= 1) {
            if (tid < o) { rs[tid] += rs[tid + o]; rq[tid] += rq[tid + o]; }
            __syncthreads();
        }
        if (tid == 0) {
            g_part[blockIdx.x * 2 + 0] = rs[0];
            g_part[blockIdx.x * 2 + 1] = rq[0];
        }
    } else {
        const int b = blockIdx.x - 1024;
        const float* W;
        __nv_bfloat16* Wt;
        int K, N, bx, by;
        if (b < 108)      { W = qkv_w;  Wt = g_wqkv;  K = CH;  N = 3 * CH; bx = b % 18;  by = b / 18; }
        else if (b < 144) { int t = b - 108; W = proj_w; Wt = g_wproj; K = CH;  N = CH;  bx = t % 6;  by = t / 6; }
        else if (b < 288) { int t = b - 144; W = fc1_w;  Wt = g_wfc1;  K = CH;  N = HID; bx = t % 24; by = t / 24; }
        else              { int t = b - 288; W = fc2_w;  Wt = g_wfc2;  K = HID; N = CH;  bx = t % 6;  by = t / 6; }
        __shared__ float t[32][33];
        const int k0 = by * 32, n0 = bx * 32;
        const int lx = tid & 31, ly = tid >> 5;
        for (int r = ly; r < 32; r += 8) t[r][lx] = W[(size_t)(k0 + r) * N + n0 + lx];
        __syncthreads();
        for (int r = ly; r < 32; r += 8)
            Wt[(size_t)(n0 + r) * K + k0 + lx] = __float2bfloat16(t[lx][r]);
    }
}

__global__ void gn_final_kernel() {
    const int b = blockIdx.x;
    const int tid = threadIdx.x;
    __shared__ double ds[128], dq[128];
    ds[tid] = (double)g_part[(b * 128 + tid) * 2 + 0];
    dq[tid] = (double)g_part[(b * 128 + tid) * 2 + 1];
    __syncthreads();
    for (int o = 64; o; o >>= 1) {
        if (tid < o) { ds[tid] += ds[tid + o]; dq[tid] += dq[tid + o]; }
        __syncthreads();
    }
    if (tid == 0) {
        const double n = 3145728.0;
        double mean = ds[0] / n;
        double var = dq[0] / n - mean * mean;
        g_stats[b * 2 + 0] = (float)mean;
        g_stats[b * 2 + 1] = (float)(1.0 / sqrt(var + 1e-5));
    }
}

// ---------------- GN apply + xb store + LN1 + shift + window partition ----------------
__global__ void build_kernel(const float* __restrict__ x,
                             const float* __restrict__ gnw, const float* __restrict__ gnb,
                             const float* __restrict__ ln1w, const float* __restrict__ ln1b) {
    __shared__ float t[CH][33];
    const int bid = blockIdx.x;
    const int xt = bid & 3;
    const int y  = (bid >> 2) & 127;
    const int b  = bid >> 9;
    const int tid = threadIdx.x;
    const float mu = g_stats[b * 2 + 0];
    const float rstd = g_stats[b * 2 + 1];
    const int lx = tid & 31;
    const int c0 = tid >> 5;

    for (int c = c0; c < CH; c += 8) {
        float v = x[((((size_t)b * CH + c) * HH + y) * WW) + xt * 32 + lx];
        t[c][lx] = (v - mu) * rstd * gnw[c] + gnb[c];
    }
    __syncthreads();

    const size_t tokbase = ((size_t)(b * HH + y) * WW) + xt * 32;
    for (int j = 0; j < 32; j++) {
        if (tid < CH) g_xb[(tokbase + j) * CH + tid] = t[tid][j];
    }

    const int warp = tid >> 5, lane = tid & 31;
    for (int j = warp; j < 32; j += 8) {
        float s = 0.f, sq = 0.f;
#pragma unroll
        for (int k = 0; k < 6; k++) {
            float v = t[lane + k * 32][j];
            s += v; sq += v * v;
        }
#pragma unroll
        for (int o = 16; o; o >>= 1) {
            s  += __shfl_xor_sync(0xffffffffu, s, o);
            sq += __shfl_xor_sync(0xffffffffu, sq, o);
        }
        float mean = s * (1.f / CH);
        float var = sq * (1.f / CH) - mean * mean;
        float r = rsqrtf(var + 1e-5f);
        const int xx = xt * 32 + j;
        const int ys = (y - SHIFT) & 127;
        const int xs = (xx - SHIFT) & 127;
        const size_t dst = ((size_t)(((b * 16 + (ys >> 3)) * 16 + (xs >> 3)) * NTOK)
                            + (ys & 7) * 8 + (xs & 7)) * CH;
#pragma unroll
        for (int k = 0; k < 6; k++) {
            int c = lane + k * 32;
            g_hw_bf[dst + c] = __float2bfloat16((t[c][j] - mean) * r * ln1w[c] + ln1b[c]);
        }
    }
}

// ---------------- mma.sync bf16 GEMM, CTA tile 128x96, 3-stage ----------------
// K=192 (qkv, fc1): full prefetch, BARRIER-FREE mainloop.
// K=768 (fc2): rolling 3-stage.
// MODE 0: qkv  -> g_qkv_bf HEAD-MAJOR layout
// MODE 2: fc1  -> GELU -> g_hid_bf
// MODE 3: fc2  -> out NCHW = clamp(. + g_xb2)
#define GSTAGE 28672
#define GSMEM  (3 * GSTAGE)   // 86016

template <int MODE>
__global__ void __launch_bounds__(256)
mma_gemm(const float* __restrict__ bias, float* __restrict__ outp) {
    constexpr int K    = (MODE == 3) ? HID : CH;
    constexpr int NST  = K / 64;
    const __nv_bfloat16* const A  = (MODE == 0) ? g_hw_bf : (MODE == 2) ? g_h2_bf : g_hid_bf;
    const __nv_bfloat16* const Bt = (MODE == 0) ? g_wqkv : (MODE == 2) ? g_wfc1 : g_wfc2;
    constexpr int Nout = (MODE == 0) ? 3 * CH : (MODE == 2) ? HID : CH;

    extern __shared__ __align__(1024) uint8_t smx[];
    const uint32_t smb = s2u(smx);
    const int tid = threadIdx.x;
    const int wid = tid >> 5, lane = tid & 31;
    const int wm = wid & 3, wn = wid >> 2;    // 4m x 2n
    const int m0 = blockIdx.y * 128;
    const int n0c = blockIdx.x * 96;

    const __nv_bfloat16* const Abase = A  + (size_t)m0 * K;
    const __nv_bfloat16* const Bbase = Bt + (size_t)n0c * K;

    auto load_stage = [&](int st) {
        const uint32_t sA = smb + (st % 3) * GSTAGE;
        const uint32_t sB = sA + 16384;
        const int kel = st * 64;
#pragma unroll
        for (int i = 0; i < 4; i++) {            // A: 128 rows x 128B
            int e = tid + i * 256;
            int row = e >> 3, c16 = e & 7;
            cp16(sA + sw128(row * 128 + c16 * 16), Abase + (size_t)row * K + kel + c16 * 8);
        }
#pragma unroll
        for (int i = 0; i < 3; i++) {            // B: 96 rows x 128B
            int e = tid + i * 256;
            int row = e >> 3, c16 = e & 7;
            cp16(sB + sw128(row * 128 + c16 * 16), Bbase + (size_t)row * K + kel + c16 * 8);
        }
    };

    float acc[2][6][4] = {};

    const int arow0 = wm * 32 + (lane & 15);
    const int akoff = (lane >> 4) * 16;
    const int brow0 = wn * 48 + (lane & 7) + ((lane >> 4) << 3);
    const int bkoff = (lane & 8) ? 16 : 0;

    load_stage(0); cp_commit();
    load_stage(1); cp_commit();
    load_stage(2); cp_commit();

    if (NST == 3) {
        // all K resident: single wait+barrier, then a straight-line mainloop
        cp_wait0();
        __syncthreads();
#pragma unroll
        for (int st = 0; st < 3; st++) {
            const uint32_t sA = smb + st * GSTAGE;
            const uint32_t sB = sA + 16384;
#pragma unroll
            for (int kk = 0; kk < 4; kk++) {
                uint32_t af[2][4], bf[3][4];
#pragma unroll
                for (int mi = 0; mi < 2; mi++)
                    ldsm4(af[mi][0], af[mi][1], af[mi][2], af[mi][3],
                          sA + sw128((arow0 + mi * 16) * 128 + kk * 32 + akoff));
#pragma unroll
                for (int bi = 0; bi < 3; bi++)
                    ldsm4(bf[bi][0], bf[bi][1], bf[bi][2], bf[bi][3],
                          sB + sw128((brow0 + bi * 16) * 128 + kk * 32 + bkoff));
#pragma unroll
                for (int mi = 0; mi < 2; mi++)
#pragma unroll
                    for (int ni = 0; ni < 6; ni++)
                        mma16816(acc[mi][ni], af[mi], &bf[ni >> 1][(ni & 1) * 2]);
            }
        }
    } else {
        for (int st = 0; st < NST; st++) {
            cp_wait2();
            __syncthreads();
            const uint32_t sA = smb + (st % 3) * GSTAGE;
            const uint32_t sB = sA + 16384;
#pragma unroll
            for (int kk = 0; kk < 4; kk++) {
                uint32_t af[2][4], bf[3][4];
#pragma unroll
                for (int mi = 0; mi < 2; mi++)
                    ldsm4(af[mi][0], af[mi][1], af[mi][2], af[mi][3],
                          sA + sw128((arow0 + mi * 16) * 128 + kk * 32 + akoff));
#pragma unroll
                for (int bi = 0; bi < 3; bi++)
                    ldsm4(bf[bi][0], bf[bi][1], bf[bi][2], bf[bi][3],
                          sB + sw128((brow0 + bi * 16) * 128 + kk * 32 + bkoff));
#pragma unroll
                for (int mi = 0; mi < 2; mi++)
#pragma unroll
                    for (int ni = 0; ni < 6; ni++)
                        mma16816(acc[mi][ni], af[mi], &bf[ni >> 1][(ni & 1) * 2]);
            }
            __syncthreads();
            if (st + 3 < NST) load_stage(st + 3);
            cp_commit();
        }
    }

    // ---- epilogue ----
    const int g = lane >> 2, tg = lane & 3;
    const int nbase = n0c + wn * 48;
    float2 bv[6];
#pragma unroll
    for (int ni = 0; ni < 6; ni++) bv[ni] = *(const float2*)&bias[nbase + ni * 8 + tg * 2];

#pragma unroll
    for (int mi = 0; mi < 2; mi++) {
#pragma unroll
        for (int half = 0; half < 2; half++) {
            const int r = m0 + wm * 32 + mi * 16 + g + half * 8;
            if (MODE == 0) {
                const int win = r >> 6, tok = r & 63;
#pragma unroll
                for (int ni = 0; ni < 6; ni++) {
                    const int c = nbase + ni * 8 + tg * 2;
                    const int mat = c / 192, hc = c - mat * 192;
                    const int head = hc >> 5, dim = hc & 31;
                    float v0 = acc[mi][ni][half * 2 + 0] + bv[ni].x;
                    float v1 = acc[mi][ni][half * 2 + 1] + bv[ni].y;
                    __nv_bfloat162 h2 = __floats2bfloat162_rn(v0, v1);
                    *(__nv_bfloat162*)&g_qkv_bf[(((size_t)win * HEADS + head) * 3 + mat) * 2048
                                                + tok * 32 + dim] = h2;
                }
            } else if (MODE == 2) {
#pragma unroll
                for (int ni = 0; ni < 6; ni++) {
                    float v0 = acc[mi][ni][half * 2 + 0] + bv[ni].x;
                    float v1 = acc[mi][ni][half * 2 + 1] + bv[ni].y;
                    v0 = 0.5f * v0 * (1.f + erff(v0 * 0.7071067811865475f));
                    v1 = 0.5f * v1 * (1.f + erff(v1 * 0.7071067811865475f));
                    __nv_bfloat162 h2 = __floats2bfloat162_rn(v0, v1);
                    *(__nv_bfloat162*)&g_hid_bf[(size_t)r * Nout + nbase + ni * 8 + tg * 2] = h2;
                }
            } else {
                const int bb2 = r >> 14, yy = (r >> 7) & 127, xx = r & 127;
                const size_t off = (size_t)r * CH;
                const size_t obase = (((size_t)bb2 * CH) * HH + yy) * WW + xx;
#pragma unroll
                for (int ni = 0; ni < 6; ni++) {
                    const size_t o = off + nbase + ni * 8 + tg * 2;
                    float2 a2 = *(const float2*)&g_xb2[o];
                    float v0 = acc[mi][ni][half * 2 + 0] + bv[ni].x + a2.x;
                    float v1 = acc[mi][ni][half * 2 + 1] + bv[ni].y + a2.y;
                    v0 = fminf(10.f, fmaxf(-10.f, v0));
                    v1 = fminf(10.f, fmaxf(-10.f, v1));
                    const int c = nbase + ni * 8 + tg * 2;
                    outp[obase + (size_t)c * (HH * WW)] = v0;
                    outp[obase + (size_t)(c + 1) * (HH * WW)] = v1;
                }
            }
        }
    }
}

// ---------------- fused proj + LN2: one window per CTA (M=64, N=192), full prefetch ----------------
#define PSTAGE 32768            // A 8KB + B 24KB
#define PSMEM  (3 * PSTAGE)     // 98304

__global__ void __launch_bounds__(256, 2)
proj_ln2(const float* __restrict__ bias,
         const float* __restrict__ ln2w, const float* __restrict__ ln2b) {
    constexpr int K = CH;
    extern __shared__ __align__(1024) uint8_t smx[];
    const uint32_t smb = s2u(smx);
    const int tid = threadIdx.x;
    const int wid = tid >> 5, lane = tid & 31;
    const int wm = wid & 1, wn = wid >> 1;     // 2m x 4n
    const int win = blockIdx.x;
    const int m0 = win * 64;

    const __nv_bfloat16* const Abase = g_attn_bf + (size_t)m0 * K;

    auto load_stage = [&](int st) {
        const uint32_t sA = smb + st * PSTAGE;
        const uint32_t sB = sA + 8192;
        const int kel = st * 64;
#pragma unroll
        for (int i = 0; i < 2; i++) {            // A: 64 rows x 128B
            int e = tid + i * 256;
            int row = e >> 3, c16 = e & 7;
            cp16(sA + sw128(row * 128 + c16 * 16), Abase + (size_t)row * K + kel + c16 * 8);
        }
#pragma unroll
        for (int i = 0; i < 6; i++) {            // B: 192 rows x 128B
            int e = tid + i * 256;
            int row = e >> 3, c16 = e & 7;
            cp16(sB + sw128(row * 128 + c16 * 16), g_wproj + (size_t)row * K + kel + c16 * 8);
        }
    };

    float acc[2][6][4] = {};
    const int arow0 = wm * 32 + (lane & 15);
    const int akoff = (lane >> 4) * 16;
    const int brow0 = wn * 48 + (lane & 7) + ((lane >> 4) << 3);
    const int bkoff = (lane & 8) ? 16 : 0;

    load_stage(0); cp_commit();
    load_stage(1); cp_commit();
    load_stage(2); cp_commit();
    cp_wait0();
    __syncthreads();

#pragma unroll
    for (int st = 0; st < 3; st++) {
        const uint32_t sA = smb + st * PSTAGE;
        const uint32_t sB = sA + 8192;
#pragma unroll
        for (int kk = 0; kk < 4; kk++) {
            uint32_t af[2][4], bf[3][4];
#pragma unroll
            for (int mi = 0; mi < 2; mi++)
                ldsm4(af[mi][0], af[mi][1], af[mi][2], af[mi][3],
                      sA + sw128((arow0 + mi * 16) * 128 + kk * 32 + akoff));
#pragma unroll
            for (int bi = 0; bi < 3; bi++)
                ldsm4(bf[bi][0], bf[bi][1], bf[bi][2], bf[bi][3],
                      sB + sw128((brow0 + bi * 16) * 128 + kk * 32 + bkoff));
#pragma unroll
            for (int mi = 0; mi < 2; mi++)
#pragma unroll
                for (int ni = 0; ni < 6; ni++)
                    mma16816(acc[mi][ni], af[mi], &bf[ni >> 1][(ni & 1) * 2]);
        }
    }
    __syncthreads();   // stage smem now reusable

    float* sx = (float*)smx;                     // [64][196] xb2 scratch
    float2* spart = (float2*)(smx + 50176);      // [64][4] (sum, sumsq)

    const int g = lane >> 2, tg = lane & 3;
    const int nbase = wn * 48;
    float2 bv[6], lw[6], lb[6];
#pragma unroll
    for (int ni = 0; ni < 6; ni++) {
        bv[ni] = *(const float2*)&bias[nbase + ni * 8 + tg * 2];
        lw[ni] = *(const float2*)&ln2w[nbase + ni * 8 + tg * 2];
        lb[ni] = *(const float2*)&ln2b[nbase + ni * 8 + tg * 2];
    }

    const int bb2 = win >> 8, wy = (win >> 4) & 15, wx = win & 15;

#pragma unroll
    for (int mi = 0; mi < 2; mi++) {
#pragma unroll
        for (int half = 0; half < 2; half++) {
            const int rl = wm * 32 + mi * 16 + g + half * 8;
            const int yy = ((wy << 3) + (rl >> 3) + SHIFT) & 127;
            const int xx = ((wx << 3) + (rl & 7) + SHIFT) & 127;
            const size_t dr = ((size_t)((bb2 * HH + yy) * WW + xx)) * CH;
            float s = 0.f, sq = 0.f;
#pragma unroll
            for (int ni = 0; ni < 6; ni++) {
                const int c = nbase + ni * 8 + tg * 2;
                float2 xbv = *(const float2*)&g_xb[dr + c];
                float x2a = acc[mi][ni][half * 2 + 0] + bv[ni].x + xbv.x;
                float x2b = acc[mi][ni][half * 2 + 1] + bv[ni].y + xbv.y;
                float2 ov;
                ov.x = x2a + xbv.x; ov.y = x2b + xbv.y;
                *(float2*)&g_xb2[dr + c] = ov;
                sx[rl * 196 + c] = x2a;
                sx[rl * 196 + c + 1] = x2b;
                s += x2a + x2b;
                sq += x2a * x2a + x2b * x2b;
            }
            s  += __shfl_xor_sync(0xffffffffu, s, 1);
            s  += __shfl_xor_sync(0xffffffffu, s, 2);
            sq += __shfl_xor_sync(0xffffffffu, sq, 1);
            sq += __shfl_xor_sync(0xffffffffu, sq, 2);
            if (tg == 0) { spart[rl * 4 + wn] = make_float2(s, sq); }
        }
    }
    __syncthreads();

#pragma unroll
    for (int mi = 0; mi < 2; mi++) {
#pragma unroll
        for (int half = 0; half < 2; half++) {
            const int rl = wm * 32 + mi * 16 + g + half * 8;
            float s = 0.f, sq = 0.f;
#pragma unroll
            for (int p = 0; p < 4; p++) {
                float2 pp = spart[rl * 4 + p];
                s += pp.x; sq += pp.y;
            }
            float mean = s * (1.f / CH);
            float var = sq * (1.f / CH) - mean * mean;
            float rstd = rsqrtf(var + 1e-5f);
            const int yy = ((wy << 3) + (rl >> 3) + SHIFT) & 127;
            const int xx = ((wx << 3) + (rl & 7) + SHIFT) & 127;
            const size_t dr = ((size_t)((bb2 * HH + yy) * WW + xx)) * CH;
#pragma unroll
            for (int ni = 0; ni < 6; ni++) {
                const int c = nbase + ni * 8 + tg * 2;
                float x2a = sx[rl * 196 + c];
                float x2b = sx[rl * 196 + c + 1];
                float h0 = (x2a - mean) * rstd * lw[ni].x + lb[ni].x;
                float h1 = (x2b - mean) * rstd * lw[ni].y + lb[ni].y;
                *(uint32_t*)&g_h2_bf[dr + c] = packbf(h0, h1);
            }
        }
    }
}

// ---------------- tensor-core windowed attention ----------------
#define ATT_SLICE 5120
#define ATT_QKV   (18 * ATT_SLICE)
#define ATT_SMEM  (ATT_QKV + 5408)
__global__ void __launch_bounds__(384)
attn_kernel(const float* __restrict__ rpb) {
    extern __shared__ __align__(128) uint8_t smem_a[];
    float* srpb = (float*)(smem_a + ATT_QKV);
    const int win = blockIdx.x;
    const int tid = threadIdx.x;
    const int wid = tid >> 5, lane = tid & 31;
    const int head = wid >> 1, wrow = wid & 1;
    const int g = lane >> 2, tg = lane & 3;

    for (int f = tid; f < 225 * HEADS; f += 384) srpb[f] = rpb[f];

    {
        const __nv_bfloat16* gb = g_qkv_bf + (size_t)win * 18 * 2048;
#pragma unroll
        for (int i = 0; i < 12; i++) {
            int idx = tid + i * 384;
            int slice = idx >> 8;
            int cidx = idx & 255;
            int row = cidx >> 2, ch = cidx & 3;
            uint4 v = *(const uint4*)(gb + slice * 2048 + cidx * 8);
            *(uint4*)(smem_a + slice * ATT_SLICE + row * 80 + ch * 16) = v;
        }
    }
    __syncthreads();

    const uint32_t sq = s2u(smem_a) + (head * 3 + 0) * ATT_SLICE;
    const uint32_t sk = sq + ATT_SLICE;
    const uint32_t sv = sq + 2 * ATT_SLICE;

    float s[2][8][4] = {};
#pragma unroll
    for (int kt = 0; kt < 2; kt++) {
        uint32_t af[2][4];
#pragma unroll
        for (int mi = 0; mi < 2; mi++)
            ldsm4(af[mi][0], af[mi][1], af[mi][2], af[mi][3],
                  sq + (wrow * 32 + mi * 16 + (lane & 15)) * 80 + kt * 32 + (lane >> 4) * 16);
#pragma unroll
        for (int nj2 = 0; nj2 < 4; nj2++) {
            uint32_t bf[4];
            ldsm4(bf[0], bf[1], bf[2], bf[3],
                  sk + (nj2 * 16 + (lane & 7) + ((lane >> 4) << 3)) * 80
                     + kt * 32 + ((lane & 8) ? 16 : 0));
#pragma unroll
            for (int mi = 0; mi < 2; mi++) {
                mma16816(s[mi][nj2 * 2 + 0], af[mi], &bf[0]);
                mma16816(s[mi][nj2 * 2 + 1], af[mi], &bf[2]);
            }
        }
    }

    const int wy = (win >> 4) & 15, wx = win & 15;
    const bool my = (wy == 15), mx = (wx == 15);
#pragma unroll
    for (int mi = 0; mi < 2; mi++)
#pragma unroll
        for (int nj = 0; nj < 8; nj++)
#pragma unroll
            for (int e = 0; e < 4; e++) {
                const int i = wrow * 32 + mi * 16 + g + ((e >= 2) ? 8 : 0);
                const int j = nj * 8 + tg * 2 + (e & 1);
                const int iy = i >> 3, ix = i & 7, jy = j >> 3, jx = j & 7;
                float v = s[mi][nj][e] * 0.17677669529663687f
                        + srpb[((iy - jy + 7) * 15 + (ix - jx + 7)) * HEADS + head];
                const int ri = (my ? (iy < 4 ? 1 : 2) : 0) * 3 + (mx ? (ix < 4 ? 1 : 2) : 0);
                const int rj = (my ? (jy < 4 ? 1 : 2) : 0) * 3 + (mx ? (jx < 4 ? 1 : 2) : 0);
                if (ri != rj) v -= 100.f;
                s[mi][nj][e] = v;
            }
#pragma unroll
    for (int mi = 0; mi < 2; mi++)
#pragma unroll
        for (int h = 0; h < 2; h++) {
            float m = -1e30f;
#pragma unroll
            for (int nj = 0; nj < 8; nj++) {
                m = fmaxf(m, s[mi][nj][h * 2 + 0]);
                m = fmaxf(m, s[mi][nj][h * 2 + 1]);
            }
            m = fmaxf(m, __shfl_xor_sync(0xffffffffu, m, 1));
            m = fmaxf(m, __shfl_xor_sync(0xffffffffu, m, 2));
            float sum = 0.f;
#pragma unroll
            for (int nj = 0; nj < 8; nj++) {
                float e0 = __expf(s[mi][nj][h * 2 + 0] - m);
                float e1 = __expf(s[mi][nj][h * 2 + 1] - m);
                s[mi][nj][h * 2 + 0] = e0;
                s[mi][nj][h * 2 + 1] = e1;
                sum += e0 + e1;
            }
            sum += __shfl_xor_sync(0xffffffffu, sum, 1);
            sum += __shfl_xor_sync(0xffffffffu, sum, 2);
            const float inv = 1.f / sum;
#pragma unroll
            for (int nj = 0; nj < 8; nj++) {
                s[mi][nj][h * 2 + 0] *= inv;
                s[mi][nj][h * 2 + 1] *= inv;
            }
        }

    float o[2][4][4] = {};
#pragma unroll
    for (int kt = 0; kt < 4; kt++) {
        const int jr = kt * 16 + (lane & 7) + ((lane & 8) ? 8 : 0);
        const uint32_t vb = sv + jr * 80 + (lane >> 4) * 16;
        uint32_t b0[4], b1[4];
        ldsm4t(b0[0], b0[1], b0[2], b0[3], vb);
        ldsm4t(b1[0], b1[1], b1[2], b1[3], vb + 32);
#pragma unroll
        for (int mi = 0; mi < 2; mi++) {
            uint32_t a[4];
            a[0] = packbf(s[mi][2 * kt][0], s[mi][2 * kt][1]);
            a[1] = packbf(s[mi][2 * kt][2], s[mi][2 * kt][3]);
            a[2] = packbf(s[mi][2 * kt + 1][0], s[mi][2 * kt + 1][1]);
            a[3] = packbf(s[mi][2 * kt + 1][2], s[mi][2 * kt + 1][3]);
            mma16816(o[mi][0], a, &b0[0]);
            mma16816(o[mi][1], a, &b0[2]);
            mma16816(o[mi][2], a, &b1[0]);
            mma16816(o[mi][3], a, &b1[2]);
        }
    }

    __nv_bfloat16* ob = g_attn_bf + (size_t)(win * NTOK) * CH + head * HD;
#pragma unroll
    for (int mi = 0; mi < 2; mi++) {
        const int rlo = wrow * 32 + mi * 16 + g;
#pragma unroll
        for (int nf = 0; nf < 4; nf++) {
            const int d = nf * 8 + tg * 2;
            *(__nv_bfloat162*)&ob[(size_t)rlo * CH + d] =
                __floats2bfloat162_rn(o[mi][nf][0], o[mi][nf][1]);
            *(__nv_bfloat162*)&ob[(size_t)(rlo + 8) * CH + d] =
                __floats2bfloat162_rn(o[mi][nf][2], o[mi][nf][3]);
        }
    }
}

// ---------------- launch ----------------
extern "C" void kernel_launch(void* const* d_in, const int* in_sizes, int n_in,
                              void* d_out, int out_size) {
    (void)in_sizes; (void)n_in; (void)out_size;
    const float* x      = (const float*)d_in[0];
    const float* gn_w   = (const float*)d_in[1];
    const float* gn_b   = (const float*)d_in[2];
    const float* ln1_w  = (const float*)d_in[3];
    const float* ln1_b  = (const float*)d_in[4];
    const float* qkv_w  = (const float*)d_in[5];
    const float* qkv_b  = (const float*)d_in[6];
    const float* proj_w = (const float*)d_in[7];
    const float* proj_b = (const float*)d_in[8];
    const float* rpb    = (const float*)d_in[9];
    const float* ln2_w  = (const float*)d_in[10];
    const float* ln2_b  = (const float*)d_in[11];
    const float* fc1_w  = (const float*)d_in[12];
    const float* fc1_b  = (const float*)d_in[13];
    const float* fc2_w  = (const float*)d_in[14];
    const float* fc2_b  = (const float*)d_in[15];
    float* out = (float*)d_out;

    cudaFuncSetAttribute((const void*)attn_kernel,
                         cudaFuncAttributeMaxDynamicSharedMemorySize, ATT_SMEM);
    cudaFuncSetAttribute((const void*)mma_gemm<0>, cudaFuncAttributeMaxDynamicSharedMemorySize, GSMEM);
    cudaFuncSetAttribute((const void*)mma_gemm<2>, cudaFuncAttributeMaxDynamicSharedMemorySize, GSMEM);
    cudaFuncSetAttribute((const void*)mma_gemm<3>, cudaFuncAttributeMaxDynamicSharedMemorySize, GSMEM);
    cudaFuncSetAttribute((const void*)proj_ln2, cudaFuncAttributeMaxDynamicSharedMemorySize, PSMEM);

    // GN partial sums + weight transposes in one launch
    prep_kernel<<<1456, 256>>>(x, qkv_w, proj_w, fc1_w, fc2_w);
    gn_final_kernel<<<BATCH, 128>>>();
    build_kernel<<<BATCH * HH * (WW / 32), 256>>>(x, gn_w, gn_b, ln1_w, ln1_b);

    // QKV -> head-major g_qkv_bf
    mma_gemm<0><<<dim3(6, TOK / 128), 256, GSMEM>>>(qkv_b, nullptr);

    attn_kernel<<<NWIN, 384, ATT_SMEM>>>(rpb);

    // fused proj + residual pre-sum + LN2 -> g_xb2 (fp32), g_h2_bf (bf16)
    proj_ln2<<<NWIN, 256, PSMEM>>>(proj_b, ln2_w, ln2_b);

    // fc1 + GELU -> g_hid_bf
    mma_gemm<2><<<dim3(8, TOK / 128), 256, GSMEM>>>(fc1_b, nullptr);

    // fc2 + pre-summed residual + clamp -> out (NCHW)
    mma_gemm<3><<<dim3(2, TOK / 128), 256, GSMEM>>>(fc2_b, out);
}

// round 17
// speedup vs baseline: 1.1679x; 1.0201x over previous
#include <cuda_runtime.h>
#include <cuda_bf16.h>
#include <cstdint>
#include <math.h>

// Problem constants
#define BATCH 8
#define CH    192
#define HH    128
#define WW    128
#define HEADS 6
#define HD    32
#define WIN   8
#define NTOK  64
#define NWIN  2048
#define TOK   131072
#define HID   768
#define SHIFT 4

// ---------------- device scratch ----------------
__device__ __align__(256) float g_xb [TOK * CH];   // GN output NHWC fp32 (residual & shortcut)
__device__ __align__(256) float g_xb2[TOK * CH];   // xb2 + xb (pre-summed residual for fc2)
__device__ __align__(256) __nv_bfloat16 g_hw_bf [TOK * CH];
// qkv in head-major layout: [win][head][mat(q,k,v)][64 tok][32 dim]
__device__ __align__(256) __nv_bfloat16 g_qkv_bf[(size_t)TOK * 3 * CH];
__device__ __align__(256) __nv_bfloat16 g_attn_bf[TOK * CH];
__device__ __align__(256) __nv_bfloat16 g_h2_bf [TOK * CH];   // LN2 output (spatial order)
__device__ __align__(256) __nv_bfloat16 g_hid_bf[(size_t)TOK * HID];
__device__ __align__(256) __nv_bfloat16 g_wqkv[3 * CH * CH];   // [576,192] (N,K)
__device__ __align__(256) __nv_bfloat16 g_wproj[CH * CH];      // [192,192]
__device__ __align__(256) __nv_bfloat16 g_wfc1[HID * CH];      // [768,192]
__device__ __align__(256) __nv_bfloat16 g_wfc2[CH * HID];      // [192,768]
__device__ float g_part[BATCH * 128 * 2];
__device__ float g_stats[BATCH * 2];

// ---------------- helpers ----------------
__device__ __forceinline__ uint32_t s2u(const void* p) {
    uint32_t a;
    asm("{ .reg .u64 t; cvta.to.shared.u64 t, %1; cvt.u32.u64 %0, t; }" : "=r"(a) : "l"(p));
    return a;
}
__device__ __forceinline__ uint32_t sw128(uint32_t o) { return o ^ ((o >> 3) & 0x70); }

__device__ __forceinline__ void cp16(uint32_t saddr, const void* gptr) {
    asm volatile("cp.async.cg.shared.global [%0], [%1], 16;" :: "r"(saddr), "l"(gptr) : "memory");
}
__device__ __forceinline__ void cp_commit() {
    asm volatile("cp.async.commit_group;" ::: "memory");
}
__device__ __forceinline__ void cp_wait0() {
    asm volatile("cp.async.wait_group 0;" ::: "memory");
}
__device__ __forceinline__ void cp_wait2() {
    asm volatile("cp.async.wait_group 2;" ::: "memory");
}
__device__ __forceinline__ void ldsm4(uint32_t& r0, uint32_t& r1, uint32_t& r2, uint32_t& r3,
                                      uint32_t a) {
    asm volatile("ldmatrix.sync.aligned.m8n8.x4.shared.b16 {%0,%1,%2,%3}, [%4];"
                 : "=r"(r0), "=r"(r1), "=r"(r2), "=r"(r3) : "r"(a));
}
__device__ __forceinline__ void ldsm4t(uint32_t& r0, uint32_t& r1, uint32_t& r2, uint32_t& r3,
                                       uint32_t a) {
    asm volatile("ldmatrix.sync.aligned.m8n8.x4.trans.shared.b16 {%0,%1,%2,%3}, [%4];"
                 : "=r"(r0), "=r"(r1), "=r"(r2), "=r"(r3) : "r"(a));
}
__device__ __forceinline__ void mma16816(float* c, const uint32_t* a, const uint32_t* b) {
    asm volatile(
        "mma.sync.aligned.m16n8k16.row.col.f32.bf16.bf16.f32 "
        "{%0,%1,%2,%3}, {%4,%5,%6,%7}, {%8,%9}, {%0,%1,%2,%3};"
        : "+f"(c[0]), "+f"(c[1]), "+f"(c[2]), "+f"(c[3])
        : "r"(a[0]), "r"(a[1]), "r"(a[2]), "r"(a[3]), "r"(b[0]), "r"(b[1]));
}
__device__ __forceinline__ uint32_t packbf(float a, float b) {
    __nv_bfloat162 h = __floats2bfloat162_rn(a, b);
    return *(uint32_t*)&h;
}

// ---------------- prep: GN partial sums (blocks 0..1023) + weight transposes (1024..1455) ----------------
__global__ void prep_kernel(const float* __restrict__ x,
                            const float* __restrict__ qkv_w, const float* __restrict__ proj_w,
                            const float* __restrict__ fc1_w, const float* __restrict__ fc2_w) {
    const int tid = threadIdx.x;
    if (blockIdx.x < 1024) {
        const int b = blockIdx.x >> 7;
        const int chunk = blockIdx.x & 127;
        const size_t per_sample = (size_t)CH * HH * WW;
        const float* p = x + (size_t)b * per_sample + (size_t)chunk * 24576;
        float s = 0.f, sq = 0.f;
        for (int i = tid; i < 24576; i += 256) { float v = p[i]; s += v; sq += v * v; }
        __shared__ float rs[256], rq[256];
        rs[tid] = s; rq[tid] = sq;
        __syncthreads();
        for (int o = 128; o; o >>= 1) {
            if (tid < o) { rs[tid] += rs[tid + o]; rq[tid] += rq[tid + o]; }
            __syncthreads();
        }
        if (tid == 0) {
            g_part[blockIdx.x * 2 + 0] = rs[0];
            g_part[blockIdx.x * 2 + 1] = rq[0];
        }
    } else {
        const int b = blockIdx.x - 1024;
        const float* W;
        __nv_bfloat16* Wt;
        int K, N, bx, by;
        if (b < 108)      { W = qkv_w;  Wt = g_wqkv;  K = CH;  N = 3 * CH; bx = b % 18;  by = b / 18; }
        else if (b < 144) { int t = b - 108; W = proj_w; Wt = g_wproj; K = CH;  N = CH;  bx = t % 6;  by = t / 6; }
        else if (b < 288) { int t = b - 144; W = fc1_w;  Wt = g_wfc1;  K = CH;  N = HID; bx = t % 24; by = t / 24; }
        else              { int t = b - 288; W = fc2_w;  Wt = g_wfc2;  K = HID; N = CH;  bx = t % 6;  by = t / 6; }
        __shared__ float t[32][33];
        const int k0 = by * 32, n0 = bx * 32;
        const int lx = tid & 31, ly = tid >> 5;
        for (int r = ly; r < 32; r += 8) t[r][lx] = W[(size_t)(k0 + r) * N + n0 + lx];
        __syncthreads();
        for (int r = ly; r < 32; r += 8)
            Wt[(size_t)(n0 + r) * K + k0 + lx] = __float2bfloat16(t[lx][r]);
    }
}

__global__ void gn_final_kernel() {
    const int b = blockIdx.x;
    const int tid = threadIdx.x;
    __shared__ double ds[128], dq[128];
    ds[tid] = (double)g_part[(b * 128 + tid) * 2 + 0];
    dq[tid] = (double)g_part[(b * 128 + tid) * 2 + 1];
    __syncthreads();
    for (int o = 64; o; o >>= 1) {
        if (tid < o) { ds[tid] += ds[tid + o]; dq[tid] += dq[tid + o]; }
        __syncthreads();
    }
    if (tid == 0) {
        const double n = 3145728.0;
        double mean = ds[0] / n;
        double var = dq[0] / n - mean * mean;
        g_stats[b * 2 + 0] = (float)mean;
        g_stats[b * 2 + 1] = (float)(1.0 / sqrt(var + 1e-5));
    }
}

// ---------------- GN apply + xb store + LN1 + shift + window partition ----------------
__global__ void build_kernel(const float* __restrict__ x,
                             const float* __restrict__ gnw, const float* __restrict__ gnb,
                             const float* __restrict__ ln1w, const float* __restrict__ ln1b) {
    __shared__ float t[CH][33];
    const int bid = blockIdx.x;
    const int xt = bid & 3;
    const int y  = (bid >> 2) & 127;
    const int b  = bid >> 9;
    const int tid = threadIdx.x;
    const float mu = g_stats[b * 2 + 0];
    const float rstd = g_stats[b * 2 + 1];
    const int lx = tid & 31;
    const int c0 = tid >> 5;

    for (int c = c0; c < CH; c += 8) {
        float v = x[((((size_t)b * CH + c) * HH + y) * WW) + xt * 32 + lx];
        t[c][lx] = (v - mu) * rstd * gnw[c] + gnb[c];
    }
    __syncthreads();

    const size_t tokbase = ((size_t)(b * HH + y) * WW) + xt * 32;
    for (int j = 0; j < 32; j++) {
        if (tid < CH) g_xb[(tokbase + j) * CH + tid] = t[tid][j];
    }

    const int warp = tid >> 5, lane = tid & 31;
    for (int j = warp; j < 32; j += 8) {
        float s = 0.f, sq = 0.f;
#pragma unroll
        for (int k = 0; k < 6; k++) {
            float v = t[lane + k * 32][j];
            s += v; sq += v * v;
        }
#pragma unroll
        for (int o = 16; o; o >>= 1) {
            s  += __shfl_xor_sync(0xffffffffu, s, o);
            sq += __shfl_xor_sync(0xffffffffu, sq, o);
        }
        float mean = s * (1.f / CH);
        float var = sq * (1.f / CH) - mean * mean;
        float r = rsqrtf(var + 1e-5f);
        const int xx = xt * 32 + j;
        const int ys = (y - SHIFT) & 127;
        const int xs = (xx - SHIFT) & 127;
        const size_t dst = ((size_t)(((b * 16 + (ys >> 3)) * 16 + (xs >> 3)) * NTOK)
                            + (ys & 7) * 8 + (xs & 7)) * CH;
#pragma unroll
        for (int k = 0; k < 6; k++) {
            int c = lane + k * 32;
            g_hw_bf[dst + c] = __float2bfloat16((t[c][j] - mean) * r * ln1w[c] + ln1b[c]);
        }
    }
}

// ---------------- mma.sync bf16 GEMM, CTA tile 128x96, 3-stage ----------------
// K=192 (qkv, fc1): full prefetch, barrier-free mainloop.
// K=768 (fc2): rolling 3-stage.
// MODE 0: qkv  -> g_qkv_bf HEAD-MAJOR, smem-staged coalesced store
// MODE 2: fc1  -> GELU -> g_hid_bf
// MODE 3: fc2  -> out NCHW = clamp(. + g_xb2), smem-transposed coalesced store
#define GSTAGE 28672
#define GSMEM  (3 * GSTAGE)   // 86016

template <int MODE>
__global__ void __launch_bounds__(256)
mma_gemm(const float* __restrict__ bias, float* __restrict__ outp) {
    constexpr int K    = (MODE == 3) ? HID : CH;
    constexpr int NST  = K / 64;
    const __nv_bfloat16* const A  = (MODE == 0) ? g_hw_bf : (MODE == 2) ? g_h2_bf : g_hid_bf;
    const __nv_bfloat16* const Bt = (MODE == 0) ? g_wqkv : (MODE == 2) ? g_wfc1 : g_wfc2;
    constexpr int Nout = (MODE == 0) ? 3 * CH : (MODE == 2) ? HID : CH;

    extern __shared__ __align__(1024) uint8_t smx[];
    const uint32_t smb = s2u(smx);
    const int tid = threadIdx.x;
    const int wid = tid >> 5, lane = tid & 31;
    const int wm = wid & 3, wn = wid >> 2;    // 4m x 2n
    const int m0 = blockIdx.y * 128;
    const int n0c = blockIdx.x * 96;

    const __nv_bfloat16* const Abase = A  + (size_t)m0 * K;
    const __nv_bfloat16* const Bbase = Bt + (size_t)n0c * K;

    auto load_stage = [&](int st) {
        const uint32_t sA = smb + (st % 3) * GSTAGE;
        const uint32_t sB = sA + 16384;
        const int kel = st * 64;
#pragma unroll
        for (int i = 0; i < 4; i++) {            // A: 128 rows x 128B
            int e = tid + i * 256;
            int row = e >> 3, c16 = e & 7;
            cp16(sA + sw128(row * 128 + c16 * 16), Abase + (size_t)row * K + kel + c16 * 8);
        }
#pragma unroll
        for (int i = 0; i < 3; i++) {            // B: 96 rows x 128B
            int e = tid + i * 256;
            int row = e >> 3, c16 = e & 7;
            cp16(sB + sw128(row * 128 + c16 * 16), Bbase + (size_t)row * K + kel + c16 * 8);
        }
    };

    float acc[2][6][4] = {};

    const int arow0 = wm * 32 + (lane & 15);
    const int akoff = (lane >> 4) * 16;
    const int brow0 = wn * 48 + (lane & 7) + ((lane >> 4) << 3);
    const int bkoff = (lane & 8) ? 16 : 0;

    load_stage(0); cp_commit();
    load_stage(1); cp_commit();
    load_stage(2); cp_commit();

    if (NST == 3) {
        cp_wait0();
        __syncthreads();
#pragma unroll
        for (int st = 0; st < 3; st++) {
            const uint32_t sA = smb + st * GSTAGE;
            const uint32_t sB = sA + 16384;
#pragma unroll
            for (int kk = 0; kk < 4; kk++) {
                uint32_t af[2][4], bf[3][4];
#pragma unroll
                for (int mi = 0; mi < 2; mi++)
                    ldsm4(af[mi][0], af[mi][1], af[mi][2], af[mi][3],
                          sA + sw128((arow0 + mi * 16) * 128 + kk * 32 + akoff));
#pragma unroll
                for (int bi = 0; bi < 3; bi++)
                    ldsm4(bf[bi][0], bf[bi][1], bf[bi][2], bf[bi][3],
                          sB + sw128((brow0 + bi * 16) * 128 + kk * 32 + bkoff));
#pragma unroll
                for (int mi = 0; mi < 2; mi++)
#pragma unroll
                    for (int ni = 0; ni < 6; ni++)
                        mma16816(acc[mi][ni], af[mi], &bf[ni >> 1][(ni & 1) * 2]);
            }
        }
    } else {
        for (int st = 0; st < NST; st++) {
            cp_wait2();
            __syncthreads();
            const uint32_t sA = smb + (st % 3) * GSTAGE;
            const uint32_t sB = sA + 16384;
#pragma unroll
            for (int kk = 0; kk < 4; kk++) {
                uint32_t af[2][4], bf[3][4];
#pragma unroll
                for (int mi = 0; mi < 2; mi++)
                    ldsm4(af[mi][0], af[mi][1], af[mi][2], af[mi][3],
                          sA + sw128((arow0 + mi * 16) * 128 + kk * 32 + akoff));
#pragma unroll
                for (int bi = 0; bi < 3; bi++)
                    ldsm4(bf[bi][0], bf[bi][1], bf[bi][2], bf[bi][3],
                          sB + sw128((brow0 + bi * 16) * 128 + kk * 32 + bkoff));
#pragma unroll
                for (int mi = 0; mi < 2; mi++)
#pragma unroll
                    for (int ni = 0; ni < 6; ni++)
                        mma16816(acc[mi][ni], af[mi], &bf[ni >> 1][(ni & 1) * 2]);
            }
            __syncthreads();
            if (st + 3 < NST) load_stage(st + 3);
            cp_commit();
        }
    }

    // ---- epilogue ----
    const int g = lane >> 2, tg = lane & 3;
    const int nbase = n0c + wn * 48;
    float2 bv[6];
#pragma unroll
    for (int ni = 0; ni < 6; ni++) bv[ni] = *(const float2*)&bias[nbase + ni * 8 + tg * 2];

    if (MODE == 0) {
        // stage bf16 C-tile [128 rows][96 cols], pitch 208B, then coalesced head-major copy
        __syncthreads();   // mainloop smem reads done in all warps
#pragma unroll
        for (int mi = 0; mi < 2; mi++)
#pragma unroll
            for (int half = 0; half < 2; half++) {
                const int rl = wm * 32 + mi * 16 + g + half * 8;
#pragma unroll
                for (int ni = 0; ni < 6; ni++) {
                    float v0 = acc[mi][ni][half * 2 + 0] + bv[ni].x;
                    float v1 = acc[mi][ni][half * 2 + 1] + bv[ni].y;
                    uint32_t p = packbf(v0, v1);
                    asm volatile("st.shared.b32 [%0], %1;"
                                 :: "r"(smb + rl * 208 + wn * 96 + ni * 16 + tg * 4), "r"(p)
                                 : "memory");
                }
            }
        __syncthreads();
        const int win0 = blockIdx.y * 2;
        const int mat = n0c / 192;
        const int head0 = (n0c % 192) / 32;
#pragma unroll
        for (int i = 0; i < 6; i++) {
            int idx = tid + i * 256;                 // 0..1535
            int slice = idx >> 8, within = idx & 255;
            int winl = slice / 3, hm = slice - winl * 3;
            int tok = within >> 2, q16 = within & 3;
            uint4 v;
            asm volatile("ld.shared.v4.u32 {%0,%1,%2,%3}, [%4];"
                         : "=r"(v.x), "=r"(v.y), "=r"(v.z), "=r"(v.w)
                         : "r"(smb + (winl * 64 + tok) * 208 + hm * 64 + q16 * 16));
            size_t sbase = (((size_t)(win0 + winl) * HEADS + head0 + hm) * 3 + mat) * 2048;
            *(uint4*)&g_qkv_bf[sbase + tok * 32 + q16 * 8] = v;
        }
    } else if (MODE == 2) {
#pragma unroll
        for (int mi = 0; mi < 2; mi++)
#pragma unroll
            for (int half = 0; half < 2; half++) {
                const int r = m0 + wm * 32 + mi * 16 + g + half * 8;
#pragma unroll
                for (int ni = 0; ni < 6; ni++) {
                    float v0 = acc[mi][ni][half * 2 + 0] + bv[ni].x;
                    float v1 = acc[mi][ni][half * 2 + 1] + bv[ni].y;
                    v0 = 0.5f * v0 * (1.f + erff(v0 * 0.7071067811865475f));
                    v1 = 0.5f * v1 * (1.f + erff(v1 * 0.7071067811865475f));
                    __nv_bfloat162 h2 = __floats2bfloat162_rn(v0, v1);
                    *(__nv_bfloat162*)&g_hid_bf[(size_t)r * Nout + nbase + ni * 8 + tg * 2] = h2;
                }
            }
    } else {
        // MODE 3: residual + clamp -> transposed smem [96 c][128 x] fp32 (pitch 528B),
        // then coalesced per-channel NCHW store
#pragma unroll
        for (int mi = 0; mi < 2; mi++)
#pragma unroll
            for (int half = 0; half < 2; half++) {
                const int rl = wm * 32 + mi * 16 + g + half * 8;
                const size_t off = (size_t)(m0 + rl) * CH;
#pragma unroll
                for (int ni = 0; ni < 6; ni++) {
                    const int cl = wn * 48 + ni * 8 + tg * 2;
                    const size_t o = off + n0c + cl;
                    float2 a2 = *(const float2*)&g_xb2[o];
                    float v0 = acc[mi][ni][half * 2 + 0] + bv[ni].x + a2.x;
                    float v1 = acc[mi][ni][half * 2 + 1] + bv[ni].y + a2.y;
                    v0 = fminf(10.f, fmaxf(-10.f, v0));
                    v1 = fminf(10.f, fmaxf(-10.f, v1));
                    asm volatile("st.shared.f32 [%0], %1;"
                                 :: "r"(smb + cl * 528 + rl * 4), "f"(v0) : "memory");
                    asm volatile("st.shared.f32 [%0], %1;"
                                 :: "r"(smb + (cl + 1) * 528 + rl * 4), "f"(v1) : "memory");
                }
            }
        __syncthreads();
        const int bb2 = m0 >> 14, yy = (m0 >> 7) & 127;
#pragma unroll
        for (int i = 0; i < 12; i++) {
            int idx = tid + i * 256;                 // 0..3071
            int c = idx >> 5;
            int xo = (idx & 31) * 4;                 // float index
            uint4 v;
            asm volatile("ld.shared.v4.u32 {%0,%1,%2,%3}, [%4];"
                         : "=r"(v.x), "=r"(v.y), "=r"(v.z), "=r"(v.w)
                         : "r"(smb + c * 528 + xo * 4));
            size_t oaddr = (((size_t)bb2 * CH + n0c + c) * HH + yy) * WW + xo;
            *(uint4*)&outp[oaddr] = v;
        }
    }
}

// ---------------- fused proj + LN2: one window per CTA (M=64, N=192), full prefetch ----------------
#define PSTAGE 32768            // A 8KB + B 24KB
#define PSMEM  (3 * PSTAGE)     // 98304

__global__ void __launch_bounds__(256, 2)
proj_ln2(const float* __restrict__ bias,
         const float* __restrict__ ln2w, const float* __restrict__ ln2b) {
    constexpr int K = CH;
    extern __shared__ __align__(1024) uint8_t smx[];
    const uint32_t smb = s2u(smx);
    const int tid = threadIdx.x;
    const int wid = tid >> 5, lane = tid & 31;
    const int wm = wid & 1, wn = wid >> 1;     // 2m x 4n
    const int win = blockIdx.x;
    const int m0 = win * 64;

    const __nv_bfloat16* const Abase = g_attn_bf + (size_t)m0 * K;

    auto load_stage = [&](int st) {
        const uint32_t sA = smb + st * PSTAGE;
        const uint32_t sB = sA + 8192;
        const int kel = st * 64;
#pragma unroll
        for (int i = 0; i < 2; i++) {            // A: 64 rows x 128B
            int e = tid + i * 256;
            int row = e >> 3, c16 = e & 7;
            cp16(sA + sw128(row * 128 + c16 * 16), Abase + (size_t)row * K + kel + c16 * 8);
        }
#pragma unroll
        for (int i = 0; i < 6; i++) {            // B: 192 rows x 128B
            int e = tid + i * 256;
            int row = e >> 3, c16 = e & 7;
            cp16(sB + sw128(row * 128 + c16 * 16), g_wproj + (size_t)row * K + kel + c16 * 8);
        }
    };

    float acc[2][6][4] = {};
    const int arow0 = wm * 32 + (lane & 15);
    const int akoff = (lane >> 4) * 16;
    const int brow0 = wn * 48 + (lane & 7) + ((lane >> 4) << 3);
    const int bkoff = (lane & 8) ? 16 : 0;

    load_stage(0); cp_commit();
    load_stage(1); cp_commit();
    load_stage(2); cp_commit();
    cp_wait0();
    __syncthreads();

#pragma unroll
    for (int st = 0; st < 3; st++) {
        const uint32_t sA = smb + st * PSTAGE;
        const uint32_t sB = sA + 8192;
#pragma unroll
        for (int kk = 0; kk < 4; kk++) {
            uint32_t af[2][4], bf[3][4];
#pragma unroll
            for (int mi = 0; mi < 2; mi++)
                ldsm4(af[mi][0], af[mi][1], af[mi][2], af[mi][3],
                      sA + sw128((arow0 + mi * 16) * 128 + kk * 32 + akoff));
#pragma unroll
            for (int bi = 0; bi < 3; bi++)
                ldsm4(bf[bi][0], bf[bi][1], bf[bi][2], bf[bi][3],
                      sB + sw128((brow0 + bi * 16) * 128 + kk * 32 + bkoff));
#pragma unroll
            for (int mi = 0; mi < 2; mi++)
#pragma unroll
                for (int ni = 0; ni < 6; ni++)
                    mma16816(acc[mi][ni], af[mi], &bf[ni >> 1][(ni & 1) * 2]);
        }
    }
    __syncthreads();   // stage smem now reusable

    float* sx = (float*)smx;                     // [64][196] xb2 scratch
    float2* spart = (float2*)(smx + 50176);      // [64][4] (sum, sumsq)

    const int g = lane >> 2, tg = lane & 3;
    const int nbase = wn * 48;
    float2 bv[6], lw[6], lb[6];
#pragma unroll
    for (int ni = 0; ni < 6; ni++) {
        bv[ni] = *(const float2*)&bias[nbase + ni * 8 + tg * 2];
        lw[ni] = *(const float2*)&ln2w[nbase + ni * 8 + tg * 2];
        lb[ni] = *(const float2*)&ln2b[nbase + ni * 8 + tg * 2];
    }

    const int bb2 = win >> 8, wy = (win >> 4) & 15, wx = win & 15;

#pragma unroll
    for (int mi = 0; mi < 2; mi++) {
#pragma unroll
        for (int half = 0; half < 2; half++) {
            const int rl = wm * 32 + mi * 16 + g + half * 8;
            const int yy = ((wy << 3) + (rl >> 3) + SHIFT) & 127;
            const int xx = ((wx << 3) + (rl & 7) + SHIFT) & 127;
            const size_t dr = ((size_t)((bb2 * HH + yy) * WW + xx)) * CH;
            float s = 0.f, sq = 0.f;
#pragma unroll
            for (int ni = 0; ni < 6; ni++) {
                const int c = nbase + ni * 8 + tg * 2;
                float2 xbv = *(const float2*)&g_xb[dr + c];
                float x2a = acc[mi][ni][half * 2 + 0] + bv[ni].x + xbv.x;
                float x2b = acc[mi][ni][half * 2 + 1] + bv[ni].y + xbv.y;
                float2 ov;
                ov.x = x2a + xbv.x; ov.y = x2b + xbv.y;
                *(float2*)&g_xb2[dr + c] = ov;
                sx[rl * 196 + c] = x2a;
                sx[rl * 196 + c + 1] = x2b;
                s += x2a + x2b;
                sq += x2a * x2a + x2b * x2b;
            }
            s  += __shfl_xor_sync(0xffffffffu, s, 1);
            s  += __shfl_xor_sync(0xffffffffu, s, 2);
            sq += __shfl_xor_sync(0xffffffffu, sq, 1);
            sq += __shfl_xor_sync(0xffffffffu, sq, 2);
            if (tg == 0) { spart[rl * 4 + wn] = make_float2(s, sq); }
        }
    }
    __syncthreads();

#pragma unroll
    for (int mi = 0; mi < 2; mi++) {
#pragma unroll
        for (int half = 0; half < 2; half++) {
            const int rl = wm * 32 + mi * 16 + g + half * 8;
            float s = 0.f, sq = 0.f;
#pragma unroll
            for (int p = 0; p < 4; p++) {
                float2 pp = spart[rl * 4 + p];
                s += pp.x; sq += pp.y;
            }
            float mean = s * (1.f / CH);
            float var = sq * (1.f / CH) - mean * mean;
            float rstd = rsqrtf(var + 1e-5f);
            const int yy = ((wy << 3) + (rl >> 3) + SHIFT) & 127;
            const int xx = ((wx << 3) + (rl & 7) + SHIFT) & 127;
            const size_t dr = ((size_t)((bb2 * HH + yy) * WW + xx)) * CH;
#pragma unroll
            for (int ni = 0; ni < 6; ni++) {
                const int c = nbase + ni * 8 + tg * 2;
                float x2a = sx[rl * 196 + c];
                float x2b = sx[rl * 196 + c + 1];
                float h0 = (x2a - mean) * rstd * lw[ni].x + lb[ni].x;
                float h1 = (x2b - mean) * rstd * lw[ni].y + lb[ni].y;
                *(uint32_t*)&g_h2_bf[dr + c] = packbf(h0, h1);
            }
        }
    }
}

// ---------------- tensor-core windowed attention ----------------
#define ATT_SLICE 5120
#define ATT_QKV   (18 * ATT_SLICE)
#define ATT_SMEM  (ATT_QKV + 5408)
__global__ void __launch_bounds__(384)
attn_kernel(const float* __restrict__ rpb) {
    extern __shared__ __align__(128) uint8_t smem_a[];
    float* srpb = (float*)(smem_a + ATT_QKV);
    const int win = blockIdx.x;
    const int tid = threadIdx.x;
    const int wid = tid >> 5, lane = tid & 31;
    const int head = wid >> 1, wrow = wid & 1;
    const int g = lane >> 2, tg = lane & 3;

    for (int f = tid; f < 225 * HEADS; f += 384) srpb[f] = rpb[f];

    {
        const __nv_bfloat16* gb = g_qkv_bf + (size_t)win * 18 * 2048;
#pragma unroll
        for (int i = 0; i < 12; i++) {
            int idx = tid + i * 384;
            int slice = idx >> 8;
            int cidx = idx & 255;
            int row = cidx >> 2, ch = cidx & 3;
            uint4 v = *(const uint4*)(gb + slice * 2048 + cidx * 8);
            *(uint4*)(smem_a + slice * ATT_SLICE + row * 80 + ch * 16) = v;
        }
    }
    __syncthreads();

    const uint32_t sq = s2u(smem_a) + (head * 3 + 0) * ATT_SLICE;
    const uint32_t sk = sq + ATT_SLICE;
    const uint32_t sv = sq + 2 * ATT_SLICE;

    float s[2][8][4] = {};
#pragma unroll
    for (int kt = 0; kt < 2; kt++) {
        uint32_t af[2][4];
#pragma unroll
        for (int mi = 0; mi < 2; mi++)
            ldsm4(af[mi][0], af[mi][1], af[mi][2], af[mi][3],
                  sq + (wrow * 32 + mi * 16 + (lane & 15)) * 80 + kt * 32 + (lane >> 4) * 16);
#pragma unroll
        for (int nj2 = 0; nj2 < 4; nj2++) {
            uint32_t bf[4];
            ldsm4(bf[0], bf[1], bf[2], bf[3],
                  sk + (nj2 * 16 + (lane & 7) + ((lane >> 4) << 3)) * 80
                     + kt * 32 + ((lane & 8) ? 16 : 0));
#pragma unroll
            for (int mi = 0; mi < 2; mi++) {
                mma16816(s[mi][nj2 * 2 + 0], af[mi], &bf[0]);
                mma16816(s[mi][nj2 * 2 + 1], af[mi], &bf[2]);
            }
        }
    }

    const int wy = (win >> 4) & 15, wx = win & 15;
    const bool my = (wy == 15), mx = (wx == 15);
#pragma unroll
    for (int mi = 0; mi < 2; mi++)
#pragma unroll
        for (int nj = 0; nj < 8; nj++)
#pragma unroll
            for (int e = 0; e < 4; e++) {
                const int i = wrow * 32 + mi * 16 + g + ((e >= 2) ? 8 : 0);
                const int j = nj * 8 + tg * 2 + (e & 1);
                const int iy = i >> 3, ix = i & 7, jy = j >> 3, jx = j & 7;
                float v = s[mi][nj][e] * 0.17677669529663687f
                        + srpb[((iy - jy + 7) * 15 + (ix - jx + 7)) * HEADS + head];
                const int ri = (my ? (iy < 4 ? 1 : 2) : 0) * 3 + (mx ? (ix < 4 ? 1 : 2) : 0);
                const int rj = (my ? (jy < 4 ? 1 : 2) : 0) * 3 + (mx ? (jx < 4 ? 1 : 2) : 0);
                if (ri != rj) v -= 100.f;
                s[mi][nj][e] = v;
            }
#pragma unroll
    for (int mi = 0; mi < 2; mi++)
#pragma unroll
        for (int h = 0; h < 2; h++) {
            float m = -1e30f;
#pragma unroll
            for (int nj = 0; nj < 8; nj++) {
                m = fmaxf(m, s[mi][nj][h * 2 + 0]);
                m = fmaxf(m, s[mi][nj][h * 2 + 1]);
            }
            m = fmaxf(m, __shfl_xor_sync(0xffffffffu, m, 1));
            m = fmaxf(m, __shfl_xor_sync(0xffffffffu, m, 2));
            float sum = 0.f;
#pragma unroll
            for (int nj = 0; nj < 8; nj++) {
                float e0 = __expf(s[mi][nj][h * 2 + 0] - m);
                float e1 = __expf(s[mi][nj][h * 2 + 1] - m);
                s[mi][nj][h * 2 + 0] = e0;
                s[mi][nj][h * 2 + 1] = e1;
                sum += e0 + e1;
            }
            sum += __shfl_xor_sync(0xffffffffu, sum, 1);
            sum += __shfl_xor_sync(0xffffffffu, sum, 2);
            const float inv = 1.f / sum;
#pragma unroll
            for (int nj = 0; nj < 8; nj++) {
                s[mi][nj][h * 2 + 0] *= inv;
                s[mi][nj][h * 2 + 1] *= inv;
            }
        }

    float o[2][4][4] = {};
#pragma unroll
    for (int kt = 0; kt < 4; kt++) {
        const int jr = kt * 16 + (lane & 7) + ((lane & 8) ? 8 : 0);
        const uint32_t vb = sv + jr * 80 + (lane >> 4) * 16;
        uint32_t b0[4], b1[4];
        ldsm4t(b0[0], b0[1], b0[2], b0[3], vb);
        ldsm4t(b1[0], b1[1], b1[2], b1[3], vb + 32);
#pragma unroll
        for (int mi = 0; mi < 2; mi++) {
            uint32_t a[4];
            a[0] = packbf(s[mi][2 * kt][0], s[mi][2 * kt][1]);
            a[1] = packbf(s[mi][2 * kt][2], s[mi][2 * kt][3]);
            a[2] = packbf(s[mi][2 * kt + 1][0], s[mi][2 * kt + 1][1]);
            a[3] = packbf(s[mi][2 * kt + 1][2], s[mi][2 * kt + 1][3]);
            mma16816(o[mi][0], a, &b0[0]);
            mma16816(o[mi][1], a, &b0[2]);
            mma16816(o[mi][2], a, &b1[0]);
            mma16816(o[mi][3], a, &b1[2]);
        }
    }

    __nv_bfloat16* ob = g_attn_bf + (size_t)(win * NTOK) * CH + head * HD;
#pragma unroll
    for (int mi = 0; mi < 2; mi++) {
        const int rlo = wrow * 32 + mi * 16 + g;
#pragma unroll
        for (int nf = 0; nf < 4; nf++) {
            const int d = nf * 8 + tg * 2;
            *(__nv_bfloat162*)&ob[(size_t)rlo * CH + d] =
                __floats2bfloat162_rn(o[mi][nf][0], o[mi][nf][1]);
            *(__nv_bfloat162*)&ob[(size_t)(rlo + 8) * CH + d] =
                __floats2bfloat162_rn(o[mi][nf][2], o[mi][nf][3]);
        }
    }
}

// ---------------- launch ----------------
extern "C" void kernel_launch(void* const* d_in, const int* in_sizes, int n_in,
                              void* d_out, int out_size) {
    (void)in_sizes; (void)n_in; (void)out_size;
    const float* x      = (const float*)d_in[0];
    const float* gn_w   = (const float*)d_in[1];
    const float* gn_b   = (const float*)d_in[2];
    const float* ln1_w  = (const float*)d_in[3];
    const float* ln1_b  = (const float*)d_in[4];
    const float* qkv_w  = (const float*)d_in[5];
    const float* qkv_b  = (const float*)d_in[6];
    const float* proj_w = (const float*)d_in[7];
    const float* proj_b = (const float*)d_in[8];
    const float* rpb    = (const float*)d_in[9];
    const float* ln2_w  = (const float*)d_in[10];
    const float* ln2_b  = (const float*)d_in[11];
    const float* fc1_w  = (const float*)d_in[12];
    const float* fc1_b  = (const float*)d_in[13];
    const float* fc2_w  = (const float*)d_in[14];
    const float* fc2_b  = (const float*)d_in[15];
    float* out = (float*)d_out;

    cudaFuncSetAttribute((const void*)attn_kernel,
                         cudaFuncAttributeMaxDynamicSharedMemorySize, ATT_SMEM);
    cudaFuncSetAttribute((const void*)mma_gemm<0>, cudaFuncAttributeMaxDynamicSharedMemorySize, GSMEM);
    cudaFuncSetAttribute((const void*)mma_gemm<2>, cudaFuncAttributeMaxDynamicSharedMemorySize, GSMEM);
    cudaFuncSetAttribute((const void*)mma_gemm<3>, cudaFuncAttributeMaxDynamicSharedMemorySize, GSMEM);
    cudaFuncSetAttribute((const void*)proj_ln2, cudaFuncAttributeMaxDynamicSharedMemorySize, PSMEM);

    // GN partial sums + weight transposes in one launch
    prep_kernel<<<1456, 256>>>(x, qkv_w, proj_w, fc1_w, fc2_w);
    gn_final_kernel<<<BATCH, 128>>>();
    build_kernel<<<BATCH * HH * (WW / 32), 256>>>(x, gn_w, gn_b, ln1_w, ln1_b);

    // QKV -> head-major g_qkv_bf (smem-staged coalesced store)
    mma_gemm<0><<<dim3(6, TOK / 128), 256, GSMEM>>>(qkv_b, nullptr);

    attn_kernel<<<NWIN, 384, ATT_SMEM>>>(rpb);

    // fused proj + residual pre-sum + LN2 -> g_xb2 (fp32), g_h2_bf (bf16)
    proj_ln2<<<NWIN, 256, PSMEM>>>(proj_b, ln2_w, ln2_b);

    // fc1 + GELU -> g_hid_bf
    mma_gemm<2><<<dim3(8, TOK / 128), 256, GSMEM>>>(fc1_b, nullptr);

    // fc2 + pre-summed residual + clamp -> out (NCHW, transposed coalesced store)
    mma_gemm<3><<<dim3(2, TOK / 128), 256, GSMEM>>>(fc2_b, out);
}